// round 1
// baseline (speedup 1.0000x reference)
#include <cuda_runtime.h>
#include <math.h>
#include <stdint.h>

// Problem constants
#define BATCH 4
#define TSEQ  1024
#define NEC   1024
#define NH    16
#define HSZ   64
#define MT    (BATCH*TSEQ)      // 4096 rows
#define EPSGN 0.00064f

// ---------------------------------------------------------------------------
// Scratch (device globals — no allocation allowed)
// ---------------------------------------------------------------------------
__device__ float g_xx  [(size_t)MT*NEC];
__device__ float g_mix [(size_t)MT*NEC];
__device__ float g_h128[(size_t)MT*128];
__device__ float g_h64 [(size_t)MT*64];
__device__ float g_h16 [(size_t)MT*16];
__device__ float g_xm  [4][(size_t)MT*NEC];
__device__ float g_r   [(size_t)MT*NEC];
__device__ float g_gg  [(size_t)MT*NEC];
__device__ float g_k   [(size_t)MT*NEC];
__device__ float g_v   [(size_t)MT*NEC];
__device__ float g_w   [(size_t)MT*NEC];
__device__ float g_kk  [(size_t)MT*NEC];
__device__ float g_a   [(size_t)MT*NEC];
__device__ float g_ma  [(size_t)MT*NEC];
__device__ float g_mk  [(size_t)MT*NEC];
__device__ float g_b   [(size_t)MT*NEC];
__device__ float g_y   [(size_t)MT*NEC];
__device__ float g_z   [(size_t)MT*NEC];

// ---------------------------------------------------------------------------
// Token shift: xx = shift(x) - x ; mix = x + xx * time_maa_x
// ---------------------------------------------------------------------------
__global__ void shift_kernel(const float* __restrict__ x,
                             const float* __restrict__ tmaax,
                             float* __restrict__ xx,
                             float* __restrict__ mix)
{
    size_t i = (size_t)blockIdx.x * blockDim.x + threadIdx.x;
    if (i >= (size_t)MT * NEC) return;
    int c = (int)(i % NEC);
    size_t row = i / NEC;
    int t = (int)(row % TSEQ);
    float xv = x[i];
    float xp = (t > 0) ? x[i - NEC] : 0.f;
    float d = xp - xv;
    xx[i]  = d;
    mix[i] = fmaf(d, tmaax[c], xv);
}

// ---------------------------------------------------------------------------
// Generic SMEM-tiled fp32 GEMM.
//   BT=true : C[M,N] = A[M,K] * B[N,K]^T   (x @ W.T, W row-major [N,K])
//   BT=false: C[M,N] = A[M,K] * B[K,N]     (h @ W2,  W2 row-major [K,N])
// Epilogues fused.
// ---------------------------------------------------------------------------
struct Epi { const float* e0; const float* e1; const float* e2; };

enum { EPI_NONE=0, EPI_TANH=1, EPI_XM=2, EPI_W=3, EPI_ADD=4, EPI_SIG=5 };

template<int BM,int BN,int BK,int TM,int TN,bool BT,int EPI>
__global__ __launch_bounds__((BM/TM)*(BN/TN))
void gemm_kernel(int M, int N, int K,
                 const float* __restrict__ A, int lda,
                 const float* __restrict__ B, int ldb,
                 float* __restrict__ Cmat, int ldc, Epi ep)
{
    constexpr int NTH = (BM/TM)*(BN/TN);
    __shared__ float As[BK][BM];
    __shared__ float Bs[BK][BN];
    const int bn0 = blockIdx.x * BN;
    const int bm0 = blockIdx.y * BM;
    const int tid = threadIdx.x;
    const int tx = tid % (BN/TN);
    const int ty = tid / (BN/TN);

    float acc[TM][TN];
    #pragma unroll
    for (int i = 0; i < TM; i++)
        #pragma unroll
        for (int j = 0; j < TN; j++) acc[i][j] = 0.f;

    for (int kb = 0; kb < K; kb += BK) {
        // ---- load A tile (BM x BK), k contiguous ----
        {
            constexpr int A4 = BM*BK/4;
            #pragma unroll
            for (int l = 0; l < (A4 + NTH - 1)/NTH; l++) {
                int idx = tid + l*NTH;
                if (idx < A4) {
                    int r  = idx / (BK/4);
                    int c4 = idx % (BK/4);
                    float4 val = *(const float4*)(A + (size_t)(bm0 + r)*lda + kb + c4*4);
                    As[c4*4+0][r] = val.x;
                    As[c4*4+1][r] = val.y;
                    As[c4*4+2][r] = val.z;
                    As[c4*4+3][r] = val.w;
                }
            }
        }
        // ---- load B tile ----
        if (BT) {
            constexpr int B4 = BN*BK/4;
            #pragma unroll
            for (int l = 0; l < (B4 + NTH - 1)/NTH; l++) {
                int idx = tid + l*NTH;
                if (idx < B4) {
                    int r  = idx / (BK/4);
                    int c4 = idx % (BK/4);
                    float4 val = *(const float4*)(B + (size_t)(bn0 + r)*ldb + kb + c4*4);
                    Bs[c4*4+0][r] = val.x;
                    Bs[c4*4+1][r] = val.y;
                    Bs[c4*4+2][r] = val.z;
                    Bs[c4*4+3][r] = val.w;
                }
            }
        } else {
            constexpr int B4 = BK*BN/4;
            #pragma unroll
            for (int l = 0; l < (B4 + NTH - 1)/NTH; l++) {
                int idx = tid + l*NTH;
                if (idx < B4) {
                    int r  = idx / (BN/4);
                    int c4 = idx % (BN/4);
                    float4 val = *(const float4*)(B + (size_t)(kb + r)*ldb + bn0 + c4*4);
                    *(float4*)&Bs[r][c4*4] = val;
                }
            }
        }
        __syncthreads();

        #pragma unroll
        for (int kk = 0; kk < BK; kk++) {
            float rm[TM], rn[TN];
            if constexpr (TM % 4 == 0) {
                #pragma unroll
                for (int i = 0; i < TM; i += 4) {
                    float4 t4 = *(const float4*)&As[kk][ty*TM + i];
                    rm[i]=t4.x; rm[i+1]=t4.y; rm[i+2]=t4.z; rm[i+3]=t4.w;
                }
            } else {
                #pragma unroll
                for (int i = 0; i < TM; i++) rm[i] = As[kk][ty*TM + i];
            }
            if constexpr (TN % 4 == 0) {
                #pragma unroll
                for (int j = 0; j < TN; j += 4) {
                    float4 t4 = *(const float4*)&Bs[kk][tx*TN + j];
                    rn[j]=t4.x; rn[j+1]=t4.y; rn[j+2]=t4.z; rn[j+3]=t4.w;
                }
            } else {
                #pragma unroll
                for (int j = 0; j < TN; j++) rn[j] = Bs[kk][tx*TN + j];
            }
            #pragma unroll
            for (int i = 0; i < TM; i++)
                #pragma unroll
                for (int j = 0; j < TN; j++)
                    acc[i][j] = fmaf(rm[i], rn[j], acc[i][j]);
        }
        __syncthreads();
    }

    // ---- epilogue + store ----
    #pragma unroll
    for (int i = 0; i < TM; i++) {
        int row = bm0 + ty*TM + i;
        #pragma unroll
        for (int j = 0; j < TN; j++) {
            int col = bn0 + tx*TN + j;
            size_t idx = (size_t)row*ldc + col;
            float vacc = acc[i][j];
            float outv;
            if      (EPI == EPI_NONE) outv = vacc;
            else if (EPI == EPI_TANH) outv = tanhf(vacc);
            else if (EPI == EPI_XM)   outv = ep.e0[idx] + ep.e1[idx]*(vacc + ep.e2[col]);
            else if (EPI == EPI_W) {
                float t = -(ep.e2[col] + vacc);
                float sp = (t > 15.f) ? t : log1pf(expf(t));
                outv = -sp - 0.5f;
            }
            else if (EPI == EPI_ADD)  outv = ep.e0[idx] + vacc;
            else { // EPI_SIG
                float u = ep.e2[col] + vacc;
                outv = 1.f / (1.f + expf(-u));
            }
            Cmat[idx] = outv;
        }
    }
}

// ---------------------------------------------------------------------------
// warp sum helper
// ---------------------------------------------------------------------------
__device__ __forceinline__ float warp_sum(float v)
{
    #pragma unroll
    for (int o = 16; o > 0; o >>= 1) v += __shfl_xor_sync(0xffffffffu, v, o);
    return v;
}

// ---------------------------------------------------------------------------
// prep: per-head L2-normalize kk ; k = k*(ma + a*(1-ma))*exp(w*mk) ;
//       b = -kk*a ; w <- exp(-exp(w))
// grid = MT blocks, 512 threads (warp per head, 2 elems per lane)
// ---------------------------------------------------------------------------
__global__ void prep_kernel(float* kptr, float* kkptr,
                            const float* __restrict__ a,
                            const float* __restrict__ ma,
                            const float* __restrict__ mk,
                            float* wptr,
                            float* __restrict__ b)
{
    int m = blockIdx.x;
    int h = threadIdx.x >> 5;
    int lane = threadIdx.x & 31;
    size_t base = (size_t)m*NEC + h*HSZ;
    size_t i0 = base + lane, i1 = i0 + 32;

    float kk0 = kkptr[i0], kk1 = kkptr[i1];
    float ss = warp_sum(kk0*kk0 + kk1*kk1);
    float inv = 1.f / fmaxf(sqrtf(ss), 1e-12f);
    float n0 = kk0*inv, n1 = kk1*inv;
    kkptr[i0] = n0; kkptr[i1] = n1;

    float a0 = a[i0], a1 = a[i1];
    b[i0] = -n0*a0; b[i1] = -n1*a1;

    float ma0 = ma[i0], ma1 = ma[i1];
    float k0v = kptr[i0], k1v = kptr[i1];
    float w0 = wptr[i0], w1 = wptr[i1];
    float mk0 = mk[i0], mk1 = mk[i1];
    kptr[i0] = k0v * (ma0 + a0*(1.f - ma0)) * expf(w0*mk0);
    kptr[i1] = k1v * (ma1 + a1*(1.f - ma1)) * expf(w1*mk1);
    wptr[i0] = expf(-expf(w0));
    wptr[i1] = expf(-expf(w1));
}

// ---------------------------------------------------------------------------
// RWKV7 delta-rule recurrence.
// grid = BATCH * NH/2 blocks; block = 128 threads (2 heads, thread owns row i).
// state s[i][j]; per step:
//   sa_i = sum_j s_ij * a_j
//   s_ij = s_ij*w_j + sa_i*b_j + v_i*k_j
//   y_i  = sum_j s_ij * q_j
// ---------------------------------------------------------------------------
__global__ __launch_bounds__(128)
void wkv7_kernel(const float* __restrict__ q, const float* __restrict__ w,
                 const float* __restrict__ k, const float* __restrict__ v,
                 const float* __restrict__ a, const float* __restrict__ b,
                 float* __restrict__ y)
{
    const int blk = blockIdx.x;           // 0 .. BATCH*8-1
    const int batch = blk >> 3;
    const int hp = blk & 7;
    const int hl = threadIdx.x >> 6;      // 0/1: which head in pair
    const int i  = threadIdx.x & 63;
    const int h  = hp*2 + hl;

    __shared__ __align__(16) float shv[2][5][HSZ]; // q,w,k,a,b per head

    float state[HSZ];
    #pragma unroll
    for (int j = 0; j < HSZ; j++) state[j] = 0.f;

    size_t base = ((size_t)batch*TSEQ)*NEC + (size_t)h*HSZ + i;

    // prefetch t=0
    float rq = q[base], rw = w[base], rk = k[base], ra = a[base], rb = b[base], rv = v[base];

    for (int t = 0; t < TSEQ; t++) {
        shv[hl][0][i] = rq;
        shv[hl][1][i] = rw;
        shv[hl][2][i] = rk;
        shv[hl][3][i] = ra;
        shv[hl][4][i] = rb;
        float vi = rv;
        __syncthreads();

        if (t < TSEQ-1) {
            size_t nb = base + (size_t)(t+1)*NEC;
            rq = q[nb]; rw = w[nb]; rk = k[nb]; ra = a[nb]; rb = b[nb]; rv = v[nb];
        }

        const float4* a4 = (const float4*)shv[hl][3];
        float sa = 0.f;
        #pragma unroll
        for (int j4 = 0; j4 < HSZ/4; j4++) {
            float4 av = a4[j4];
            sa = fmaf(state[j4*4+0], av.x, sa);
            sa = fmaf(state[j4*4+1], av.y, sa);
            sa = fmaf(state[j4*4+2], av.z, sa);
            sa = fmaf(state[j4*4+3], av.w, sa);
        }

        const float4* q4 = (const float4*)shv[hl][0];
        const float4* w4 = (const float4*)shv[hl][1];
        const float4* k4 = (const float4*)shv[hl][2];
        const float4* b4 = (const float4*)shv[hl][4];
        float yi = 0.f;
        #pragma unroll
        for (int j4 = 0; j4 < HSZ/4; j4++) {
            float4 wv = w4[j4], kv = k4[j4], bv = b4[j4], qv = q4[j4];
            float s0 = fmaf(state[j4*4+0], wv.x, fmaf(sa, bv.x, vi*kv.x));
            float s1 = fmaf(state[j4*4+1], wv.y, fmaf(sa, bv.y, vi*kv.y));
            float s2 = fmaf(state[j4*4+2], wv.z, fmaf(sa, bv.z, vi*kv.z));
            float s3 = fmaf(state[j4*4+3], wv.w, fmaf(sa, bv.w, vi*kv.w));
            yi = fmaf(s0, qv.x, yi);
            yi = fmaf(s1, qv.y, yi);
            yi = fmaf(s2, qv.z, yi);
            yi = fmaf(s3, qv.w, yi);
            state[j4*4+0] = s0; state[j4*4+1] = s1;
            state[j4*4+2] = s2; state[j4*4+3] = s3;
        }
        y[base + (size_t)t*NEC] = yi;
        __syncthreads();
    }
}

// ---------------------------------------------------------------------------
// GroupNorm(H groups, eps) + per-head bonus + gate multiply:
//   z = (GN(y)*ln_w + ln_b + (sum_hs r*k*faaaa) * v) * g
// grid = MT blocks, 512 threads (warp per head)
// ---------------------------------------------------------------------------
__global__ void gn_kernel(const float* __restrict__ y,
                          const float* __restrict__ r,
                          const float* __restrict__ k,
                          const float* __restrict__ v,
                          const float* __restrict__ gg,
                          const float* __restrict__ ln_w,
                          const float* __restrict__ ln_b,
                          const float* __restrict__ faaaa,
                          float* __restrict__ z)
{
    int m = blockIdx.x;
    int h = threadIdx.x >> 5;
    int lane = threadIdx.x & 31;
    size_t base = (size_t)m*NEC + h*HSZ;
    int c0 = h*HSZ + lane, c1 = c0 + 32;
    size_t i0 = base + lane, i1 = i0 + 32;

    float y0 = y[i0], y1 = y[i1];
    float mu = warp_sum(y0 + y1) * (1.f/64.f);
    float d0 = y0 - mu, d1 = y1 - mu;
    float var = warp_sum(d0*d0 + d1*d1) * (1.f/64.f);
    float rstd = rsqrtf(var + EPSGN);
    float yn0 = d0*rstd*ln_w[c0] + ln_b[c0];
    float yn1 = d1*rstd*ln_w[c1] + ln_b[c1];

    float r0 = r[i0], r1 = r[i1];
    float k0v = k[i0], k1v = k[i1];
    float rk = warp_sum(r0*k0v*faaaa[c0] + r1*k1v*faaaa[c1]);

    float v0 = v[i0], v1 = v[i1];
    z[i0] = (yn0 + rk*v0) * gg[i0];
    z[i1] = (yn1 + rk*v1) * gg[i1];
}

// ---------------------------------------------------------------------------
// Host side
// ---------------------------------------------------------------------------
static inline Epi mkEpi(const float* a=nullptr, const float* b=nullptr, const float* c=nullptr)
{ Epi e; e.e0=a; e.e1=b; e.e2=c; return e; }

extern "C" void kernel_launch(void* const* d_in, const int* in_sizes, int n_in,
                              void* d_out, int out_size)
{
    const float* x          = (const float*)d_in[0];
    const float* time_maa_x = (const float*)d_in[1];
    const float* time_maa   = (const float*)d_in[2];
    const float* maa_w1     = (const float*)d_in[3];
    const float* maa_w2     = (const float*)d_in[4];
    const float* decay_w1   = (const float*)d_in[5];
    const float* decay_w2   = (const float*)d_in[6];
    const float* aaa_w1     = (const float*)d_in[7];
    const float* aaa_w2     = (const float*)d_in[8];
    const float* kkk_w1     = (const float*)d_in[9];
    const float* kkk_w2     = (const float*)d_in[10];
    const float* gate_w1    = (const float*)d_in[11];
    const float* gate_w2    = (const float*)d_in[12];
    const float* ma_w1      = (const float*)d_in[13];
    const float* ma_w2      = (const float*)d_in[14];
    const float* mk_w1      = (const float*)d_in[15];
    const float* mk_w2      = (const float*)d_in[16];
    const float* time_decay = (const float*)d_in[17];
    const float* time_faaaa = (const float*)d_in[18];
    const float* time_aaaaa = (const float*)d_in[19];
    const float* time_misc_a= (const float*)d_in[20];
    const float* time_misc_k= (const float*)d_in[21];
    const float* Wr         = (const float*)d_in[22];
    const float* Wk         = (const float*)d_in[23];
    const float* Wv         = (const float*)d_in[24];
    const float* Wo         = (const float*)d_in[25];
    const float* ln_w       = (const float*)d_in[26];
    const float* ln_b       = (const float*)d_in[27];
    float* out = (float*)d_out;

    float *xx, *mix, *h128, *h64, *h16, *xm, *r, *gg, *k, *v, *w, *kk, *a, *ma, *mk, *b, *y, *z;
    cudaGetSymbolAddress((void**)&xx,  g_xx);
    cudaGetSymbolAddress((void**)&mix, g_mix);
    cudaGetSymbolAddress((void**)&h128,g_h128);
    cudaGetSymbolAddress((void**)&h64, g_h64);
    cudaGetSymbolAddress((void**)&h16, g_h16);
    cudaGetSymbolAddress((void**)&xm,  g_xm);
    cudaGetSymbolAddress((void**)&r,   g_r);
    cudaGetSymbolAddress((void**)&gg,  g_gg);
    cudaGetSymbolAddress((void**)&k,   g_k);
    cudaGetSymbolAddress((void**)&v,   g_v);
    cudaGetSymbolAddress((void**)&w,   g_w);
    cudaGetSymbolAddress((void**)&kk,  g_kk);
    cudaGetSymbolAddress((void**)&a,   g_a);
    cudaGetSymbolAddress((void**)&ma,  g_ma);
    cudaGetSymbolAddress((void**)&mk,  g_mk);
    cudaGetSymbolAddress((void**)&b,   g_b);
    cudaGetSymbolAddress((void**)&y,   g_y);
    cudaGetSymbolAddress((void**)&z,   g_z);

    const float* xrg = xm + 0*(size_t)MT*NEC;
    const float* xwa = xm + 1*(size_t)MT*NEC;
    const float* xk  = xm + 2*(size_t)MT*NEC;
    const float* xv  = xm + 3*(size_t)MT*NEC;

    // 1) token shift
    {
        size_t n = (size_t)MT*NEC;
        shift_kernel<<<(unsigned)((n + 255)/256), 256>>>(x, time_maa_x, xx, mix);
    }

    // 2) maa hidden: h128 = tanh(mix @ maa_w1.T)   [4096,128]
    gemm_kernel<128,128,16,8,8,true,EPI_TANH><<<dim3(1,32),256>>>(
        MT,128,NEC, mix,NEC, maa_w1,NEC, h128,128, mkEpi());

    // 3) xm_g = x + xx*(h128[:,g*32:]@maa_w2[g] + time_maa[g])
    for (int g = 0; g < 4; g++) {
        gemm_kernel<128,128,16,8,8,false,EPI_XM><<<dim3(8,32),256>>>(
            MT,NEC,32, h128 + g*32,128, maa_w2 + (size_t)g*32*NEC,NEC,
            xm + (size_t)g*MT*NEC,NEC, mkEpi(x, xx, time_maa + g*NEC));
    }

    // 4) r = xrg @ Wr.T
    gemm_kernel<128,128,16,8,8,true,EPI_NONE><<<dim3(8,32),256>>>(
        MT,NEC,NEC, xrg,NEC, Wr,NEC, r,NEC, mkEpi());
    // 5) gate: h128 = tanh(xrg @ gate_w1.T); gg = h128 @ gate_w2
    gemm_kernel<128,128,16,8,8,true,EPI_TANH><<<dim3(1,32),256>>>(
        MT,128,NEC, xrg,NEC, gate_w1,NEC, h128,128, mkEpi());
    gemm_kernel<128,128,16,8,8,false,EPI_NONE><<<dim3(8,32),256>>>(
        MT,NEC,128, h128,128, gate_w2,NEC, gg,NEC, mkEpi());
    // 6) k = xk @ Wk.T ; v = xv @ Wv.T
    gemm_kernel<128,128,16,8,8,true,EPI_NONE><<<dim3(8,32),256>>>(
        MT,NEC,NEC, xk,NEC, Wk,NEC, k,NEC, mkEpi());
    gemm_kernel<128,128,16,8,8,true,EPI_NONE><<<dim3(8,32),256>>>(
        MT,NEC,NEC, xv,NEC, Wv,NEC, v,NEC, mkEpi());
    // 7) decay: h64 = tanh(xwa @ decay_w1.T); w = -softplus(-(td + h64@decay_w2)) - 0.5
    gemm_kernel<128,64,16,8,8,true,EPI_TANH><<<dim3(1,32),128>>>(
        MT,64,NEC, xwa,NEC, decay_w1,NEC, h64,64, mkEpi());
    gemm_kernel<128,128,16,8,8,false,EPI_W><<<dim3(8,32),256>>>(
        MT,NEC,64, h64,64, decay_w2,NEC, w,NEC, mkEpi(nullptr,nullptr,time_decay));
    // 8) kk_raw = k + tanh(xk @ kkk_w1.T) @ kkk_w2
    gemm_kernel<128,16,16,8,2,true,EPI_TANH><<<dim3(1,32),128>>>(
        MT,16,NEC, xk,NEC, kkk_w1,NEC, h16,16, mkEpi());
    gemm_kernel<128,128,16,8,8,false,EPI_ADD><<<dim3(8,32),256>>>(
        MT,NEC,16, h16,16, kkk_w2,NEC, kk,NEC, mkEpi(k));
    // 9) a = sigmoid(time_aaaaa + (xwa@aaa_w1.T)@aaa_w2)    (no tanh on hidden)
    gemm_kernel<128,16,16,8,2,true,EPI_NONE><<<dim3(1,32),128>>>(
        MT,16,NEC, xwa,NEC, aaa_w1,NEC, h16,16, mkEpi());
    gemm_kernel<128,128,16,8,8,false,EPI_SIG><<<dim3(8,32),256>>>(
        MT,NEC,16, h16,16, aaa_w2,NEC, a,NEC, mkEpi(nullptr,nullptr,time_aaaaa));
    // 10) ma = sigmoid(time_misc_a + (xwa@ma_w1.T)@ma_w2)
    gemm_kernel<128,16,16,8,2,true,EPI_NONE><<<dim3(1,32),128>>>(
        MT,16,NEC, xwa,NEC, ma_w1,NEC, h16,16, mkEpi());
    gemm_kernel<128,128,16,8,8,false,EPI_SIG><<<dim3(8,32),256>>>(
        MT,NEC,16, h16,16, ma_w2,NEC, ma,NEC, mkEpi(nullptr,nullptr,time_misc_a));
    // 11) mk = sigmoid(time_misc_k + (xk@mk_w1.T)@mk_w2)
    gemm_kernel<128,16,16,8,2,true,EPI_NONE><<<dim3(1,32),128>>>(
        MT,16,NEC, xk,NEC, mk_w1,NEC, h16,16, mkEpi());
    gemm_kernel<128,128,16,8,8,false,EPI_SIG><<<dim3(8,32),256>>>(
        MT,NEC,16, h16,16, mk_w2,NEC, mk,NEC, mkEpi(nullptr,nullptr,time_misc_k));

    // 12) prep: normalize kk per head, k final, b = -kk*a, w <- exp(-exp(w))
    prep_kernel<<<MT,512>>>(k, kk, a, ma, mk, w, b);

    // 13) recurrence
    wkv7_kernel<<<BATCH*(NH/2),128>>>(r, w, k, v, kk, b, y);

    // 14) groupnorm + bonus + gate
    gn_kernel<<<MT,512>>>(y, r, k, v, gg, ln_w, ln_b, time_faaaa, z);

    // 15) out = z @ Wo.T
    gemm_kernel<128,128,16,8,8,true,EPI_NONE><<<dim3(8,32),256>>>(
        MT,NEC,NEC, z,NEC, Wo,NEC, out,NEC, mkEpi());
}

// round 2
// speedup vs baseline: 1.2068x; 1.2068x over previous
#include <cuda_runtime.h>
#include <math.h>
#include <stdint.h>

// Problem constants
#define BATCH 4
#define TSEQ  1024
#define NEC   1024
#define NH    16
#define HSZ   64
#define MT    (BATCH*TSEQ)      // 4096 rows
#define EPSGN 0.00064f

// ---------------------------------------------------------------------------
// Scratch (device globals — no allocation allowed)
// ---------------------------------------------------------------------------
__device__ float g_xx  [(size_t)MT*NEC];
__device__ float g_mix [(size_t)MT*NEC];
__device__ float g_h128[(size_t)MT*128];
__device__ float g_h64 [(size_t)MT*64];
__device__ float g_h16 [(size_t)MT*16];
__device__ float g_xm  [4][(size_t)MT*NEC];
__device__ float g_r   [(size_t)MT*NEC];
__device__ float g_gg  [(size_t)MT*NEC];
__device__ float g_k   [(size_t)MT*NEC];
__device__ float g_v   [(size_t)MT*NEC];
__device__ float g_w   [(size_t)MT*NEC];
__device__ float g_kk  [(size_t)MT*NEC];
__device__ float g_a   [(size_t)MT*NEC];
__device__ float g_ma  [(size_t)MT*NEC];
__device__ float g_mk  [(size_t)MT*NEC];
__device__ float g_b   [(size_t)MT*NEC];
__device__ float g_y   [(size_t)MT*NEC];
__device__ float g_z   [(size_t)MT*NEC];

struct Epi { const float* e0; const float* e1; const float* e2; };
enum { EPI_NONE=0, EPI_TANH=1, EPI_XM=2, EPI_W=3, EPI_ADD=4, EPI_SIG=5 };

// ---------------------------------------------------------------------------
// Token shift: xx = shift(x) - x ; mix = x + xx * time_maa_x
// ---------------------------------------------------------------------------
__global__ void shift_kernel(const float* __restrict__ x,
                             const float* __restrict__ tmaax,
                             float* __restrict__ xx,
                             float* __restrict__ mix)
{
    size_t i = (size_t)blockIdx.x * blockDim.x + threadIdx.x;
    if (i >= (size_t)MT * NEC) return;
    int c = (int)(i % NEC);
    size_t row = i / NEC;
    int t = (int)(row % TSEQ);
    float xv = x[i];
    float xp = (t > 0) ? x[i - NEC] : 0.f;
    float d = xp - xv;
    xx[i]  = d;
    mix[i] = fmaf(d, tmaax[c], xv);
}

// ---------------------------------------------------------------------------
// tf32 helpers
// ---------------------------------------------------------------------------
__device__ __forceinline__ uint32_t f2tf32(float v){
    uint32_t r; asm("cvt.rna.tf32.f32 %0, %1;" : "=r"(r) : "f"(v)); return r;
}
__device__ __forceinline__ void split_tf32(float v, uint32_t &hi, uint32_t &lo){
    hi = f2tf32(v);
    float rem = v - __uint_as_float(hi);
    lo = f2tf32(rem);
}
__device__ __forceinline__ void mma_tf32(float* c, const uint32_t* a, const uint32_t* b){
    asm volatile("mma.sync.aligned.m16n8k8.row.col.f32.tf32.tf32.f32 "
        "{%0,%1,%2,%3},{%4,%5,%6,%7},{%8,%9},{%0,%1,%2,%3};\n"
        : "+f"(c[0]), "+f"(c[1]), "+f"(c[2]), "+f"(c[3])
        : "r"(a[0]), "r"(a[1]), "r"(a[2]), "r"(a[3]), "r"(b[0]), "r"(b[1]));
}

template<int EPI>
__device__ __forceinline__ float epi_apply(float vacc, const Epi& ep, size_t idx, int col)
{
    if      (EPI == EPI_NONE) return vacc;
    else if (EPI == EPI_TANH) return tanhf(vacc);
    else if (EPI == EPI_XM)   return ep.e0[idx] + ep.e1[idx]*(vacc + ep.e2[col]);
    else if (EPI == EPI_W) {
        float t = -(ep.e2[col] + vacc);
        float sp = (t > 15.f) ? t : log1pf(expf(t));
        return -sp - 0.5f;
    }
    else if (EPI == EPI_ADD)  return ep.e0[idx] + vacc;
    else {
        float u = ep.e2[col] + vacc;
        return 1.f / (1.f + expf(-u));
    }
}

// ---------------------------------------------------------------------------
// Tensor-core GEMM (tf32 split-3 for ~fp32 accuracy).
//   BT=true : C[M,N] = A[M,K] * B[N,K]^T   (W row-major [N,K])
//   BT=false: C[M,N] = A[M,K] * B[K,N]     (W2 row-major [K,N])
// Requires: M%128==0, N%128==0, K%16==0. Block 256 thr, tile 128x128x16.
// ---------------------------------------------------------------------------
template<int EPI, bool BT>
__global__ __launch_bounds__(256)
void gemm_tc(int M, int N, int K,
             const float* __restrict__ A, int lda,
             const float* __restrict__ B, int ldb,
             float* __restrict__ C, int ldc, Epi ep)
{
    constexpr int BM=128, BN=128, BK=16, LDS = BK+4; // stride 20 floats: conflict-free frag loads
    __shared__ uint32_t Ah[BM][LDS], Al[BM][LDS];
    __shared__ uint32_t Bh[BN][LDS], Bl[BN][LDS];

    const int tid  = threadIdx.x;
    const int bn0  = blockIdx.x * BN;
    const int bm0  = blockIdx.y * BM;
    const int warp = tid >> 5, lane = tid & 31;
    const int grp  = lane >> 2, q = lane & 3;
    const int wm   = (warp >> 2) * 64;   // 2 warps along M
    const int wn   = (warp & 3) * 32;    // 4 warps along N

    float acc[4][4][4];
    #pragma unroll
    for (int mi=0; mi<4; mi++)
        #pragma unroll
        for (int ni=0; ni<4; ni++)
            #pragma unroll
            for (int e=0; e<4; e++) acc[mi][ni][e] = 0.f;

    for (int kb = 0; kb < K; kb += BK) {
        // ---- A tile: [BM x BK], k contiguous ----
        #pragma unroll
        for (int l = 0; l < 2; l++) {
            int idx = tid + l*256;          // 512 float4
            int r = idx >> 2, c4 = idx & 3;
            float4 val = *(const float4*)(A + (size_t)(bm0 + r)*lda + kb + c4*4);
            uint32_t h, lo;
            split_tf32(val.x, h, lo); Ah[r][c4*4+0]=h; Al[r][c4*4+0]=lo;
            split_tf32(val.y, h, lo); Ah[r][c4*4+1]=h; Al[r][c4*4+1]=lo;
            split_tf32(val.z, h, lo); Ah[r][c4*4+2]=h; Al[r][c4*4+2]=lo;
            split_tf32(val.w, h, lo); Ah[r][c4*4+3]=h; Al[r][c4*4+3]=lo;
        }
        // ---- B tile -> Bs[n][k] ----
        if (BT) {
            #pragma unroll
            for (int l = 0; l < 2; l++) {
                int idx = tid + l*256;
                int r = idx >> 2, c4 = idx & 3;
                float4 val = *(const float4*)(B + (size_t)(bn0 + r)*ldb + kb + c4*4);
                uint32_t h, lo;
                split_tf32(val.x, h, lo); Bh[r][c4*4+0]=h; Bl[r][c4*4+0]=lo;
                split_tf32(val.y, h, lo); Bh[r][c4*4+1]=h; Bl[r][c4*4+1]=lo;
                split_tf32(val.z, h, lo); Bh[r][c4*4+2]=h; Bl[r][c4*4+2]=lo;
                split_tf32(val.w, h, lo); Bh[r][c4*4+3]=h; Bl[r][c4*4+3]=lo;
            }
        } else {
            #pragma unroll
            for (int l = 0; l < 2; l++) {
                int idx = tid + l*256;
                int kk_ = idx >> 5, n4 = idx & 31;
                float4 val = *(const float4*)(B + (size_t)(kb + kk_)*ldb + bn0 + n4*4);
                uint32_t h, lo;
                split_tf32(val.x, h, lo); Bh[n4*4+0][kk_]=h; Bl[n4*4+0][kk_]=lo;
                split_tf32(val.y, h, lo); Bh[n4*4+1][kk_]=h; Bl[n4*4+1][kk_]=lo;
                split_tf32(val.z, h, lo); Bh[n4*4+2][kk_]=h; Bl[n4*4+2][kk_]=lo;
                split_tf32(val.w, h, lo); Bh[n4*4+3][kk_]=h; Bl[n4*4+3][kk_]=lo;
            }
        }
        __syncthreads();

        #pragma unroll
        for (int kc = 0; kc < BK; kc += 8) {
            uint32_t ah[4][4], al[4][4], bh[4][2], bl[4][2];
            #pragma unroll
            for (int mi = 0; mi < 4; mi++) {
                int r0 = wm + mi*16 + grp;
                ah[mi][0]=Ah[r0  ][kc+q  ]; al[mi][0]=Al[r0  ][kc+q  ];
                ah[mi][1]=Ah[r0+8][kc+q  ]; al[mi][1]=Al[r0+8][kc+q  ];
                ah[mi][2]=Ah[r0  ][kc+q+4]; al[mi][2]=Al[r0  ][kc+q+4];
                ah[mi][3]=Ah[r0+8][kc+q+4]; al[mi][3]=Al[r0+8][kc+q+4];
            }
            #pragma unroll
            for (int ni = 0; ni < 4; ni++) {
                int c0 = wn + ni*8 + grp;
                bh[ni][0]=Bh[c0][kc+q]; bh[ni][1]=Bh[c0][kc+q+4];
                bl[ni][0]=Bl[c0][kc+q]; bl[ni][1]=Bl[c0][kc+q+4];
            }
            #pragma unroll
            for (int mi = 0; mi < 4; mi++)
                #pragma unroll
                for (int ni = 0; ni < 4; ni++) {
                    mma_tf32(acc[mi][ni], ah[mi], bh[ni]);
                    mma_tf32(acc[mi][ni], ah[mi], bl[ni]);
                    mma_tf32(acc[mi][ni], al[mi], bh[ni]);
                }
        }
        __syncthreads();
    }

    // ---- epilogue ----
    #pragma unroll
    for (int mi = 0; mi < 4; mi++) {
        int row0 = bm0 + wm + mi*16 + grp;
        #pragma unroll
        for (int ni = 0; ni < 4; ni++) {
            int col = bn0 + wn + ni*8 + 2*q;
            {
                size_t idx = (size_t)row0*ldc + col;
                float2 o;
                o.x = epi_apply<EPI>(acc[mi][ni][0], ep, idx,   col);
                o.y = epi_apply<EPI>(acc[mi][ni][1], ep, idx+1, col+1);
                *(float2*)&C[idx] = o;
            }
            {
                size_t idx = (size_t)(row0+8)*ldc + col;
                float2 o;
                o.x = epi_apply<EPI>(acc[mi][ni][2], ep, idx,   col);
                o.y = epi_apply<EPI>(acc[mi][ni][3], ep, idx+1, col+1);
                *(float2*)&C[idx] = o;
            }
        }
    }
}

// ---------------------------------------------------------------------------
// fp32 SMEM-tiled GEMM (kept for small-N LoRA hiddens, NT only)
// ---------------------------------------------------------------------------
template<int BM,int BN,int BK,int TM,int TN,int EPI>
__global__ __launch_bounds__((BM/TM)*(BN/TN))
void gemm_kernel(int M, int N, int K,
                 const float* __restrict__ A, int lda,
                 const float* __restrict__ B, int ldb,
                 float* __restrict__ Cmat, int ldc, Epi ep)
{
    constexpr int NTH = (BM/TM)*(BN/TN);
    __shared__ float As[BK][BM];
    __shared__ float Bs[BK][BN];
    const int bn0 = blockIdx.x * BN;
    const int bm0 = blockIdx.y * BM;
    const int tid = threadIdx.x;
    const int tx = tid % (BN/TN);
    const int ty = tid / (BN/TN);

    float acc[TM][TN];
    #pragma unroll
    for (int i = 0; i < TM; i++)
        #pragma unroll
        for (int j = 0; j < TN; j++) acc[i][j] = 0.f;

    for (int kb = 0; kb < K; kb += BK) {
        {
            constexpr int A4 = BM*BK/4;
            #pragma unroll
            for (int l = 0; l < (A4 + NTH - 1)/NTH; l++) {
                int idx = tid + l*NTH;
                if (idx < A4) {
                    int r  = idx / (BK/4);
                    int c4 = idx % (BK/4);
                    float4 val = *(const float4*)(A + (size_t)(bm0 + r)*lda + kb + c4*4);
                    As[c4*4+0][r] = val.x;
                    As[c4*4+1][r] = val.y;
                    As[c4*4+2][r] = val.z;
                    As[c4*4+3][r] = val.w;
                }
            }
        }
        {
            constexpr int B4 = BN*BK/4;
            #pragma unroll
            for (int l = 0; l < (B4 + NTH - 1)/NTH; l++) {
                int idx = tid + l*NTH;
                if (idx < B4) {
                    int r  = idx / (BK/4);
                    int c4 = idx % (BK/4);
                    float4 val = *(const float4*)(B + (size_t)(bn0 + r)*ldb + kb + c4*4);
                    Bs[c4*4+0][r] = val.x;
                    Bs[c4*4+1][r] = val.y;
                    Bs[c4*4+2][r] = val.z;
                    Bs[c4*4+3][r] = val.w;
                }
            }
        }
        __syncthreads();

        #pragma unroll
        for (int kk = 0; kk < BK; kk++) {
            float rm[TM], rn[TN];
            #pragma unroll
            for (int i = 0; i < TM; i++) rm[i] = As[kk][ty*TM + i];
            #pragma unroll
            for (int j = 0; j < TN; j++) rn[j] = Bs[kk][tx*TN + j];
            #pragma unroll
            for (int i = 0; i < TM; i++)
                #pragma unroll
                for (int j = 0; j < TN; j++)
                    acc[i][j] = fmaf(rm[i], rn[j], acc[i][j]);
        }
        __syncthreads();
    }

    #pragma unroll
    for (int i = 0; i < TM; i++) {
        int row = bm0 + ty*TM + i;
        #pragma unroll
        for (int j = 0; j < TN; j++) {
            int col = bn0 + tx*TN + j;
            size_t idx = (size_t)row*ldc + col;
            Cmat[idx] = epi_apply<EPI>(acc[i][j], ep, idx, col);
        }
    }
}

// ---------------------------------------------------------------------------
// warp sum helper
// ---------------------------------------------------------------------------
__device__ __forceinline__ float warp_sum(float v)
{
    #pragma unroll
    for (int o = 16; o > 0; o >>= 1) v += __shfl_xor_sync(0xffffffffu, v, o);
    return v;
}

// ---------------------------------------------------------------------------
// prep: per-head L2-normalize kk ; k = k*(ma + a*(1-ma))*exp(w*mk) ;
//       b = -kk*a ; w <- exp(-exp(w))
// ---------------------------------------------------------------------------
__global__ void prep_kernel(float* kptr, float* kkptr,
                            const float* __restrict__ a,
                            const float* __restrict__ ma,
                            const float* __restrict__ mk,
                            float* wptr,
                            float* __restrict__ b)
{
    int m = blockIdx.x;
    int h = threadIdx.x >> 5;
    int lane = threadIdx.x & 31;
    size_t base = (size_t)m*NEC + h*HSZ;
    size_t i0 = base + lane, i1 = i0 + 32;

    float kk0 = kkptr[i0], kk1 = kkptr[i1];
    float ss = warp_sum(kk0*kk0 + kk1*kk1);
    float inv = 1.f / fmaxf(sqrtf(ss), 1e-12f);
    float n0 = kk0*inv, n1 = kk1*inv;
    kkptr[i0] = n0; kkptr[i1] = n1;

    float a0 = a[i0], a1 = a[i1];
    b[i0] = -n0*a0; b[i1] = -n1*a1;

    float ma0 = ma[i0], ma1 = ma[i1];
    float k0v = kptr[i0], k1v = kptr[i1];
    float w0 = wptr[i0], w1 = wptr[i1];
    float mk0 = mk[i0], mk1 = mk[i1];
    kptr[i0] = k0v * (ma0 + a0*(1.f - ma0)) * expf(w0*mk0);
    kptr[i1] = k1v * (ma1 + a1*(1.f - ma1)) * expf(w1*mk1);
    wptr[i0] = expf(-expf(w0));
    wptr[i1] = expf(-expf(w1));
}

// ---------------------------------------------------------------------------
// RWKV7 delta-rule recurrence, 2-way column split per state row.
// grid = B*H = 64 blocks; block = 128 threads.
// thread (i = tid>>1, half = tid&1) owns s[i][half*32 .. +32).
// ---------------------------------------------------------------------------
__global__ __launch_bounds__(128)
void wkv7_kernel(const float* __restrict__ q, const float* __restrict__ w,
                 const float* __restrict__ k, const float* __restrict__ v,
                 const float* __restrict__ a, const float* __restrict__ b,
                 float* __restrict__ y)
{
    const int bh = blockIdx.x;          // 0..63
    const int batch = bh >> 4, h = bh & 15;
    const int tid = threadIdx.x;
    const int i = tid >> 1;
    const int half = tid & 1;

    __shared__ __align__(16) float buf[2][6][HSZ];  // q,w,k,a,b,v (ping-pong)

    float s[32];
    #pragma unroll
    for (int j = 0; j < 32; j++) s[j] = 0.f;

    size_t base = ((size_t)batch * TSEQ) * NEC + (size_t)h * HSZ;

    // loader mapping: each thread fills 3 of the 6*64 slots
    const int j0 = tid & 63;
    const int vsel = tid >> 6;                 // 0 or 1
    const float* p0 = vsel ? w : q;            // vec 0/1
    const float* p1 = vsel ? a : k;            // vec 2/3
    const float* p2 = vsel ? v : b;            // vec 4/5
    const int v0i = vsel, v1i = 2 + vsel, v2i = 4 + vsel;

    buf[0][v0i][j0] = p0[base + j0];
    buf[0][v1i][j0] = p1[base + j0];
    buf[0][v2i][j0] = p2[base + j0];
    __syncthreads();

    int p = 0;
    for (int t = 0; t < TSEQ; t++) {
        if (t + 1 < TSEQ) {
            size_t o = base + (size_t)(t+1)*NEC + j0;
            buf[p^1][v0i][j0] = p0[o];
            buf[p^1][v1i][j0] = p1[o];
            buf[p^1][v2i][j0] = p2[o];
        }
        const float4* qj = (const float4*)&buf[p][0][half*32];
        const float4* wj = (const float4*)&buf[p][1][half*32];
        const float4* kj = (const float4*)&buf[p][2][half*32];
        const float4* aj = (const float4*)&buf[p][3][half*32];
        const float4* bj = (const float4*)&buf[p][4][half*32];
        float vi = buf[p][5][i];

        float sa = 0.f;
        #pragma unroll
        for (int j4 = 0; j4 < 8; j4++) {
            float4 av = aj[j4];
            sa = fmaf(s[j4*4+0], av.x, sa);
            sa = fmaf(s[j4*4+1], av.y, sa);
            sa = fmaf(s[j4*4+2], av.z, sa);
            sa = fmaf(s[j4*4+3], av.w, sa);
        }
        sa += __shfl_xor_sync(0xffffffffu, sa, 1);

        float yi = 0.f;
        #pragma unroll
        for (int j4 = 0; j4 < 8; j4++) {
            float4 wv = wj[j4], kv = kj[j4], bv = bj[j4], qv = qj[j4];
            float s0 = fmaf(s[j4*4+0], wv.x, fmaf(sa, bv.x, vi*kv.x));
            float s1 = fmaf(s[j4*4+1], wv.y, fmaf(sa, bv.y, vi*kv.y));
            float s2 = fmaf(s[j4*4+2], wv.z, fmaf(sa, bv.z, vi*kv.z));
            float s3 = fmaf(s[j4*4+3], wv.w, fmaf(sa, bv.w, vi*kv.w));
            yi = fmaf(s0, qv.x, yi);
            yi = fmaf(s1, qv.y, yi);
            yi = fmaf(s2, qv.z, yi);
            yi = fmaf(s3, qv.w, yi);
            s[j4*4+0] = s0; s[j4*4+1] = s1; s[j4*4+2] = s2; s[j4*4+3] = s3;
        }
        yi += __shfl_xor_sync(0xffffffffu, yi, 1);
        if (half == 0) y[base + (size_t)t*NEC + i] = yi;
        p ^= 1;
        __syncthreads();
    }
}

// ---------------------------------------------------------------------------
// GroupNorm + per-head bonus + gate
// ---------------------------------------------------------------------------
__global__ void gn_kernel(const float* __restrict__ y,
                          const float* __restrict__ r,
                          const float* __restrict__ k,
                          const float* __restrict__ v,
                          const float* __restrict__ gg,
                          const float* __restrict__ ln_w,
                          const float* __restrict__ ln_b,
                          const float* __restrict__ faaaa,
                          float* __restrict__ z)
{
    int m = blockIdx.x;
    int h = threadIdx.x >> 5;
    int lane = threadIdx.x & 31;
    size_t base = (size_t)m*NEC + h*HSZ;
    int c0 = h*HSZ + lane, c1 = c0 + 32;
    size_t i0 = base + lane, i1 = i0 + 32;

    float y0 = y[i0], y1 = y[i1];
    float mu = warp_sum(y0 + y1) * (1.f/64.f);
    float d0 = y0 - mu, d1 = y1 - mu;
    float var = warp_sum(d0*d0 + d1*d1) * (1.f/64.f);
    float rstd = rsqrtf(var + EPSGN);
    float yn0 = d0*rstd*ln_w[c0] + ln_b[c0];
    float yn1 = d1*rstd*ln_w[c1] + ln_b[c1];

    float r0 = r[i0], r1 = r[i1];
    float k0v = k[i0], k1v = k[i1];
    float rk = warp_sum(r0*k0v*faaaa[c0] + r1*k1v*faaaa[c1]);

    float v0 = v[i0], v1 = v[i1];
    z[i0] = (yn0 + rk*v0) * gg[i0];
    z[i1] = (yn1 + rk*v1) * gg[i1];
}

// ---------------------------------------------------------------------------
// Host side
// ---------------------------------------------------------------------------
static inline Epi mkEpi(const float* a=nullptr, const float* b=nullptr, const float* c=nullptr)
{ Epi e; e.e0=a; e.e1=b; e.e2=c; return e; }

extern "C" void kernel_launch(void* const* d_in, const int* in_sizes, int n_in,
                              void* d_out, int out_size)
{
    const float* x          = (const float*)d_in[0];
    const float* time_maa_x = (const float*)d_in[1];
    const float* time_maa   = (const float*)d_in[2];
    const float* maa_w1     = (const float*)d_in[3];
    const float* maa_w2     = (const float*)d_in[4];
    const float* decay_w1   = (const float*)d_in[5];
    const float* decay_w2   = (const float*)d_in[6];
    const float* aaa_w1     = (const float*)d_in[7];
    const float* aaa_w2     = (const float*)d_in[8];
    const float* kkk_w1     = (const float*)d_in[9];
    const float* kkk_w2     = (const float*)d_in[10];
    const float* gate_w1    = (const float*)d_in[11];
    const float* gate_w2    = (const float*)d_in[12];
    const float* ma_w1      = (const float*)d_in[13];
    const float* ma_w2      = (const float*)d_in[14];
    const float* mk_w1      = (const float*)d_in[15];
    const float* mk_w2      = (const float*)d_in[16];
    const float* time_decay = (const float*)d_in[17];
    const float* time_faaaa = (const float*)d_in[18];
    const float* time_aaaaa = (const float*)d_in[19];
    const float* time_misc_a= (const float*)d_in[20];
    const float* time_misc_k= (const float*)d_in[21];
    const float* Wr         = (const float*)d_in[22];
    const float* Wk         = (const float*)d_in[23];
    const float* Wv         = (const float*)d_in[24];
    const float* Wo         = (const float*)d_in[25];
    const float* ln_w       = (const float*)d_in[26];
    const float* ln_b       = (const float*)d_in[27];
    float* out = (float*)d_out;

    float *xx, *mix, *h128, *h64, *h16, *xm, *r, *gg, *k, *v, *w, *kk, *a, *ma, *mk, *b, *y, *z;
    cudaGetSymbolAddress((void**)&xx,  g_xx);
    cudaGetSymbolAddress((void**)&mix, g_mix);
    cudaGetSymbolAddress((void**)&h128,g_h128);
    cudaGetSymbolAddress((void**)&h64, g_h64);
    cudaGetSymbolAddress((void**)&h16, g_h16);
    cudaGetSymbolAddress((void**)&xm,  g_xm);
    cudaGetSymbolAddress((void**)&r,   g_r);
    cudaGetSymbolAddress((void**)&gg,  g_gg);
    cudaGetSymbolAddress((void**)&k,   g_k);
    cudaGetSymbolAddress((void**)&v,   g_v);
    cudaGetSymbolAddress((void**)&w,   g_w);
    cudaGetSymbolAddress((void**)&kk,  g_kk);
    cudaGetSymbolAddress((void**)&a,   g_a);
    cudaGetSymbolAddress((void**)&ma,  g_ma);
    cudaGetSymbolAddress((void**)&mk,  g_mk);
    cudaGetSymbolAddress((void**)&b,   g_b);
    cudaGetSymbolAddress((void**)&y,   g_y);
    cudaGetSymbolAddress((void**)&z,   g_z);

    const float* xrg = xm + 0*(size_t)MT*NEC;
    const float* xwa = xm + 1*(size_t)MT*NEC;
    const float* xk  = xm + 2*(size_t)MT*NEC;
    const float* xv  = xm + 3*(size_t)MT*NEC;

    // 1) token shift
    {
        size_t n = (size_t)MT*NEC;
        shift_kernel<<<(unsigned)((n + 255)/256), 256>>>(x, time_maa_x, xx, mix);
    }

    // 2) maa hidden: h128 = tanh(mix @ maa_w1.T)   [4096,128]
    gemm_tc<EPI_TANH,true><<<dim3(1,32),256>>>(
        MT,128,NEC, mix,NEC, maa_w1,NEC, h128,128, mkEpi());

    // 3) xm_g = x + xx*(h128[:,g*32:]@maa_w2[g] + time_maa[g])
    for (int g = 0; g < 4; g++) {
        gemm_tc<EPI_XM,false><<<dim3(8,32),256>>>(
            MT,NEC,32, h128 + g*32,128, maa_w2 + (size_t)g*32*NEC,NEC,
            xm + (size_t)g*MT*NEC,NEC, mkEpi(x, xx, time_maa + g*NEC));
    }

    // 4) r = xrg @ Wr.T
    gemm_tc<EPI_NONE,true><<<dim3(8,32),256>>>(
        MT,NEC,NEC, xrg,NEC, Wr,NEC, r,NEC, mkEpi());
    // 5) gate: h128 = tanh(xrg @ gate_w1.T); gg = h128 @ gate_w2
    gemm_tc<EPI_TANH,true><<<dim3(1,32),256>>>(
        MT,128,NEC, xrg,NEC, gate_w1,NEC, h128,128, mkEpi());
    gemm_tc<EPI_NONE,false><<<dim3(8,32),256>>>(
        MT,NEC,128, h128,128, gate_w2,NEC, gg,NEC, mkEpi());
    // 6) k = xk @ Wk.T ; v = xv @ Wv.T
    gemm_tc<EPI_NONE,true><<<dim3(8,32),256>>>(
        MT,NEC,NEC, xk,NEC, Wk,NEC, k,NEC, mkEpi());
    gemm_tc<EPI_NONE,true><<<dim3(8,32),256>>>(
        MT,NEC,NEC, xv,NEC, Wv,NEC, v,NEC, mkEpi());
    // 7) decay: h64 = tanh(xwa @ decay_w1.T); w = -softplus(-(td + h64@decay_w2)) - 0.5
    gemm_kernel<128,64,16,8,8,EPI_TANH><<<dim3(1,32),128>>>(
        MT,64,NEC, xwa,NEC, decay_w1,NEC, h64,64, mkEpi());
    gemm_tc<EPI_W,false><<<dim3(8,32),256>>>(
        MT,NEC,64, h64,64, decay_w2,NEC, w,NEC, mkEpi(nullptr,nullptr,time_decay));
    // 8) kk_raw = k + tanh(xk @ kkk_w1.T) @ kkk_w2
    gemm_kernel<128,16,16,8,2,EPI_TANH><<<dim3(1,32),128>>>(
        MT,16,NEC, xk,NEC, kkk_w1,NEC, h16,16, mkEpi());
    gemm_tc<EPI_ADD,false><<<dim3(8,32),256>>>(
        MT,NEC,16, h16,16, kkk_w2,NEC, kk,NEC, mkEpi(k));
    // 9) a = sigmoid(time_aaaaa + (xwa@aaa_w1.T)@aaa_w2)
    gemm_kernel<128,16,16,8,2,EPI_NONE><<<dim3(1,32),128>>>(
        MT,16,NEC, xwa,NEC, aaa_w1,NEC, h16,16, mkEpi());
    gemm_tc<EPI_SIG,false><<<dim3(8,32),256>>>(
        MT,NEC,16, h16,16, aaa_w2,NEC, a,NEC, mkEpi(nullptr,nullptr,time_aaaaa));
    // 10) ma = sigmoid(time_misc_a + (xwa@ma_w1.T)@ma_w2)
    gemm_kernel<128,16,16,8,2,EPI_NONE><<<dim3(1,32),128>>>(
        MT,16,NEC, xwa,NEC, ma_w1,NEC, h16,16, mkEpi());
    gemm_tc<EPI_SIG,false><<<dim3(8,32),256>>>(
        MT,NEC,16, h16,16, ma_w2,NEC, ma,NEC, mkEpi(nullptr,nullptr,time_misc_a));
    // 11) mk = sigmoid(time_misc_k + (xk@mk_w1.T)@mk_w2)
    gemm_kernel<128,16,16,8,2,EPI_NONE><<<dim3(1,32),128>>>(
        MT,16,NEC, xk,NEC, mk_w1,NEC, h16,16, mkEpi());
    gemm_tc<EPI_SIG,false><<<dim3(8,32),256>>>(
        MT,NEC,16, h16,16, mk_w2,NEC, mk,NEC, mkEpi(nullptr,nullptr,time_misc_k));

    // 12) prep
    prep_kernel<<<MT,512>>>(k, kk, a, ma, mk, w, b);

    // 13) recurrence
    wkv7_kernel<<<BATCH*NH,128>>>(r, w, k, v, kk, b, y);

    // 14) groupnorm + bonus + gate
    gn_kernel<<<MT,512>>>(y, r, k, v, gg, ln_w, ln_b, time_faaaa, z);

    // 15) out = z @ Wo.T
    gemm_tc<EPI_NONE,true><<<dim3(8,32),256>>>(
        MT,NEC,NEC, z,NEC, Wo,NEC, out,NEC, mkEpi());
}

// round 3
// speedup vs baseline: 1.5612x; 1.2936x over previous
#include <cuda_runtime.h>
#include <math.h>
#include <stdint.h>

// Problem constants
#define BATCH 4
#define TSEQ  1024
#define NEC   1024
#define NH    16
#define HSZ   64
#define MT    (BATCH*TSEQ)      // 4096 rows
#define EPSGN 0.00064f

// ---------------------------------------------------------------------------
// Scratch (device globals)
// ---------------------------------------------------------------------------
__device__ float g_xx   [(size_t)MT*NEC];
__device__ float g_mix  [(size_t)MT*NEC];
__device__ float g_hmaa [(size_t)MT*128];
__device__ float g_hgate[(size_t)MT*128];
__device__ float g_hdec [(size_t)MT*64];
__device__ float g_haaa [(size_t)MT*16];
__device__ float g_hma  [(size_t)MT*16];
__device__ float g_hkkk [(size_t)MT*16];
__device__ float g_hmk  [(size_t)MT*16];
__device__ float g_xm   [4][(size_t)MT*NEC];
__device__ float g_r    [(size_t)MT*NEC];
__device__ float g_gg   [(size_t)MT*NEC];
__device__ float g_k    [(size_t)MT*NEC];
__device__ float g_v    [(size_t)MT*NEC];
__device__ float g_w    [(size_t)MT*NEC];
__device__ float g_kk   [(size_t)MT*NEC];
__device__ float g_a    [(size_t)MT*NEC];
__device__ float g_ma   [(size_t)MT*NEC];
__device__ float g_mk   [(size_t)MT*NEC];
__device__ float g_b    [(size_t)MT*NEC];
__device__ float g_y    [(size_t)MT*NEC];
__device__ float g_z    [(size_t)MT*NEC];

enum { EPI_NONE=0, EPI_W=3, EPI_ADD=4, EPI_SIG=5 };

// ---------------------------------------------------------------------------
// Token shift
// ---------------------------------------------------------------------------
__global__ void shift_kernel(const float* __restrict__ x,
                             const float* __restrict__ tmaax,
                             float* __restrict__ xx,
                             float* __restrict__ mix)
{
    size_t i = (size_t)blockIdx.x * blockDim.x + threadIdx.x;
    if (i >= (size_t)MT * NEC) return;
    int c = (int)(i % NEC);
    size_t row = i / NEC;
    int t = (int)(row % TSEQ);
    float xv = x[i];
    float xp = (t > 0) ? x[i - NEC] : 0.f;
    float d = xp - xv;
    xx[i]  = d;
    mix[i] = fmaf(d, tmaax[c], xv);
}

// ---------------------------------------------------------------------------
// tf32 helpers
// ---------------------------------------------------------------------------
__device__ __forceinline__ uint32_t f2tf32(float v){
    uint32_t r; asm("cvt.rna.tf32.f32 %0, %1;" : "=r"(r) : "f"(v)); return r;
}
__device__ __forceinline__ void split_tf32(float v, uint32_t &hi, uint32_t &lo){
    hi = f2tf32(v);
    float rem = v - __uint_as_float(hi);
    lo = f2tf32(rem);
}
__device__ __forceinline__ void mma_tf32(float* c, const uint32_t* a, const uint32_t* b){
    asm volatile("mma.sync.aligned.m16n8k8.row.col.f32.tf32.tf32.f32 "
        "{%0,%1,%2,%3},{%4,%5,%6,%7},{%8,%9},{%0,%1,%2,%3};\n"
        : "+f"(c[0]), "+f"(c[1]), "+f"(c[2]), "+f"(c[3])
        : "r"(a[0]), "r"(a[1]), "r"(a[2]), "r"(a[3]), "r"(b[0]), "r"(b[1]));
}

// ---------------------------------------------------------------------------
// Big NT tensor-core GEMM, tf32 split-3, double-buffered.
//   C[M,N] = A[M,K] * B[N,K]^T, K=1024, lda=ldb=K, ldc=N.
// Tile 64x128xBK16. 256 threads, 2 CTAs/SM. Dynamic smem 60KB.
// ---------------------------------------------------------------------------
#define TC_LDS 20
#define TC_BUFW 7680   // words per buffer: A(64*20)*2 + B(128*20)*2

__global__ __launch_bounds__(256, 2)
void gemm_tc_nt(int M, int N, int K,
                const float* __restrict__ A,
                const float* __restrict__ B,
                float* __restrict__ C)
{
    extern __shared__ uint32_t sm[];
    const int tid = threadIdx.x;
    const int bn0 = blockIdx.x*128, bm0 = blockIdx.y*64;
    const int warp = tid>>5, lane = tid&31;
    const int grp = lane>>2, q = lane&3;
    const int wm = (warp>>2)*32, wn = (warp&3)*32;

    float acc[2][4][4];
    #pragma unroll
    for (int mi=0;mi<2;mi++)
        #pragma unroll
        for (int ni=0;ni<4;ni++)
            #pragma unroll
            for (int e=0;e<4;e++) acc[mi][ni][e]=0.f;

    const float* Abase = A + (size_t)bm0*K;
    const float* Bbase = B + (size_t)bn0*K;
    const int ar = tid>>2, ac = (tid&3)*4;   // A: 64 rows, 4 cols of f4
    // B: 128 rows in two halves

    float4 pa, pb0, pb1;

    // ---- prologue: load k-tile 0
    pa  = *(const float4*)(Abase + (size_t)ar*K + ac);
    pb0 = *(const float4*)(Bbase + (size_t)ar*K + ac);
    pb1 = *(const float4*)(Bbase + (size_t)(ar+64)*K + ac);
    {
        uint32_t* Ah = sm; uint32_t* Al = Ah+1280; uint32_t* Bh = Ah+2560; uint32_t* Bl = Ah+5120;
        uint32_t h,l;
        split_tf32(pa.x,h,l);  Ah[ar*TC_LDS+ac+0]=h; Al[ar*TC_LDS+ac+0]=l;
        split_tf32(pa.y,h,l);  Ah[ar*TC_LDS+ac+1]=h; Al[ar*TC_LDS+ac+1]=l;
        split_tf32(pa.z,h,l);  Ah[ar*TC_LDS+ac+2]=h; Al[ar*TC_LDS+ac+2]=l;
        split_tf32(pa.w,h,l);  Ah[ar*TC_LDS+ac+3]=h; Al[ar*TC_LDS+ac+3]=l;
        split_tf32(pb0.x,h,l); Bh[ar*TC_LDS+ac+0]=h; Bl[ar*TC_LDS+ac+0]=l;
        split_tf32(pb0.y,h,l); Bh[ar*TC_LDS+ac+1]=h; Bl[ar*TC_LDS+ac+1]=l;
        split_tf32(pb0.z,h,l); Bh[ar*TC_LDS+ac+2]=h; Bl[ar*TC_LDS+ac+2]=l;
        split_tf32(pb0.w,h,l); Bh[ar*TC_LDS+ac+3]=h; Bl[ar*TC_LDS+ac+3]=l;
        split_tf32(pb1.x,h,l); Bh[(ar+64)*TC_LDS+ac+0]=h; Bl[(ar+64)*TC_LDS+ac+0]=l;
        split_tf32(pb1.y,h,l); Bh[(ar+64)*TC_LDS+ac+1]=h; Bl[(ar+64)*TC_LDS+ac+1]=l;
        split_tf32(pb1.z,h,l); Bh[(ar+64)*TC_LDS+ac+2]=h; Bl[(ar+64)*TC_LDS+ac+2]=l;
        split_tf32(pb1.w,h,l); Bh[(ar+64)*TC_LDS+ac+3]=h; Bl[(ar+64)*TC_LDS+ac+3]=l;
    }
    __syncthreads();

    int p = 0;
    for (int kb = 0; kb < K; kb += 16) {
        const bool haveNext = (kb + 16 < K);
        if (haveNext) {
            pa  = *(const float4*)(Abase + (size_t)ar*K + kb+16 + ac);
            pb0 = *(const float4*)(Bbase + (size_t)ar*K + kb+16 + ac);
            pb1 = *(const float4*)(Bbase + (size_t)(ar+64)*K + kb+16 + ac);
        }
        // ---- compute on buffer p
        {
            const uint32_t* Ah = sm + p*TC_BUFW;
            const uint32_t* Al = Ah+1280;
            const uint32_t* Bh = Ah+2560;
            const uint32_t* Bl = Ah+5120;
            #pragma unroll
            for (int kc = 0; kc < 16; kc += 8) {
                uint32_t ah[2][4], al[2][4], bh[4][2], bl[4][2];
                #pragma unroll
                for (int mi = 0; mi < 2; mi++) {
                    int r0 = (wm + mi*16 + grp)*TC_LDS;
                    ah[mi][0]=Ah[r0          +kc+q  ]; al[mi][0]=Al[r0          +kc+q  ];
                    ah[mi][1]=Ah[r0+8*TC_LDS +kc+q  ]; al[mi][1]=Al[r0+8*TC_LDS +kc+q  ];
                    ah[mi][2]=Ah[r0          +kc+q+4]; al[mi][2]=Al[r0          +kc+q+4];
                    ah[mi][3]=Ah[r0+8*TC_LDS +kc+q+4]; al[mi][3]=Al[r0+8*TC_LDS +kc+q+4];
                }
                #pragma unroll
                for (int ni = 0; ni < 4; ni++) {
                    int c0 = (wn + ni*8 + grp)*TC_LDS;
                    bh[ni][0]=Bh[c0+kc+q]; bh[ni][1]=Bh[c0+kc+q+4];
                    bl[ni][0]=Bl[c0+kc+q]; bl[ni][1]=Bl[c0+kc+q+4];
                }
                #pragma unroll
                for (int mi = 0; mi < 2; mi++)
                    #pragma unroll
                    for (int ni = 0; ni < 4; ni++) {
                        mma_tf32(acc[mi][ni], ah[mi], bh[ni]);
                        mma_tf32(acc[mi][ni], ah[mi], bl[ni]);
                        mma_tf32(acc[mi][ni], al[mi], bh[ni]);
                    }
            }
        }
        // ---- store prefetched into other buffer
        if (haveNext) {
            uint32_t* Ah = sm + (p^1)*TC_BUFW;
            uint32_t* Al = Ah+1280; uint32_t* Bh = Ah+2560; uint32_t* Bl = Ah+5120;
            uint32_t h,l;
            split_tf32(pa.x,h,l);  Ah[ar*TC_LDS+ac+0]=h; Al[ar*TC_LDS+ac+0]=l;
            split_tf32(pa.y,h,l);  Ah[ar*TC_LDS+ac+1]=h; Al[ar*TC_LDS+ac+1]=l;
            split_tf32(pa.z,h,l);  Ah[ar*TC_LDS+ac+2]=h; Al[ar*TC_LDS+ac+2]=l;
            split_tf32(pa.w,h,l);  Ah[ar*TC_LDS+ac+3]=h; Al[ar*TC_LDS+ac+3]=l;
            split_tf32(pb0.x,h,l); Bh[ar*TC_LDS+ac+0]=h; Bl[ar*TC_LDS+ac+0]=l;
            split_tf32(pb0.y,h,l); Bh[ar*TC_LDS+ac+1]=h; Bl[ar*TC_LDS+ac+1]=l;
            split_tf32(pb0.z,h,l); Bh[ar*TC_LDS+ac+2]=h; Bl[ar*TC_LDS+ac+2]=l;
            split_tf32(pb0.w,h,l); Bh[ar*TC_LDS+ac+3]=h; Bl[ar*TC_LDS+ac+3]=l;
            split_tf32(pb1.x,h,l); Bh[(ar+64)*TC_LDS+ac+0]=h; Bl[(ar+64)*TC_LDS+ac+0]=l;
            split_tf32(pb1.y,h,l); Bh[(ar+64)*TC_LDS+ac+1]=h; Bl[(ar+64)*TC_LDS+ac+1]=l;
            split_tf32(pb1.z,h,l); Bh[(ar+64)*TC_LDS+ac+2]=h; Bl[(ar+64)*TC_LDS+ac+2]=l;
            split_tf32(pb1.w,h,l); Bh[(ar+64)*TC_LDS+ac+3]=h; Bl[(ar+64)*TC_LDS+ac+3]=l;
        }
        __syncthreads();
        p ^= 1;
    }

    // ---- epilogue
    #pragma unroll
    for (int mi = 0; mi < 2; mi++) {
        int row0 = bm0 + wm + mi*16 + grp;
        #pragma unroll
        for (int ni = 0; ni < 4; ni++) {
            int col = bn0 + wn + ni*8 + 2*q;
            *(float2*)&C[(size_t)row0*N + col]     = make_float2(acc[mi][ni][0], acc[mi][ni][1]);
            *(float2*)&C[(size_t)(row0+8)*N + col] = make_float2(acc[mi][ni][2], acc[mi][ni][3]);
        }
    }
}

// ---------------------------------------------------------------------------
// Grouped NT LoRA-hidden kernel: per tile C = act(A @ B_tile^T), K=1024.
// Tile 128x32xBK32, fp32, 256 threads, TM=4 TN=4.
// ---------------------------------------------------------------------------
struct NTTile { const float* B; float* C; int ldc; int nvalid; int tanhf; int asel; };
struct NTArgs { const float* Aptr[3]; NTTile t[12]; };

__global__ __launch_bounds__(256)
void lora_nt_kernel(NTArgs args)
{
    constexpr int BM=128, BN=32, BK=32, K=NEC;
    __shared__ float As[BK][BM+1];
    __shared__ float Bs[BK][BN+1];
    NTTile tl = args.t[blockIdx.x];
    const float* A = args.Aptr[tl.asel];
    const int bm0 = blockIdx.y*BM;
    const int tid = threadIdx.x;
    const int tx = tid & 7;     // 8 cols of TN=4
    const int ty = tid >> 3;    // 32 rows of TM=4

    float acc[4][4];
    #pragma unroll
    for (int i=0;i<4;i++)
        #pragma unroll
        for (int j=0;j<4;j++) acc[i][j]=0.f;

    for (int kb = 0; kb < K; kb += BK) {
        #pragma unroll
        for (int l = 0; l < 4; l++) {           // A: 1024 f4
            int idx = tid + l*256;
            int r = idx >> 3, c = (idx & 7)*4;
            float4 val = *(const float4*)(A + (size_t)(bm0+r)*K + kb + c);
            As[c+0][r]=val.x; As[c+1][r]=val.y; As[c+2][r]=val.z; As[c+3][r]=val.w;
        }
        {                                        // B: 256 f4
            int r = tid >> 3, c = (tid & 7)*4;
            float4 val = (r < tl.nvalid) ?
                *(const float4*)(tl.B + (size_t)r*K + kb + c) : make_float4(0,0,0,0);
            Bs[c+0][r]=val.x; Bs[c+1][r]=val.y; Bs[c+2][r]=val.z; Bs[c+3][r]=val.w;
        }
        __syncthreads();
        #pragma unroll
        for (int kk = 0; kk < BK; kk++) {
            float rm[4], rn[4];
            #pragma unroll
            for (int i=0;i<4;i++) rm[i] = As[kk][ty*4+i];
            #pragma unroll
            for (int j=0;j<4;j++) rn[j] = Bs[kk][tx*4+j];
            #pragma unroll
            for (int i=0;i<4;i++)
                #pragma unroll
                for (int j=0;j<4;j++) acc[i][j] = fmaf(rm[i], rn[j], acc[i][j]);
        }
        __syncthreads();
    }
    #pragma unroll
    for (int i=0;i<4;i++) {
        int row = bm0 + ty*4 + i;
        #pragma unroll
        for (int j=0;j<4;j++) {
            int col = tx*4 + j;
            if (col < tl.nvalid) {
                float vv = acc[i][j];
                if (tl.tanhf) vv = tanhf(vv);
                tl.C[(size_t)row*tl.ldc + col] = vv;
            }
        }
    }
}

// ---------------------------------------------------------------------------
// Fused xm kernel: grid.z = group g. C = x + xx*(Ag @ Bg + time_maa[g]).
// A = h_maa (+g*32) [4096,128], B = maa_w2[g] [32,1024]. Tile 128x128, K=32.
// ---------------------------------------------------------------------------
__global__ __launch_bounds__(256)
void xm_kernel(const float* __restrict__ hmaa,
               const float* __restrict__ maa_w2,
               const float* __restrict__ x,
               const float* __restrict__ xx,
               const float* __restrict__ time_maa,
               float* __restrict__ xmbase)
{
    constexpr int BM=128, BN=128, BK=32;
    __shared__ float As[BK][BM+1];
    __shared__ float Bs[BK][BN];
    const int g = blockIdx.z;
    const float* A = hmaa + g*32;               // lda = 128
    const float* B = maa_w2 + (size_t)g*32*NEC; // ldb = 1024
    float* C = xmbase + (size_t)g*MT*NEC;
    const float* tm = time_maa + g*NEC;
    const int bm0 = blockIdx.y*BM, bn0 = blockIdx.x*BN;
    const int tid = threadIdx.x;
    const int tx = tid & 15, ty = tid >> 4;     // 16x16 threads, TM=8 TN=8

    float acc[8][8];
    #pragma unroll
    for (int i=0;i<8;i++)
        #pragma unroll
        for (int j=0;j<8;j++) acc[i][j]=0.f;

    #pragma unroll
    for (int l = 0; l < 4; l++) {               // A: 128x32 = 1024 f4
        int idx = tid + l*256;
        int r = idx >> 3, c = (idx & 7)*4;
        float4 val = *(const float4*)(A + (size_t)(bm0+r)*128 + c);
        As[c+0][r]=val.x; As[c+1][r]=val.y; As[c+2][r]=val.z; As[c+3][r]=val.w;
    }
    #pragma unroll
    for (int l = 0; l < 4; l++) {               // B: 32x128 = 1024 f4
        int idx = tid + l*256;
        int r = idx >> 5, c = (idx & 31)*4;
        *(float4*)&Bs[r][c] = *(const float4*)(B + (size_t)r*NEC + bn0 + c);
    }
    __syncthreads();
    #pragma unroll
    for (int kk = 0; kk < BK; kk++) {
        float rm[8], rn[8];
        #pragma unroll
        for (int i=0;i<8;i++) rm[i] = As[kk][ty*8+i];
        #pragma unroll
        for (int j=0;j<8;j++) rn[j] = Bs[kk][tx*8+j];
        #pragma unroll
        for (int i=0;i<8;i++)
            #pragma unroll
            for (int j=0;j<8;j++) acc[i][j] = fmaf(rm[i], rn[j], acc[i][j]);
    }
    #pragma unroll
    for (int i=0;i<8;i++) {
        int row = bm0 + ty*8 + i;
        #pragma unroll
        for (int j=0;j<8;j++) {
            int col = bn0 + tx*8 + j;
            size_t idx = (size_t)row*NEC + col;
            C[idx] = fmaf(xx[idx], acc[i][j] + tm[col], x[idx]);
        }
    }
}

// ---------------------------------------------------------------------------
// Grouped second-stage NN kernel: C = epi(A[M,Kg] @ B[Kg,1024]).
// Tile 128x128xBK16, fp32. grid (8,32,6).
// ---------------------------------------------------------------------------
struct NNGroup { const float* A; const float* B; float* C; int K; int epi;
                 const float* e0; const float* e2; };
struct NNArgs { NNGroup g[6]; };

__global__ __launch_bounds__(256)
void lora_nn_kernel(NNArgs args)
{
    constexpr int BM=128, BN=128, BK=16;
    __shared__ float As[BK][BM+1];
    __shared__ float Bs[BK][BN];
    NNGroup grp = args.g[blockIdx.z];
    const int K = grp.K;
    const int bm0 = blockIdx.y*BM, bn0 = blockIdx.x*BN;
    const int tid = threadIdx.x;
    const int tx = tid & 15, ty = tid >> 4;

    float acc[8][8];
    #pragma unroll
    for (int i=0;i<8;i++)
        #pragma unroll
        for (int j=0;j<8;j++) acc[i][j]=0.f;

    for (int kb = 0; kb < K; kb += BK) {
        #pragma unroll
        for (int l = 0; l < 2; l++) {           // A: 128x16 = 512 f4
            int idx = tid + l*256;
            int r = idx >> 2, c = (idx & 3)*4;
            float4 val = *(const float4*)(grp.A + (size_t)(bm0+r)*K + kb + c);
            As[c+0][r]=val.x; As[c+1][r]=val.y; As[c+2][r]=val.z; As[c+3][r]=val.w;
        }
        #pragma unroll
        for (int l = 0; l < 2; l++) {           // B: 16x128 = 512 f4
            int idx = tid + l*256;
            int r = idx >> 5, c = (idx & 31)*4;
            *(float4*)&Bs[r][c] = *(const float4*)(grp.B + (size_t)(kb+r)*NEC + bn0 + c);
        }
        __syncthreads();
        #pragma unroll
        for (int kk = 0; kk < BK; kk++) {
            float rm[8], rn[8];
            #pragma unroll
            for (int i=0;i<8;i++) rm[i] = As[kk][ty*8+i];
            #pragma unroll
            for (int j=0;j<8;j++) rn[j] = Bs[kk][tx*8+j];
            #pragma unroll
            for (int i=0;i<8;i++)
                #pragma unroll
                for (int j=0;j<8;j++) acc[i][j] = fmaf(rm[i], rn[j], acc[i][j]);
        }
        __syncthreads();
    }
    #pragma unroll
    for (int i=0;i<8;i++) {
        int row = bm0 + ty*8 + i;
        #pragma unroll
        for (int j=0;j<8;j++) {
            int col = bn0 + tx*8 + j;
            size_t idx = (size_t)row*NEC + col;
            float vv = acc[i][j], outv;
            switch (grp.epi) {
                case EPI_W: {
                    float tt = -(grp.e2[col] + vv);
                    float sp = (tt > 15.f) ? tt : log1pf(expf(tt));
                    outv = -sp - 0.5f;
                } break;
                case EPI_ADD: outv = grp.e0[idx] + vv; break;
                case EPI_SIG: {
                    float u = grp.e2[col] + vv;
                    outv = 1.f / (1.f + expf(-u));
                } break;
                default: outv = vv;
            }
            grp.C[idx] = outv;
        }
    }
}

// ---------------------------------------------------------------------------
// warp sum
// ---------------------------------------------------------------------------
__device__ __forceinline__ float warp_sum(float v)
{
    #pragma unroll
    for (int o = 16; o > 0; o >>= 1) v += __shfl_xor_sync(0xffffffffu, v, o);
    return v;
}

// ---------------------------------------------------------------------------
// prep
// ---------------------------------------------------------------------------
__global__ void prep_kernel(float* kptr, float* kkptr,
                            const float* __restrict__ a,
                            const float* __restrict__ ma,
                            const float* __restrict__ mk,
                            float* wptr,
                            float* __restrict__ b)
{
    int m = blockIdx.x;
    int h = threadIdx.x >> 5;
    int lane = threadIdx.x & 31;
    size_t base = (size_t)m*NEC + h*HSZ;
    size_t i0 = base + lane, i1 = i0 + 32;

    float kk0 = kkptr[i0], kk1 = kkptr[i1];
    float ss = warp_sum(kk0*kk0 + kk1*kk1);
    float inv = 1.f / fmaxf(sqrtf(ss), 1e-12f);
    float n0 = kk0*inv, n1 = kk1*inv;
    kkptr[i0] = n0; kkptr[i1] = n1;

    float a0 = a[i0], a1 = a[i1];
    b[i0] = -n0*a0; b[i1] = -n1*a1;

    float ma0 = ma[i0], ma1 = ma[i1];
    float k0v = kptr[i0], k1v = kptr[i1];
    float w0 = wptr[i0], w1 = wptr[i1];
    float mk0 = mk[i0], mk1 = mk[i1];
    kptr[i0] = k0v * (ma0 + a0*(1.f - ma0)) * expf(w0*mk0);
    kptr[i1] = k1v * (ma1 + a1*(1.f - ma1)) * expf(w1*mk1);
    wptr[i0] = expf(-expf(w0));
    wptr[i1] = expf(-expf(w1));
}

// ---------------------------------------------------------------------------
// RWKV7 recurrence (2-way split rows)
// ---------------------------------------------------------------------------
__global__ __launch_bounds__(128)
void wkv7_kernel(const float* __restrict__ q, const float* __restrict__ w,
                 const float* __restrict__ k, const float* __restrict__ v,
                 const float* __restrict__ a, const float* __restrict__ b,
                 float* __restrict__ y)
{
    const int bh = blockIdx.x;
    const int batch = bh >> 4, h = bh & 15;
    const int tid = threadIdx.x;
    const int i = tid >> 1;
    const int half = tid & 1;

    __shared__ __align__(16) float buf[2][6][HSZ];

    float s[32];
    #pragma unroll
    for (int j = 0; j < 32; j++) s[j] = 0.f;

    size_t base = ((size_t)batch * TSEQ) * NEC + (size_t)h * HSZ;

    const int j0 = tid & 63;
    const int vsel = tid >> 6;
    const float* p0 = vsel ? w : q;
    const float* p1 = vsel ? a : k;
    const float* p2 = vsel ? v : b;
    const int v0i = vsel, v1i = 2 + vsel, v2i = 4 + vsel;

    buf[0][v0i][j0] = p0[base + j0];
    buf[0][v1i][j0] = p1[base + j0];
    buf[0][v2i][j0] = p2[base + j0];
    __syncthreads();

    int p = 0;
    for (int t = 0; t < TSEQ; t++) {
        if (t + 1 < TSEQ) {
            size_t o = base + (size_t)(t+1)*NEC + j0;
            buf[p^1][v0i][j0] = p0[o];
            buf[p^1][v1i][j0] = p1[o];
            buf[p^1][v2i][j0] = p2[o];
        }
        const float4* qj = (const float4*)&buf[p][0][half*32];
        const float4* wj = (const float4*)&buf[p][1][half*32];
        const float4* kj = (const float4*)&buf[p][2][half*32];
        const float4* aj = (const float4*)&buf[p][3][half*32];
        const float4* bj = (const float4*)&buf[p][4][half*32];
        float vi = buf[p][5][i];

        float sa = 0.f;
        #pragma unroll
        for (int j4 = 0; j4 < 8; j4++) {
            float4 av = aj[j4];
            sa = fmaf(s[j4*4+0], av.x, sa);
            sa = fmaf(s[j4*4+1], av.y, sa);
            sa = fmaf(s[j4*4+2], av.z, sa);
            sa = fmaf(s[j4*4+3], av.w, sa);
        }
        sa += __shfl_xor_sync(0xffffffffu, sa, 1);

        float yi = 0.f;
        #pragma unroll
        for (int j4 = 0; j4 < 8; j4++) {
            float4 wv = wj[j4], kv = kj[j4], bv = bj[j4], qv = qj[j4];
            float s0 = fmaf(s[j4*4+0], wv.x, fmaf(sa, bv.x, vi*kv.x));
            float s1 = fmaf(s[j4*4+1], wv.y, fmaf(sa, bv.y, vi*kv.y));
            float s2 = fmaf(s[j4*4+2], wv.z, fmaf(sa, bv.z, vi*kv.z));
            float s3 = fmaf(s[j4*4+3], wv.w, fmaf(sa, bv.w, vi*kv.w));
            yi = fmaf(s0, qv.x, yi);
            yi = fmaf(s1, qv.y, yi);
            yi = fmaf(s2, qv.z, yi);
            yi = fmaf(s3, qv.w, yi);
            s[j4*4+0] = s0; s[j4*4+1] = s1; s[j4*4+2] = s2; s[j4*4+3] = s3;
        }
        yi += __shfl_xor_sync(0xffffffffu, yi, 1);
        if (half == 0) y[base + (size_t)t*NEC + i] = yi;
        p ^= 1;
        __syncthreads();
    }
}

// ---------------------------------------------------------------------------
// GroupNorm + bonus + gate
// ---------------------------------------------------------------------------
__global__ void gn_kernel(const float* __restrict__ y,
                          const float* __restrict__ r,
                          const float* __restrict__ k,
                          const float* __restrict__ v,
                          const float* __restrict__ gg,
                          const float* __restrict__ ln_w,
                          const float* __restrict__ ln_b,
                          const float* __restrict__ faaaa,
                          float* __restrict__ z)
{
    int m = blockIdx.x;
    int h = threadIdx.x >> 5;
    int lane = threadIdx.x & 31;
    size_t base = (size_t)m*NEC + h*HSZ;
    int c0 = h*HSZ + lane, c1 = c0 + 32;
    size_t i0 = base + lane, i1 = i0 + 32;

    float y0 = y[i0], y1 = y[i1];
    float mu = warp_sum(y0 + y1) * (1.f/64.f);
    float d0 = y0 - mu, d1 = y1 - mu;
    float var = warp_sum(d0*d0 + d1*d1) * (1.f/64.f);
    float rstd = rsqrtf(var + EPSGN);
    float yn0 = d0*rstd*ln_w[c0] + ln_b[c0];
    float yn1 = d1*rstd*ln_w[c1] + ln_b[c1];

    float r0 = r[i0], r1 = r[i1];
    float k0v = k[i0], k1v = k[i1];
    float rk = warp_sum(r0*k0v*faaaa[c0] + r1*k1v*faaaa[c1]);

    float v0 = v[i0], v1 = v[i1];
    z[i0] = (yn0 + rk*v0) * gg[i0];
    z[i1] = (yn1 + rk*v1) * gg[i1];
}

// ---------------------------------------------------------------------------
// Host side
// ---------------------------------------------------------------------------
extern "C" void kernel_launch(void* const* d_in, const int* in_sizes, int n_in,
                              void* d_out, int out_size)
{
    const float* x          = (const float*)d_in[0];
    const float* time_maa_x = (const float*)d_in[1];
    const float* time_maa   = (const float*)d_in[2];
    const float* maa_w1     = (const float*)d_in[3];
    const float* maa_w2     = (const float*)d_in[4];
    const float* decay_w1   = (const float*)d_in[5];
    const float* decay_w2   = (const float*)d_in[6];
    const float* aaa_w1     = (const float*)d_in[7];
    const float* aaa_w2     = (const float*)d_in[8];
    const float* kkk_w1     = (const float*)d_in[9];
    const float* kkk_w2     = (const float*)d_in[10];
    const float* gate_w1    = (const float*)d_in[11];
    const float* gate_w2    = (const float*)d_in[12];
    const float* ma_w1      = (const float*)d_in[13];
    const float* ma_w2      = (const float*)d_in[14];
    const float* mk_w1      = (const float*)d_in[15];
    const float* mk_w2      = (const float*)d_in[16];
    const float* time_decay = (const float*)d_in[17];
    const float* time_faaaa = (const float*)d_in[18];
    const float* time_aaaaa = (const float*)d_in[19];
    const float* time_misc_a= (const float*)d_in[20];
    const float* time_misc_k= (const float*)d_in[21];
    const float* Wr         = (const float*)d_in[22];
    const float* Wk         = (const float*)d_in[23];
    const float* Wv         = (const float*)d_in[24];
    const float* Wo         = (const float*)d_in[25];
    const float* ln_w       = (const float*)d_in[26];
    const float* ln_b       = (const float*)d_in[27];
    float* out = (float*)d_out;

    float *xx,*mix,*hmaa,*hgate,*hdec,*haaa,*hma,*hkkk,*hmk,*xm;
    float *r,*gg,*k,*v,*w,*kk,*a,*ma,*mk,*b,*y,*z;
    cudaGetSymbolAddress((void**)&xx,   g_xx);
    cudaGetSymbolAddress((void**)&mix,  g_mix);
    cudaGetSymbolAddress((void**)&hmaa, g_hmaa);
    cudaGetSymbolAddress((void**)&hgate,g_hgate);
    cudaGetSymbolAddress((void**)&hdec, g_hdec);
    cudaGetSymbolAddress((void**)&haaa, g_haaa);
    cudaGetSymbolAddress((void**)&hma,  g_hma);
    cudaGetSymbolAddress((void**)&hkkk, g_hkkk);
    cudaGetSymbolAddress((void**)&hmk,  g_hmk);
    cudaGetSymbolAddress((void**)&xm,   g_xm);
    cudaGetSymbolAddress((void**)&r,    g_r);
    cudaGetSymbolAddress((void**)&gg,   g_gg);
    cudaGetSymbolAddress((void**)&k,    g_k);
    cudaGetSymbolAddress((void**)&v,    g_v);
    cudaGetSymbolAddress((void**)&w,    g_w);
    cudaGetSymbolAddress((void**)&kk,   g_kk);
    cudaGetSymbolAddress((void**)&a,    g_a);
    cudaGetSymbolAddress((void**)&ma,   g_ma);
    cudaGetSymbolAddress((void**)&mk,   g_mk);
    cudaGetSymbolAddress((void**)&b,    g_b);
    cudaGetSymbolAddress((void**)&y,    g_y);
    cudaGetSymbolAddress((void**)&z,    g_z);

    const float* xrg = xm + 0*(size_t)MT*NEC;
    const float* xwa = xm + 1*(size_t)MT*NEC;
    const float* xk  = xm + 2*(size_t)MT*NEC;
    const float* xv  = xm + 3*(size_t)MT*NEC;

    static bool attr_done = false;
    if (!attr_done) {
        cudaFuncSetAttribute(gemm_tc_nt, cudaFuncAttributeMaxDynamicSharedMemorySize,
                             2*TC_BUFW*4);
        attr_done = true;
    }
    const int tc_smem = 2*TC_BUFW*4;

    // 1) token shift
    {
        size_t n = (size_t)MT*NEC;
        shift_kernel<<<(unsigned)((n + 255)/256), 256>>>(x, time_maa_x, xx, mix);
    }

    // 2) maa hidden (4 tiles)
    {
        NTArgs na = {};
        na.Aptr[0] = mix;
        for (int i = 0; i < 4; i++)
            na.t[i] = { maa_w1 + (size_t)i*32*NEC, hmaa + i*32, 128, 32, 1, 0 };
        lora_nt_kernel<<<dim3(4, MT/128), 256>>>(na);
    }

    // 3) xm fused (4 groups)
    xm_kernel<<<dim3(8, MT/128, 4), 256>>>(hmaa, maa_w2, x, xx, time_maa, xm);

    // 4) hidden group 2: gate/decay/aaa/ma/kkk/mk (10 tiles)
    {
        NTArgs na = {};
        na.Aptr[0] = xrg; na.Aptr[1] = xwa; na.Aptr[2] = xk;
        int ti = 0;
        for (int i = 0; i < 4; i++)
            na.t[ti++] = { gate_w1 + (size_t)i*32*NEC, hgate + i*32, 128, 32, 1, 0 };
        for (int i = 0; i < 2; i++)
            na.t[ti++] = { decay_w1 + (size_t)i*32*NEC, hdec + i*32, 64, 32, 1, 1 };
        na.t[ti++] = { aaa_w1, haaa, 16, 16, 0, 1 };
        na.t[ti++] = { ma_w1,  hma,  16, 16, 0, 1 };
        na.t[ti++] = { kkk_w1, hkkk, 16, 16, 1, 2 };
        na.t[ti++] = { mk_w1,  hmk,  16, 16, 0, 2 };
        lora_nt_kernel<<<dim3(10, MT/128), 256>>>(na);
    }

    // 5) big GEMMs: r, k, v
    gemm_tc_nt<<<dim3(NEC/128, MT/64), 256, tc_smem>>>(MT, NEC, NEC, xrg, Wr, r);
    gemm_tc_nt<<<dim3(NEC/128, MT/64), 256, tc_smem>>>(MT, NEC, NEC, xk,  Wk, k);
    gemm_tc_nt<<<dim3(NEC/128, MT/64), 256, tc_smem>>>(MT, NEC, NEC, xv,  Wv, v);

    // 6) second stage: gg, w, kk, a, ma, mk (6 groups)
    {
        NNArgs nn = {};
        nn.g[0] = { hgate, gate_w2,  gg, 128, EPI_NONE, nullptr, nullptr };
        nn.g[1] = { hdec,  decay_w2, w,   64, EPI_W,    nullptr, time_decay };
        nn.g[2] = { hkkk,  kkk_w2,   kk,  16, EPI_ADD,  k,       nullptr };
        nn.g[3] = { haaa,  aaa_w2,   a,   16, EPI_SIG,  nullptr, time_aaaaa };
        nn.g[4] = { hma,   ma_w2,    ma,  16, EPI_SIG,  nullptr, time_misc_a };
        nn.g[5] = { hmk,   mk_w2,    mk,  16, EPI_SIG,  nullptr, time_misc_k };
        lora_nn_kernel<<<dim3(8, MT/128, 6), 256>>>(nn);
    }

    // 7) prep
    prep_kernel<<<MT, 512>>>(k, kk, a, ma, mk, w, b);

    // 8) recurrence
    wkv7_kernel<<<BATCH*NH, 128>>>(r, w, k, v, kk, b, y);

    // 9) groupnorm + bonus + gate
    gn_kernel<<<MT, 512>>>(y, r, k, v, gg, ln_w, ln_b, time_faaaa, z);

    // 10) out = z @ Wo.T
    gemm_tc_nt<<<dim3(NEC/128, MT/64), 256, tc_smem>>>(MT, NEC, NEC, z, Wo, out);
}

// round 4
// speedup vs baseline: 1.7543x; 1.1237x over previous
#include <cuda_runtime.h>
#include <math.h>
#include <stdint.h>

// Problem constants
#define BATCH 4
#define TSEQ  1024
#define NEC   1024
#define NH    16
#define HSZ   64
#define MT    (BATCH*TSEQ)      // 4096 rows
#define EPSGN 0.00064f
#define NM    ((size_t)NEC*NEC) // 1M

// ---------------------------------------------------------------------------
// Scratch (device globals)
// ---------------------------------------------------------------------------
__device__ float g_xx   [(size_t)MT*NEC];
__device__ float g_mix  [(size_t)MT*NEC];
__device__ float g_hmaa [(size_t)MT*128];
__device__ float g_hgate[(size_t)MT*128];
__device__ float g_hdec [(size_t)MT*64];
__device__ float g_haaa [(size_t)MT*16];
__device__ float g_hma  [(size_t)MT*16];
__device__ float g_hkkk [(size_t)MT*16];
__device__ float g_hmk  [(size_t)MT*16];
__device__ float g_xm   [4][(size_t)MT*NEC];
__device__ float g_ahi  [3][(size_t)MT*NEC];   // xrg, xk, xv (tf32 hi)
__device__ float g_alo  [3][(size_t)MT*NEC];   // (tf32 lo)
__device__ float g_zhi  [(size_t)MT*NEC];
__device__ float g_zlo  [(size_t)MT*NEC];
__device__ float g_whi  [4*NM];                // Wr,Wk,Wv,Wo hi
__device__ float g_wlo  [4*NM];
__device__ float g_r    [(size_t)MT*NEC];
__device__ float g_gg   [(size_t)MT*NEC];
__device__ float g_k    [(size_t)MT*NEC];
__device__ float g_v    [(size_t)MT*NEC];
__device__ float g_w    [(size_t)MT*NEC];
__device__ float g_kk   [(size_t)MT*NEC];
__device__ float g_a    [(size_t)MT*NEC];
__device__ float g_ma   [(size_t)MT*NEC];
__device__ float g_mk   [(size_t)MT*NEC];
__device__ float g_b    [(size_t)MT*NEC];
__device__ float g_y    [(size_t)MT*NEC];

enum { EPI_NONE=0, EPI_W=3, EPI_ADD=4, EPI_SIG=5 };

// ---------------------------------------------------------------------------
// tf32 helpers
// ---------------------------------------------------------------------------
__device__ __forceinline__ uint32_t f2tf32(float v){
    uint32_t r; asm("cvt.rna.tf32.f32 %0, %1;" : "=r"(r) : "f"(v)); return r;
}
__device__ __forceinline__ void split_tf32(float v, uint32_t &hi, uint32_t &lo){
    hi = f2tf32(v);
    float rem = v - __uint_as_float(hi);
    lo = f2tf32(rem);
}
__device__ __forceinline__ void mma_tf32(float* c, const uint32_t* a, const uint32_t* b){
    asm volatile("mma.sync.aligned.m16n8k8.row.col.f32.tf32.tf32.f32 "
        "{%0,%1,%2,%3},{%4,%5,%6,%7},{%8,%9},{%0,%1,%2,%3};\n"
        : "+f"(c[0]), "+f"(c[1]), "+f"(c[2]), "+f"(c[3])
        : "r"(a[0]), "r"(a[1]), "r"(a[2]), "r"(a[3]), "r"(b[0]), "r"(b[1]));
}
__device__ __forceinline__ void cpa16(uint32_t dst, const void* src){
    asm volatile("cp.async.cg.shared.global [%0],[%1],16;\n"::"r"(dst),"l"(src));
}
#define CP_COMMIT() asm volatile("cp.async.commit_group;\n")
#define CP_WAIT0()  asm volatile("cp.async.wait_group 0;\n")

// ---------------------------------------------------------------------------
// Token shift
// ---------------------------------------------------------------------------
__global__ void shift_kernel(const float* __restrict__ x,
                             const float* __restrict__ tmaax,
                             float* __restrict__ xx,
                             float* __restrict__ mix)
{
    size_t i = (size_t)blockIdx.x * blockDim.x + threadIdx.x;
    if (i >= (size_t)MT * NEC) return;
    int c = (int)(i % NEC);
    size_t row = i / NEC;
    int t = (int)(row % TSEQ);
    float xv = x[i];
    float xp = (t > 0) ? x[i - NEC] : 0.f;
    float d = xp - xv;
    xx[i]  = d;
    mix[i] = fmaf(d, tmaax[c], xv);
}

// ---------------------------------------------------------------------------
// Weight split (tf32 hi/lo) for Wr,Wk,Wv,Wo
// ---------------------------------------------------------------------------
__global__ void wsplit_kernel(const float* __restrict__ Wr, const float* __restrict__ Wk,
                              const float* __restrict__ Wv, const float* __restrict__ Wo,
                              float* __restrict__ whi, float* __restrict__ wlo)
{
    size_t i = (size_t)blockIdx.x * blockDim.x + threadIdx.x;
    if (i >= 4*NM) return;
    int seg = (int)(i >> 20);       // NM = 2^20
    size_t off = i & (NM - 1);
    const float* src = (seg==0) ? Wr : (seg==1) ? Wk : (seg==2) ? Wv : Wo;
    uint32_t h, l; split_tf32(src[off], h, l);
    whi[i] = __uint_as_float(h);
    wlo[i] = __uint_as_float(l);
}

// ---------------------------------------------------------------------------
// Pure-tf32 pre-split GEMM: C[M,N] = (Ah+Al)[M,K] * (Bh+Bl)[N,K]^T  (3 combos)
// Tile 128x128x16, 256 threads, cp.async double-buffered, 2 CTA/SM.
// ---------------------------------------------------------------------------
#define G2_LDS 20
#define G2_STG 10240   // floats per stage: 4 arrays * 128*20

__global__ __launch_bounds__(256, 2)
void gemm_tc2(const float* __restrict__ Ahg, const float* __restrict__ Alg,
              const float* __restrict__ Bhg, const float* __restrict__ Blg,
              float* __restrict__ C, int M, int N, int K)
{
    extern __shared__ float sm2[];
    const int tid = threadIdx.x;
    const int bm0 = blockIdx.y*128, bn0 = blockIdx.x*128;
    const int warp = tid>>5, lane = tid&31, grp = lane>>2, q = lane&3;
    const int wm = (warp&1)*64, wn = (warp>>1)*32;

    const int lr = tid>>2, lc = (tid&3)*4;
    const uint32_t sbase = (uint32_t)__cvta_generic_to_shared(sm2);

    float acc[4][4][4];
    #pragma unroll
    for (int mi=0;mi<4;mi++)
        #pragma unroll
        for (int ni=0;ni<4;ni++)
            #pragma unroll
            for (int e=0;e<4;e++) acc[mi][ni][e]=0.f;

    const float* pAh = Ahg + (size_t)(bm0+lr)*K + lc;
    const float* pAl = Alg + (size_t)(bm0+lr)*K + lc;
    const float* pBh = Bhg + (size_t)(bn0+lr)*K + lc;
    const float* pBl = Blg + (size_t)(bn0+lr)*K + lc;
    const uint32_t d0 = (lr*G2_LDS + lc)*4;
    const uint32_t d1 = ((lr+64)*G2_LDS + lc)*4;

#define G2_LOAD(st, kb) do {                                             \
        uint32_t _b = sbase + (st)*G2_STG*4;                             \
        cpa16(_b + d0,           pAh + (kb));                            \
        cpa16(_b + d1,           pAh + 64*(size_t)K + (kb));             \
        cpa16(_b + 2560*4 + d0,  pAl + (kb));                            \
        cpa16(_b + 2560*4 + d1,  pAl + 64*(size_t)K + (kb));             \
        cpa16(_b + 5120*4 + d0,  pBh + (kb));                            \
        cpa16(_b + 5120*4 + d1,  pBh + 64*(size_t)K + (kb));             \
        cpa16(_b + 7680*4 + d0,  pBl + (kb));                            \
        cpa16(_b + 7680*4 + d1,  pBl + 64*(size_t)K + (kb));             \
    } while(0)

    G2_LOAD(0, 0); CP_COMMIT();

    int p = 0;
    for (int kb = 0; kb < K; kb += 16) {
        CP_WAIT0();
        __syncthreads();
        if (kb + 16 < K) { G2_LOAD(p^1, kb+16); CP_COMMIT(); }

        const float* Ah = sm2 + p*G2_STG;
        const float* Al = Ah + 2560;
        const float* Bh = Ah + 5120;
        const float* Bl = Ah + 7680;

        #pragma unroll
        for (int kc = 0; kc < 16; kc += 8) {
            uint32_t ah[4][4], al[4][4], bh[4][2], bl[4][2];
            #pragma unroll
            for (int mi = 0; mi < 4; mi++) {
                int r0 = (wm + mi*16 + grp)*G2_LDS;
                ah[mi][0]=__float_as_uint(Ah[r0          +kc+q  ]);
                ah[mi][1]=__float_as_uint(Ah[r0+8*G2_LDS +kc+q  ]);
                ah[mi][2]=__float_as_uint(Ah[r0          +kc+q+4]);
                ah[mi][3]=__float_as_uint(Ah[r0+8*G2_LDS +kc+q+4]);
                al[mi][0]=__float_as_uint(Al[r0          +kc+q  ]);
                al[mi][1]=__float_as_uint(Al[r0+8*G2_LDS +kc+q  ]);
                al[mi][2]=__float_as_uint(Al[r0          +kc+q+4]);
                al[mi][3]=__float_as_uint(Al[r0+8*G2_LDS +kc+q+4]);
            }
            #pragma unroll
            for (int ni = 0; ni < 4; ni++) {
                int c0 = (wn + ni*8 + grp)*G2_LDS;
                bh[ni][0]=__float_as_uint(Bh[c0+kc+q]);
                bh[ni][1]=__float_as_uint(Bh[c0+kc+q+4]);
                bl[ni][0]=__float_as_uint(Bl[c0+kc+q]);
                bl[ni][1]=__float_as_uint(Bl[c0+kc+q+4]);
            }
            #pragma unroll
            for (int mi = 0; mi < 4; mi++)
                #pragma unroll
                for (int ni = 0; ni < 4; ni++) {
                    mma_tf32(acc[mi][ni], ah[mi], bh[ni]);
                    mma_tf32(acc[mi][ni], ah[mi], bl[ni]);
                    mma_tf32(acc[mi][ni], al[mi], bh[ni]);
                }
        }
        __syncthreads();
        p ^= 1;
    }

    #pragma unroll
    for (int mi = 0; mi < 4; mi++) {
        int row0 = bm0 + wm + mi*16 + grp;
        #pragma unroll
        for (int ni = 0; ni < 4; ni++) {
            int col = bn0 + wn + ni*8 + 2*q;
            *(float2*)&C[(size_t)row0*N + col]     = make_float2(acc[mi][ni][0], acc[mi][ni][1]);
            *(float2*)&C[(size_t)(row0+8)*N + col] = make_float2(acc[mi][ni][2], acc[mi][ni][3]);
        }
    }
#undef G2_LOAD
}

// ---------------------------------------------------------------------------
// Grouped NT LoRA-hidden kernel v2: C = act(A @ B_tile^T), K=1024.
// Tile 128x32xBK32, fp32, 128 threads, TM=8 TN=4, float4 smem reads.
// ---------------------------------------------------------------------------
struct NTTile { const float* B; float* C; int ldc; int nvalid; int tanhf; int asel; };
struct NTArgs { const float* Aptr[3]; NTTile t[12]; };

__global__ __launch_bounds__(128)
void lora_nt_kernel(NTArgs args)
{
    constexpr int BK=32, K=NEC;
    __shared__ __align__(16) float As[BK][132];
    __shared__ __align__(16) float Bs[BK][36];
    NTTile tl = args.t[blockIdx.x];
    const float* A = args.Aptr[tl.asel];
    const int bm0 = blockIdx.y*128;
    const int tid = threadIdx.x;
    const int tx = tid & 7;     // 8 cols of TN=4
    const int ty = tid >> 3;    // 16 rows of TM=8

    float acc[8][4];
    #pragma unroll
    for (int i=0;i<8;i++)
        #pragma unroll
        for (int j=0;j<4;j++) acc[i][j]=0.f;

    for (int kb = 0; kb < K; kb += BK) {
        #pragma unroll
        for (int l = 0; l < 8; l++) {           // A: 128x32 = 1024 f4
            int idx = tid + l*128;
            int r = idx >> 3, c = (idx & 7)*4;
            float4 val = *(const float4*)(A + (size_t)(bm0+r)*K + kb + c);
            As[c+0][r]=val.x; As[c+1][r]=val.y; As[c+2][r]=val.z; As[c+3][r]=val.w;
        }
        #pragma unroll
        for (int l = 0; l < 2; l++) {           // B: 32x32 = 256 f4
            int idx = tid + l*128;
            int r = idx >> 3, c = (idx & 7)*4;
            float4 val = (r < tl.nvalid) ?
                *(const float4*)(tl.B + (size_t)r*K + kb + c) : make_float4(0,0,0,0);
            Bs[c+0][r]=val.x; Bs[c+1][r]=val.y; Bs[c+2][r]=val.z; Bs[c+3][r]=val.w;
        }
        __syncthreads();
        #pragma unroll
        for (int kk = 0; kk < BK; kk++) {
            float4 m0 = *(const float4*)&As[kk][ty*8];
            float4 m1 = *(const float4*)&As[kk][ty*8+4];
            float4 rn = *(const float4*)&Bs[kk][tx*4];
            float rm[8] = {m0.x,m0.y,m0.z,m0.w,m1.x,m1.y,m1.z,m1.w};
            #pragma unroll
            for (int i=0;i<8;i++) {
                acc[i][0] = fmaf(rm[i], rn.x, acc[i][0]);
                acc[i][1] = fmaf(rm[i], rn.y, acc[i][1]);
                acc[i][2] = fmaf(rm[i], rn.z, acc[i][2]);
                acc[i][3] = fmaf(rm[i], rn.w, acc[i][3]);
            }
        }
        __syncthreads();
    }
    #pragma unroll
    for (int i=0;i<8;i++) {
        int row = bm0 + ty*8 + i;
        #pragma unroll
        for (int j=0;j<4;j++) {
            int col = tx*4 + j;
            if (col < tl.nvalid) {
                float vv = acc[i][j];
                if (tl.tanhf) vv = tanhf(vv);
                tl.C[(size_t)row*tl.ldc + col] = vv;
            }
        }
    }
}

// ---------------------------------------------------------------------------
// Fused xm kernel: grid.z = group g. C = x + xx*(Ag @ Bg + time_maa[g]).
// Also emits tf32 hi/lo for xrg (g0), xk (g2), xv (g3); skips fp32 for g3.
// ---------------------------------------------------------------------------
__global__ __launch_bounds__(256)
void xm_kernel(const float* __restrict__ hmaa,
               const float* __restrict__ maa_w2,
               const float* __restrict__ x,
               const float* __restrict__ xx,
               const float* __restrict__ time_maa,
               float* __restrict__ xmbase,
               float* __restrict__ ahibase,
               float* __restrict__ alobase)
{
    constexpr int BM=128, BN=128, BK=32;
    __shared__ float As[BK][BM+1];
    __shared__ float Bs[BK][BN];
    const int g = blockIdx.z;
    const float* A = hmaa + g*32;               // lda = 128
    const float* B = maa_w2 + (size_t)g*32*NEC; // ldb = 1024
    float* C = xmbase + (size_t)g*MT*NEC;
    const int slot = (g==0) ? 0 : (g==2) ? 1 : 2;
    float* HI = ahibase + (size_t)slot*MT*NEC;
    float* LO = alobase + (size_t)slot*MT*NEC;
    const float* tm = time_maa + g*NEC;
    const int bm0 = blockIdx.y*BM, bn0 = blockIdx.x*BN;
    const int tid = threadIdx.x;
    const int tx = tid & 15, ty = tid >> 4;

    float acc[8][8];
    #pragma unroll
    for (int i=0;i<8;i++)
        #pragma unroll
        for (int j=0;j<8;j++) acc[i][j]=0.f;

    #pragma unroll
    for (int l = 0; l < 4; l++) {
        int idx = tid + l*256;
        int r = idx >> 3, c = (idx & 7)*4;
        float4 val = *(const float4*)(A + (size_t)(bm0+r)*128 + c);
        As[c+0][r]=val.x; As[c+1][r]=val.y; As[c+2][r]=val.z; As[c+3][r]=val.w;
    }
    #pragma unroll
    for (int l = 0; l < 4; l++) {
        int idx = tid + l*256;
        int r = idx >> 5, c = (idx & 31)*4;
        *(float4*)&Bs[r][c] = *(const float4*)(B + (size_t)r*NEC + bn0 + c);
    }
    __syncthreads();
    #pragma unroll
    for (int kk = 0; kk < BK; kk++) {
        float rm[8], rn[8];
        #pragma unroll
        for (int i=0;i<8;i++) rm[i] = As[kk][ty*8+i];
        #pragma unroll
        for (int j=0;j<8;j++) rn[j] = Bs[kk][tx*8+j];
        #pragma unroll
        for (int i=0;i<8;i++)
            #pragma unroll
            for (int j=0;j<8;j++) acc[i][j] = fmaf(rm[i], rn[j], acc[i][j]);
    }
    #pragma unroll
    for (int i=0;i<8;i++) {
        int row = bm0 + ty*8 + i;
        #pragma unroll
        for (int j=0;j<8;j++) {
            int col = bn0 + tx*8 + j;
            size_t idx = (size_t)row*NEC + col;
            float val = fmaf(xx[idx], acc[i][j] + tm[col], x[idx]);
            if (g != 3) C[idx] = val;
            if (g != 1) {
                uint32_t h, l; split_tf32(val, h, l);
                HI[idx] = __uint_as_float(h);
                LO[idx] = __uint_as_float(l);
            }
        }
    }
}

// ---------------------------------------------------------------------------
// Grouped second-stage NN kernel (unchanged)
// ---------------------------------------------------------------------------
struct NNGroup { const float* A; const float* B; float* C; int K; int epi;
                 const float* e0; const float* e2; };
struct NNArgs { NNGroup g[6]; };

__global__ __launch_bounds__(256)
void lora_nn_kernel(NNArgs args)
{
    constexpr int BM=128, BN=128, BK=16;
    __shared__ float As[BK][BM+1];
    __shared__ float Bs[BK][BN];
    NNGroup grp = args.g[blockIdx.z];
    const int K = grp.K;
    const int bm0 = blockIdx.y*BM, bn0 = blockIdx.x*BN;
    const int tid = threadIdx.x;
    const int tx = tid & 15, ty = tid >> 4;

    float acc[8][8];
    #pragma unroll
    for (int i=0;i<8;i++)
        #pragma unroll
        for (int j=0;j<8;j++) acc[i][j]=0.f;

    for (int kb = 0; kb < K; kb += BK) {
        #pragma unroll
        for (int l = 0; l < 2; l++) {
            int idx = tid + l*256;
            int r = idx >> 2, c = (idx & 3)*4;
            float4 val = *(const float4*)(grp.A + (size_t)(bm0+r)*K + kb + c);
            As[c+0][r]=val.x; As[c+1][r]=val.y; As[c+2][r]=val.z; As[c+3][r]=val.w;
        }
        #pragma unroll
        for (int l = 0; l < 2; l++) {
            int idx = tid + l*256;
            int r = idx >> 5, c = (idx & 31)*4;
            *(float4*)&Bs[r][c] = *(const float4*)(grp.B + (size_t)(kb+r)*NEC + bn0 + c);
        }
        __syncthreads();
        #pragma unroll
        for (int kk = 0; kk < BK; kk++) {
            float rm[8], rn[8];
            #pragma unroll
            for (int i=0;i<8;i++) rm[i] = As[kk][ty*8+i];
            #pragma unroll
            for (int j=0;j<8;j++) rn[j] = Bs[kk][tx*8+j];
            #pragma unroll
            for (int i=0;i<8;i++)
                #pragma unroll
                for (int j=0;j<8;j++) acc[i][j] = fmaf(rm[i], rn[j], acc[i][j]);
        }
        __syncthreads();
    }
    #pragma unroll
    for (int i=0;i<8;i++) {
        int row = bm0 + ty*8 + i;
        #pragma unroll
        for (int j=0;j<8;j++) {
            int col = bn0 + tx*8 + j;
            size_t idx = (size_t)row*NEC + col;
            float vv = acc[i][j], outv;
            switch (grp.epi) {
                case EPI_W: {
                    float tt = -(grp.e2[col] + vv);
                    float sp = (tt > 15.f) ? tt : log1pf(expf(tt));
                    outv = -sp - 0.5f;
                } break;
                case EPI_ADD: outv = grp.e0[idx] + vv; break;
                case EPI_SIG: {
                    float u = grp.e2[col] + vv;
                    outv = 1.f / (1.f + expf(-u));
                } break;
                default: outv = vv;
            }
            grp.C[idx] = outv;
        }
    }
}

// ---------------------------------------------------------------------------
// warp sum
// ---------------------------------------------------------------------------
__device__ __forceinline__ float warp_sum(float v)
{
    #pragma unroll
    for (int o = 16; o > 0; o >>= 1) v += __shfl_xor_sync(0xffffffffu, v, o);
    return v;
}

// ---------------------------------------------------------------------------
// prep
// ---------------------------------------------------------------------------
__global__ void prep_kernel(float* kptr, float* kkptr,
                            const float* __restrict__ a,
                            const float* __restrict__ ma,
                            const float* __restrict__ mk,
                            float* wptr,
                            float* __restrict__ b)
{
    int m = blockIdx.x;
    int h = threadIdx.x >> 5;
    int lane = threadIdx.x & 31;
    size_t base = (size_t)m*NEC + h*HSZ;
    size_t i0 = base + lane, i1 = i0 + 32;

    float kk0 = kkptr[i0], kk1 = kkptr[i1];
    float ss = warp_sum(kk0*kk0 + kk1*kk1);
    float inv = 1.f / fmaxf(sqrtf(ss), 1e-12f);
    float n0 = kk0*inv, n1 = kk1*inv;
    kkptr[i0] = n0; kkptr[i1] = n1;

    float a0 = a[i0], a1 = a[i1];
    b[i0] = -n0*a0; b[i1] = -n1*a1;

    float ma0 = ma[i0], ma1 = ma[i1];
    float k0v = kptr[i0], k1v = kptr[i1];
    float w0 = wptr[i0], w1 = wptr[i1];
    float mk0 = mk[i0], mk1 = mk[i1];
    kptr[i0] = k0v * (ma0 + a0*(1.f - ma0)) * expf(w0*mk0);
    kptr[i1] = k1v * (ma1 + a1*(1.f - ma1)) * expf(w1*mk1);
    wptr[i0] = expf(-expf(w0));
    wptr[i1] = expf(-expf(w1));
}

// ---------------------------------------------------------------------------
// RWKV7 recurrence v2: 2 heads per 256-thr block, 2-way column split,
// ILP-4 accumulators. grid = 32 blocks.
// ---------------------------------------------------------------------------
__global__ __launch_bounds__(256)
void wkv7_kernel(const float* __restrict__ q, const float* __restrict__ w,
                 const float* __restrict__ k, const float* __restrict__ v,
                 const float* __restrict__ a, const float* __restrict__ b,
                 float* __restrict__ y)
{
    const int blk = blockIdx.x;           // 0..31
    const int batch = blk >> 3, hp = blk & 7;
    const int tid = threadIdx.x;
    const int hl = tid >> 7;               // head in pair (compute role)
    const int r2 = tid & 127;
    const int i = r2 >> 1, half = r2 & 1;

    __shared__ __align__(16) float buf[2][768];   // [pp][head*384 + vec*64 + j]

    float s[32];
    #pragma unroll
    for (int j = 0; j < 32; j++) s[j] = 0.f;

    const size_t bbase = (size_t)batch * TSEQ * NEC;

    // loader triples: 768 floats/step over 256 threads = 3 each
    const float* table[6] = {q, w, k, a, b, v};
    const float* src[3]; int off[3];
    #pragma unroll
    for (int sl = 0; sl < 3; sl++) {
        int fid = sl*256 + tid;
        int lh  = (fid >= 384) ? 1 : 0;
        int rem = fid - lh*384;
        int vec = rem >> 6, j = rem & 63;
        src[sl] = table[vec] + bbase + (size_t)(hp*2 + lh)*HSZ + j;
        off[sl] = lh*384 + vec*64 + j;
    }
    #pragma unroll
    for (int sl = 0; sl < 3; sl++) buf[0][off[sl]] = src[sl][0];
    __syncthreads();

    const size_t ybase = bbase + (size_t)(hp*2 + hl)*HSZ;

    int p = 0;
    for (int t = 0; t < TSEQ; t++) {
        float pre0, pre1, pre2;
        if (t + 1 < TSEQ) {
            size_t o = (size_t)(t+1)*NEC;
            pre0 = src[0][o]; pre1 = src[1][o]; pre2 = src[2][o];
        }

        const float* base = &buf[p][hl*384];
        const float4* q4 = (const float4*)(base +   0 + half*32);
        const float4* w4 = (const float4*)(base +  64 + half*32);
        const float4* k4 = (const float4*)(base + 128 + half*32);
        const float4* a4 = (const float4*)(base + 192 + half*32);
        const float4* b4 = (const float4*)(base + 256 + half*32);
        float vi = base[320 + i];

        float sa0=0.f, sa1=0.f, sa2=0.f, sa3=0.f;
        #pragma unroll
        for (int j4 = 0; j4 < 8; j4++) {
            float4 av = a4[j4];
            sa0 = fmaf(s[j4*4+0], av.x, sa0);
            sa1 = fmaf(s[j4*4+1], av.y, sa1);
            sa2 = fmaf(s[j4*4+2], av.z, sa2);
            sa3 = fmaf(s[j4*4+3], av.w, sa3);
        }
        float sa = (sa0+sa1) + (sa2+sa3);
        sa += __shfl_xor_sync(0xffffffffu, sa, 1);

        float y0=0.f, y1=0.f, y2=0.f, y3=0.f;
        #pragma unroll
        for (int j4 = 0; j4 < 8; j4++) {
            float4 wv = w4[j4], kv = k4[j4], bv = b4[j4], qv = q4[j4];
            float s0 = fmaf(s[j4*4+0], wv.x, fmaf(sa, bv.x, vi*kv.x));
            float s1 = fmaf(s[j4*4+1], wv.y, fmaf(sa, bv.y, vi*kv.y));
            float s2 = fmaf(s[j4*4+2], wv.z, fmaf(sa, bv.z, vi*kv.z));
            float s3 = fmaf(s[j4*4+3], wv.w, fmaf(sa, bv.w, vi*kv.w));
            y0 = fmaf(s0, qv.x, y0);
            y1 = fmaf(s1, qv.y, y1);
            y2 = fmaf(s2, qv.z, y2);
            y3 = fmaf(s3, qv.w, y3);
            s[j4*4+0]=s0; s[j4*4+1]=s1; s[j4*4+2]=s2; s[j4*4+3]=s3;
        }
        float yi = (y0+y1) + (y2+y3);
        yi += __shfl_xor_sync(0xffffffffu, yi, 1);
        if (half == 0) y[ybase + (size_t)t*NEC + i] = yi;

        if (t + 1 < TSEQ) {
            buf[p^1][off[0]] = pre0;
            buf[p^1][off[1]] = pre1;
            buf[p^1][off[2]] = pre2;
        }
        __syncthreads();
        p ^= 1;
    }
}

// ---------------------------------------------------------------------------
// GroupNorm + bonus + gate -> tf32 hi/lo of z (consumed by Wo GEMM)
// ---------------------------------------------------------------------------
__global__ void gn_kernel(const float* __restrict__ y,
                          const float* __restrict__ r,
                          const float* __restrict__ k,
                          const float* __restrict__ v,
                          const float* __restrict__ gg,
                          const float* __restrict__ ln_w,
                          const float* __restrict__ ln_b,
                          const float* __restrict__ faaaa,
                          float* __restrict__ zhi,
                          float* __restrict__ zlo)
{
    int m = blockIdx.x;
    int h = threadIdx.x >> 5;
    int lane = threadIdx.x & 31;
    size_t base = (size_t)m*NEC + h*HSZ;
    int c0 = h*HSZ + lane, c1 = c0 + 32;
    size_t i0 = base + lane, i1 = i0 + 32;

    float y0 = y[i0], y1 = y[i1];
    float mu = warp_sum(y0 + y1) * (1.f/64.f);
    float d0 = y0 - mu, d1 = y1 - mu;
    float var = warp_sum(d0*d0 + d1*d1) * (1.f/64.f);
    float rstd = rsqrtf(var + EPSGN);
    float yn0 = d0*rstd*ln_w[c0] + ln_b[c0];
    float yn1 = d1*rstd*ln_w[c1] + ln_b[c1];

    float r0 = r[i0], r1 = r[i1];
    float k0v = k[i0], k1v = k[i1];
    float rk = warp_sum(r0*k0v*faaaa[c0] + r1*k1v*faaaa[c1]);

    float v0 = v[i0], v1 = v[i1];
    float z0 = (yn0 + rk*v0) * gg[i0];
    float z1 = (yn1 + rk*v1) * gg[i1];

    uint32_t h0,l0,h1,l1;
    split_tf32(z0,h0,l0); split_tf32(z1,h1,l1);
    zhi[i0]=__uint_as_float(h0); zlo[i0]=__uint_as_float(l0);
    zhi[i1]=__uint_as_float(h1); zlo[i1]=__uint_as_float(l1);
}

// ---------------------------------------------------------------------------
// Host side
// ---------------------------------------------------------------------------
extern "C" void kernel_launch(void* const* d_in, const int* in_sizes, int n_in,
                              void* d_out, int out_size)
{
    const float* x          = (const float*)d_in[0];
    const float* time_maa_x = (const float*)d_in[1];
    const float* time_maa   = (const float*)d_in[2];
    const float* maa_w1     = (const float*)d_in[3];
    const float* maa_w2     = (const float*)d_in[4];
    const float* decay_w1   = (const float*)d_in[5];
    const float* decay_w2   = (const float*)d_in[6];
    const float* aaa_w1     = (const float*)d_in[7];
    const float* aaa_w2     = (const float*)d_in[8];
    const float* kkk_w1     = (const float*)d_in[9];
    const float* kkk_w2     = (const float*)d_in[10];
    const float* gate_w1    = (const float*)d_in[11];
    const float* gate_w2    = (const float*)d_in[12];
    const float* ma_w1      = (const float*)d_in[13];
    const float* ma_w2      = (const float*)d_in[14];
    const float* mk_w1      = (const float*)d_in[15];
    const float* mk_w2      = (const float*)d_in[16];
    const float* time_decay = (const float*)d_in[17];
    const float* time_faaaa = (const float*)d_in[18];
    const float* time_aaaaa = (const float*)d_in[19];
    const float* time_misc_a= (const float*)d_in[20];
    const float* time_misc_k= (const float*)d_in[21];
    const float* Wr         = (const float*)d_in[22];
    const float* Wk         = (const float*)d_in[23];
    const float* Wv         = (const float*)d_in[24];
    const float* Wo         = (const float*)d_in[25];
    const float* ln_w       = (const float*)d_in[26];
    const float* ln_b       = (const float*)d_in[27];
    float* out = (float*)d_out;

    float *xx,*mix,*hmaa,*hgate,*hdec,*haaa,*hma,*hkkk,*hmk,*xm;
    float *ahi,*alo,*zhi,*zlo,*whi,*wlo;
    float *r,*gg,*k,*v,*w,*kk,*a,*ma,*mk,*b,*y;
    cudaGetSymbolAddress((void**)&xx,   g_xx);
    cudaGetSymbolAddress((void**)&mix,  g_mix);
    cudaGetSymbolAddress((void**)&hmaa, g_hmaa);
    cudaGetSymbolAddress((void**)&hgate,g_hgate);
    cudaGetSymbolAddress((void**)&hdec, g_hdec);
    cudaGetSymbolAddress((void**)&haaa, g_haaa);
    cudaGetSymbolAddress((void**)&hma,  g_hma);
    cudaGetSymbolAddress((void**)&hkkk, g_hkkk);
    cudaGetSymbolAddress((void**)&hmk,  g_hmk);
    cudaGetSymbolAddress((void**)&xm,   g_xm);
    cudaGetSymbolAddress((void**)&ahi,  g_ahi);
    cudaGetSymbolAddress((void**)&alo,  g_alo);
    cudaGetSymbolAddress((void**)&zhi,  g_zhi);
    cudaGetSymbolAddress((void**)&zlo,  g_zlo);
    cudaGetSymbolAddress((void**)&whi,  g_whi);
    cudaGetSymbolAddress((void**)&wlo,  g_wlo);
    cudaGetSymbolAddress((void**)&r,    g_r);
    cudaGetSymbolAddress((void**)&gg,   g_gg);
    cudaGetSymbolAddress((void**)&k,    g_k);
    cudaGetSymbolAddress((void**)&v,    g_v);
    cudaGetSymbolAddress((void**)&w,    g_w);
    cudaGetSymbolAddress((void**)&kk,   g_kk);
    cudaGetSymbolAddress((void**)&a,    g_a);
    cudaGetSymbolAddress((void**)&ma,   g_ma);
    cudaGetSymbolAddress((void**)&mk,   g_mk);
    cudaGetSymbolAddress((void**)&b,    g_b);
    cudaGetSymbolAddress((void**)&y,    g_y);

    const float* xrg = xm + 0*(size_t)MT*NEC;
    const float* xwa = xm + 1*(size_t)MT*NEC;
    const float* xk  = xm + 2*(size_t)MT*NEC;

    static bool attr_done = false;
    if (!attr_done) {
        cudaFuncSetAttribute(gemm_tc2, cudaFuncAttributeMaxDynamicSharedMemorySize,
                             2*G2_STG*4);
        attr_done = true;
    }
    const int g2_smem = 2*G2_STG*4;
    const size_t S = (size_t)MT*NEC;

    // 1) token shift
    shift_kernel<<<(unsigned)((S + 255)/256), 256>>>(x, time_maa_x, xx, mix);

    // 2) weight tf32 split
    wsplit_kernel<<<(unsigned)((4*NM + 255)/256), 256>>>(Wr, Wk, Wv, Wo, whi, wlo);

    // 3) maa hidden (4 tiles)
    {
        NTArgs na = {};
        na.Aptr[0] = mix;
        for (int i = 0; i < 4; i++)
            na.t[i] = { maa_w1 + (size_t)i*32*NEC, hmaa + i*32, 128, 32, 1, 0 };
        lora_nt_kernel<<<dim3(4, MT/128), 128>>>(na);
    }

    // 4) xm fused (4 groups) + activation splits
    xm_kernel<<<dim3(8, MT/128, 4), 256>>>(hmaa, maa_w2, x, xx, time_maa, xm, ahi, alo);

    // 5) hidden group 2 (10 tiles)
    {
        NTArgs na = {};
        na.Aptr[0] = xrg; na.Aptr[1] = xwa; na.Aptr[2] = xk;
        int ti = 0;
        for (int i = 0; i < 4; i++)
            na.t[ti++] = { gate_w1 + (size_t)i*32*NEC, hgate + i*32, 128, 32, 1, 0 };
        for (int i = 0; i < 2; i++)
            na.t[ti++] = { decay_w1 + (size_t)i*32*NEC, hdec + i*32, 64, 32, 1, 1 };
        na.t[ti++] = { aaa_w1, haaa, 16, 16, 0, 1 };
        na.t[ti++] = { ma_w1,  hma,  16, 16, 0, 1 };
        na.t[ti++] = { kkk_w1, hkkk, 16, 16, 1, 2 };
        na.t[ti++] = { mk_w1,  hmk,  16, 16, 0, 2 };
        lora_nt_kernel<<<dim3(10, MT/128), 128>>>(na);
    }

    // 6) big GEMMs: r, k, v (pre-split tf32)
    gemm_tc2<<<dim3(8,32), 256, g2_smem>>>(ahi+0*S, alo+0*S, whi+0*NM, wlo+0*NM, r, MT, NEC, NEC);
    gemm_tc2<<<dim3(8,32), 256, g2_smem>>>(ahi+1*S, alo+1*S, whi+1*NM, wlo+1*NM, k, MT, NEC, NEC);
    gemm_tc2<<<dim3(8,32), 256, g2_smem>>>(ahi+2*S, alo+2*S, whi+2*NM, wlo+2*NM, v, MT, NEC, NEC);

    // 7) second stage (6 groups)
    {
        NNArgs nn = {};
        nn.g[0] = { hgate, gate_w2,  gg, 128, EPI_NONE, nullptr, nullptr };
        nn.g[1] = { hdec,  decay_w2, w,   64, EPI_W,    nullptr, time_decay };
        nn.g[2] = { hkkk,  kkk_w2,   kk,  16, EPI_ADD,  k,       nullptr };
        nn.g[3] = { haaa,  aaa_w2,   a,   16, EPI_SIG,  nullptr, time_aaaaa };
        nn.g[4] = { hma,   ma_w2,    ma,  16, EPI_SIG,  nullptr, time_misc_a };
        nn.g[5] = { hmk,   mk_w2,    mk,  16, EPI_SIG,  nullptr, time_misc_k };
        lora_nn_kernel<<<dim3(8, MT/128, 6), 256>>>(nn);
    }

    // 8) prep
    prep_kernel<<<MT, 512>>>(k, kk, a, ma, mk, w, b);

    // 9) recurrence
    wkv7_kernel<<<BATCH*NH/2, 256>>>(r, w, k, v, kk, b, y);

    // 10) groupnorm + bonus + gate -> z hi/lo
    gn_kernel<<<MT, 512>>>(y, r, k, v, gg, ln_w, ln_b, time_faaaa, zhi, zlo);

    // 11) out = z @ Wo.T
    gemm_tc2<<<dim3(8,32), 256, g2_smem>>>(zhi, zlo, whi+3*NM, wlo+3*NM, out, MT, NEC, NEC);
}

// round 5
// speedup vs baseline: 1.7588x; 1.0026x over previous
#include <cuda_runtime.h>
#include <math.h>
#include <stdint.h>

// Problem constants
#define BATCH 4
#define TSEQ  1024
#define NEC   1024
#define NH    16
#define HSZ   64
#define MT    (BATCH*TSEQ)      // 4096 rows
#define EPSGN 0.00064f
#define NM    ((size_t)NEC*NEC) // 1M

// ---------------------------------------------------------------------------
// Scratch (device globals)
// ---------------------------------------------------------------------------
__device__ float g_xx   [(size_t)MT*NEC];
__device__ float g_mix  [(size_t)MT*NEC];
__device__ float g_hmaa [(size_t)MT*128];
__device__ float g_hgate[(size_t)MT*128];
__device__ float g_hdec [(size_t)MT*64];
__device__ float g_haaa [(size_t)MT*16];
__device__ float g_hma  [(size_t)MT*16];
__device__ float g_hkkk [(size_t)MT*16];
__device__ float g_hmk  [(size_t)MT*16];
__device__ float g_xm   [4][(size_t)MT*NEC];
__device__ float g_whi  [4*NM];                // Wr,Wk,Wv,Wo hi
__device__ float g_wlo  [4*NM];
__device__ float g_r    [(size_t)MT*NEC];
__device__ float g_gg   [(size_t)MT*NEC];
__device__ float g_k    [(size_t)MT*NEC];
__device__ float g_v    [(size_t)MT*NEC];
__device__ float g_w    [(size_t)MT*NEC];
__device__ float g_kk   [(size_t)MT*NEC];
__device__ float g_a    [(size_t)MT*NEC];
__device__ float g_ma   [(size_t)MT*NEC];
__device__ float g_mk   [(size_t)MT*NEC];
__device__ float g_b    [(size_t)MT*NEC];
__device__ float g_y    [(size_t)MT*NEC];
__device__ float g_z    [(size_t)MT*NEC];

enum { EPI_NONE=0, EPI_W=3, EPI_ADD=4, EPI_SIG=5 };

// ---------------------------------------------------------------------------
// tf32 helpers
// ---------------------------------------------------------------------------
__device__ __forceinline__ uint32_t f2tf32(float v){
    uint32_t r; asm("cvt.rna.tf32.f32 %0, %1;" : "=r"(r) : "f"(v)); return r;
}
__device__ __forceinline__ void split_tf32(float v, uint32_t &hi, uint32_t &lo){
    hi = f2tf32(v);
    float rem = v - __uint_as_float(hi);
    lo = f2tf32(rem);
}
__device__ __forceinline__ void mma_tf32(float* c, const uint32_t* a, const uint32_t* b){
    asm volatile("mma.sync.aligned.m16n8k8.row.col.f32.tf32.tf32.f32 "
        "{%0,%1,%2,%3},{%4,%5,%6,%7},{%8,%9},{%0,%1,%2,%3};\n"
        : "+f"(c[0]), "+f"(c[1]), "+f"(c[2]), "+f"(c[3])
        : "r"(a[0]), "r"(a[1]), "r"(a[2]), "r"(a[3]), "r"(b[0]), "r"(b[1]));
}
__device__ __forceinline__ void cpa16(uint32_t dst, const void* src){
    asm volatile("cp.async.cg.shared.global [%0],[%1],16;\n"::"r"(dst),"l"(src));
}
#define CP_COMMIT() asm volatile("cp.async.commit_group;\n")
#define CP_WAIT0()  asm volatile("cp.async.wait_group 0;\n")

// ---------------------------------------------------------------------------
// Token shift
// ---------------------------------------------------------------------------
__global__ void shift_kernel(const float* __restrict__ x,
                             const float* __restrict__ tmaax,
                             float* __restrict__ xx,
                             float* __restrict__ mix)
{
    size_t i = (size_t)blockIdx.x * blockDim.x + threadIdx.x;
    if (i >= (size_t)MT * NEC) return;
    int c = (int)(i % NEC);
    size_t row = i / NEC;
    int t = (int)(row % TSEQ);
    float xv = x[i];
    float xp = (t > 0) ? x[i - NEC] : 0.f;
    float d = xp - xv;
    xx[i]  = d;
    mix[i] = fmaf(d, tmaax[c], xv);
}

// ---------------------------------------------------------------------------
// Weight split (tf32 hi/lo) for Wr,Wk,Wv,Wo
// ---------------------------------------------------------------------------
__global__ void wsplit_kernel(const float* __restrict__ Wr, const float* __restrict__ Wk,
                              const float* __restrict__ Wv, const float* __restrict__ Wo,
                              float* __restrict__ whi, float* __restrict__ wlo)
{
    size_t i = (size_t)blockIdx.x * blockDim.x + threadIdx.x;
    if (i >= 4*NM) return;
    int seg = (int)(i >> 20);       // NM = 2^20
    size_t off = i & (NM - 1);
    const float* src = (seg==0) ? Wr : (seg==1) ? Wk : (seg==2) ? Wv : Wo;
    uint32_t h, l; split_tf32(src[off], h, l);
    whi[i] = __uint_as_float(h);
    wlo[i] = __uint_as_float(l);
}

// ---------------------------------------------------------------------------
// NT GEMM: C[M,N] = A(fp32)[M,K] * (Bh+Bl)[N,K]^T, split A at frag-load time.
// Tile 128x128x16, 256 threads, cp.async double-buffered, 2 CTA/SM.
// ---------------------------------------------------------------------------
#define G3_LDS 20
#define G3_STG 7680   // floats/stage: Af 2560 + Bh 2560 + Bl 2560

__global__ __launch_bounds__(256, 2)
void gemm_tc3(const float* __restrict__ Ag,
              const float* __restrict__ Bhg, const float* __restrict__ Blg,
              float* __restrict__ C, int M, int N, int K)
{
    extern __shared__ float sm3[];
    const int tid = threadIdx.x;
    const int bm0 = blockIdx.y*128, bn0 = blockIdx.x*128;
    const int warp = tid>>5, lane = tid&31, grp = lane>>2, q = lane&3;
    const int wm = (warp&1)*64, wn = (warp>>1)*32;

    const int lr = tid>>2, lc = (tid&3)*4;
    const uint32_t sbase = (uint32_t)__cvta_generic_to_shared(sm3);

    float acc[4][4][4];
    #pragma unroll
    for (int mi=0;mi<4;mi++)
        #pragma unroll
        for (int ni=0;ni<4;ni++)
            #pragma unroll
            for (int e=0;e<4;e++) acc[mi][ni][e]=0.f;

    const float* pA  = Ag  + (size_t)(bm0+lr)*K + lc;
    const float* pBh = Bhg + (size_t)(bn0+lr)*K + lc;
    const float* pBl = Blg + (size_t)(bn0+lr)*K + lc;
    const uint32_t d0 = (lr*G3_LDS + lc)*4;
    const uint32_t d1 = ((lr+64)*G3_LDS + lc)*4;

#define G3_LOAD(st, kb) do {                                             \
        uint32_t _b = sbase + (st)*G3_STG*4;                             \
        cpa16(_b + d0,           pA  + (kb));                            \
        cpa16(_b + d1,           pA  + 64*(size_t)K + (kb));             \
        cpa16(_b + 2560*4 + d0,  pBh + (kb));                            \
        cpa16(_b + 2560*4 + d1,  pBh + 64*(size_t)K + (kb));             \
        cpa16(_b + 5120*4 + d0,  pBl + (kb));                            \
        cpa16(_b + 5120*4 + d1,  pBl + 64*(size_t)K + (kb));             \
    } while(0)

    G3_LOAD(0, 0); CP_COMMIT();

    int p = 0;
    for (int kb = 0; kb < K; kb += 16) {
        CP_WAIT0();
        __syncthreads();
        if (kb + 16 < K) { G3_LOAD(p^1, kb+16); CP_COMMIT(); }

        const float* Af = sm3 + p*G3_STG;
        const float* Bh = Af + 2560;
        const float* Bl = Af + 5120;

        #pragma unroll
        for (int kc = 0; kc < 16; kc += 8) {
            uint32_t ah[4][4], al[4][4], bh[4][2], bl[4][2];
            #pragma unroll
            for (int mi = 0; mi < 4; mi++) {
                int r0 = (wm + mi*16 + grp)*G3_LDS;
                float v0 = Af[r0          +kc+q  ];
                float v1 = Af[r0+8*G3_LDS +kc+q  ];
                float v2 = Af[r0          +kc+q+4];
                float v3 = Af[r0+8*G3_LDS +kc+q+4];
                split_tf32(v0, ah[mi][0], al[mi][0]);
                split_tf32(v1, ah[mi][1], al[mi][1]);
                split_tf32(v2, ah[mi][2], al[mi][2]);
                split_tf32(v3, ah[mi][3], al[mi][3]);
            }
            #pragma unroll
            for (int ni = 0; ni < 4; ni++) {
                int c0 = (wn + ni*8 + grp)*G3_LDS;
                bh[ni][0]=__float_as_uint(Bh[c0+kc+q]);
                bh[ni][1]=__float_as_uint(Bh[c0+kc+q+4]);
                bl[ni][0]=__float_as_uint(Bl[c0+kc+q]);
                bl[ni][1]=__float_as_uint(Bl[c0+kc+q+4]);
            }
            #pragma unroll
            for (int mi = 0; mi < 4; mi++)
                #pragma unroll
                for (int ni = 0; ni < 4; ni++) {
                    mma_tf32(acc[mi][ni], ah[mi], bh[ni]);
                    mma_tf32(acc[mi][ni], ah[mi], bl[ni]);
                    mma_tf32(acc[mi][ni], al[mi], bh[ni]);
                }
        }
        __syncthreads();
        p ^= 1;
    }

    #pragma unroll
    for (int mi = 0; mi < 4; mi++) {
        int row0 = bm0 + wm + mi*16 + grp;
        #pragma unroll
        for (int ni = 0; ni < 4; ni++) {
            int col = bn0 + wn + ni*8 + 2*q;
            *(float2*)&C[(size_t)row0*N + col]     = make_float2(acc[mi][ni][0], acc[mi][ni][1]);
            *(float2*)&C[(size_t)(row0+8)*N + col] = make_float2(acc[mi][ni][2], acc[mi][ni][3]);
        }
    }
#undef G3_LOAD
}

// ---------------------------------------------------------------------------
// Grouped NT LoRA-hidden kernel: C = act(A @ B_tile^T), K=1024.
// Tile 128x32xBK32, fp32, 128 threads, TM=8 TN=4, float4 smem reads.
// ---------------------------------------------------------------------------
struct NTTile { const float* B; float* C; int ldc; int nvalid; int tanhf; int asel; };
struct NTArgs { const float* Aptr[3]; NTTile t[12]; };

__global__ __launch_bounds__(128)
void lora_nt_kernel(NTArgs args)
{
    constexpr int BK=32, K=NEC;
    __shared__ __align__(16) float As[BK][132];
    __shared__ __align__(16) float Bs[BK][36];
    NTTile tl = args.t[blockIdx.x];
    const float* A = args.Aptr[tl.asel];
    const int bm0 = blockIdx.y*128;
    const int tid = threadIdx.x;
    const int tx = tid & 7;
    const int ty = tid >> 3;

    float acc[8][4];
    #pragma unroll
    for (int i=0;i<8;i++)
        #pragma unroll
        for (int j=0;j<4;j++) acc[i][j]=0.f;

    for (int kb = 0; kb < K; kb += BK) {
        #pragma unroll
        for (int l = 0; l < 8; l++) {
            int idx = tid + l*128;
            int r = idx >> 3, c = (idx & 7)*4;
            float4 val = *(const float4*)(A + (size_t)(bm0+r)*K + kb + c);
            As[c+0][r]=val.x; As[c+1][r]=val.y; As[c+2][r]=val.z; As[c+3][r]=val.w;
        }
        #pragma unroll
        for (int l = 0; l < 2; l++) {
            int idx = tid + l*128;
            int r = idx >> 3, c = (idx & 7)*4;
            float4 val = (r < tl.nvalid) ?
                *(const float4*)(tl.B + (size_t)r*K + kb + c) : make_float4(0,0,0,0);
            Bs[c+0][r]=val.x; Bs[c+1][r]=val.y; Bs[c+2][r]=val.z; Bs[c+3][r]=val.w;
        }
        __syncthreads();
        #pragma unroll
        for (int kk = 0; kk < BK; kk++) {
            float4 m0 = *(const float4*)&As[kk][ty*8];
            float4 m1 = *(const float4*)&As[kk][ty*8+4];
            float4 rn = *(const float4*)&Bs[kk][tx*4];
            float rm[8] = {m0.x,m0.y,m0.z,m0.w,m1.x,m1.y,m1.z,m1.w};
            #pragma unroll
            for (int i=0;i<8;i++) {
                acc[i][0] = fmaf(rm[i], rn.x, acc[i][0]);
                acc[i][1] = fmaf(rm[i], rn.y, acc[i][1]);
                acc[i][2] = fmaf(rm[i], rn.z, acc[i][2]);
                acc[i][3] = fmaf(rm[i], rn.w, acc[i][3]);
            }
        }
        __syncthreads();
    }
    #pragma unroll
    for (int i=0;i<8;i++) {
        int row = bm0 + ty*8 + i;
        #pragma unroll
        for (int j=0;j<4;j++) {
            int col = tx*4 + j;
            if (col < tl.nvalid) {
                float vv = acc[i][j];
                if (tl.tanhf) vv = tanhf(vv);
                tl.C[(size_t)row*tl.ldc + col] = vv;
            }
        }
    }
}

// ---------------------------------------------------------------------------
// Fused xm kernel: grid.z = group g. C = x + xx*(Ag @ Bg + time_maa[g]).
// ---------------------------------------------------------------------------
__global__ __launch_bounds__(256)
void xm_kernel(const float* __restrict__ hmaa,
               const float* __restrict__ maa_w2,
               const float* __restrict__ x,
               const float* __restrict__ xx,
               const float* __restrict__ time_maa,
               float* __restrict__ xmbase)
{
    constexpr int BM=128, BN=128, BK=32;
    __shared__ float As[BK][BM+1];
    __shared__ float Bs[BK][BN];
    const int g = blockIdx.z;
    const float* A = hmaa + g*32;               // lda = 128
    const float* B = maa_w2 + (size_t)g*32*NEC; // ldb = 1024
    float* C = xmbase + (size_t)g*MT*NEC;
    const float* tm = time_maa + g*NEC;
    const int bm0 = blockIdx.y*BM, bn0 = blockIdx.x*BN;
    const int tid = threadIdx.x;
    const int tx = tid & 15, ty = tid >> 4;

    float acc[8][8];
    #pragma unroll
    for (int i=0;i<8;i++)
        #pragma unroll
        for (int j=0;j<8;j++) acc[i][j]=0.f;

    #pragma unroll
    for (int l = 0; l < 4; l++) {
        int idx = tid + l*256;
        int r = idx >> 3, c = (idx & 7)*4;
        float4 val = *(const float4*)(A + (size_t)(bm0+r)*128 + c);
        As[c+0][r]=val.x; As[c+1][r]=val.y; As[c+2][r]=val.z; As[c+3][r]=val.w;
    }
    #pragma unroll
    for (int l = 0; l < 4; l++) {
        int idx = tid + l*256;
        int r = idx >> 5, c = (idx & 31)*4;
        *(float4*)&Bs[r][c] = *(const float4*)(B + (size_t)r*NEC + bn0 + c);
    }
    __syncthreads();
    #pragma unroll
    for (int kk = 0; kk < BK; kk++) {
        float rm[8], rn[8];
        #pragma unroll
        for (int i=0;i<8;i++) rm[i] = As[kk][ty*8+i];
        #pragma unroll
        for (int j=0;j<8;j++) rn[j] = Bs[kk][tx*8+j];
        #pragma unroll
        for (int i=0;i<8;i++)
            #pragma unroll
            for (int j=0;j<8;j++) acc[i][j] = fmaf(rm[i], rn[j], acc[i][j]);
    }
    #pragma unroll
    for (int i=0;i<8;i++) {
        int row = bm0 + ty*8 + i;
        #pragma unroll
        for (int j=0;j<8;j+=2) {
            int col = bn0 + tx*8 + j;
            size_t idx = (size_t)row*NEC + col;
            float2 xv = *(const float2*)&x[idx];
            float2 dv = *(const float2*)&xx[idx];
            float2 o;
            o.x = fmaf(dv.x, acc[i][j]   + tm[col],   xv.x);
            o.y = fmaf(dv.y, acc[i][j+1] + tm[col+1], xv.y);
            *(float2*)&C[idx] = o;
        }
    }
}

// ---------------------------------------------------------------------------
// Grouped second-stage NN kernel
// ---------------------------------------------------------------------------
struct NNGroup { const float* A; const float* B; float* C; int K; int epi;
                 const float* e0; const float* e2; };
struct NNArgs { NNGroup g[6]; };

__global__ __launch_bounds__(256)
void lora_nn_kernel(NNArgs args)
{
    constexpr int BM=128, BN=128, BK=16;
    __shared__ float As[BK][BM+1];
    __shared__ float Bs[BK][BN];
    NNGroup grp = args.g[blockIdx.z];
    const int K = grp.K;
    const int bm0 = blockIdx.y*BM, bn0 = blockIdx.x*BN;
    const int tid = threadIdx.x;
    const int tx = tid & 15, ty = tid >> 4;

    float acc[8][8];
    #pragma unroll
    for (int i=0;i<8;i++)
        #pragma unroll
        for (int j=0;j<8;j++) acc[i][j]=0.f;

    for (int kb = 0; kb < K; kb += BK) {
        #pragma unroll
        for (int l = 0; l < 2; l++) {
            int idx = tid + l*256;
            int r = idx >> 2, c = (idx & 3)*4;
            float4 val = *(const float4*)(grp.A + (size_t)(bm0+r)*K + kb + c);
            As[c+0][r]=val.x; As[c+1][r]=val.y; As[c+2][r]=val.z; As[c+3][r]=val.w;
        }
        #pragma unroll
        for (int l = 0; l < 2; l++) {
            int idx = tid + l*256;
            int r = idx >> 5, c = (idx & 31)*4;
            *(float4*)&Bs[r][c] = *(const float4*)(grp.B + (size_t)(kb+r)*NEC + bn0 + c);
        }
        __syncthreads();
        #pragma unroll
        for (int kk = 0; kk < BK; kk++) {
            float rm[8], rn[8];
            #pragma unroll
            for (int i=0;i<8;i++) rm[i] = As[kk][ty*8+i];
            #pragma unroll
            for (int j=0;j<8;j++) rn[j] = Bs[kk][tx*8+j];
            #pragma unroll
            for (int i=0;i<8;i++)
                #pragma unroll
                for (int j=0;j<8;j++) acc[i][j] = fmaf(rm[i], rn[j], acc[i][j]);
        }
        __syncthreads();
    }
    #pragma unroll
    for (int i=0;i<8;i++) {
        int row = bm0 + ty*8 + i;
        #pragma unroll
        for (int j=0;j<8;j++) {
            int col = bn0 + tx*8 + j;
            size_t idx = (size_t)row*NEC + col;
            float vv = acc[i][j], outv;
            switch (grp.epi) {
                case EPI_W: {
                    float tt = -(grp.e2[col] + vv);
                    float sp = (tt > 15.f) ? tt : log1pf(expf(tt));
                    outv = -sp - 0.5f;
                } break;
                case EPI_ADD: outv = grp.e0[idx] + vv; break;
                case EPI_SIG: {
                    float u = grp.e2[col] + vv;
                    outv = 1.f / (1.f + expf(-u));
                } break;
                default: outv = vv;
            }
            grp.C[idx] = outv;
        }
    }
}

// ---------------------------------------------------------------------------
// warp sum
// ---------------------------------------------------------------------------
__device__ __forceinline__ float warp_sum(float v)
{
    #pragma unroll
    for (int o = 16; o > 0; o >>= 1) v += __shfl_xor_sync(0xffffffffu, v, o);
    return v;
}

// ---------------------------------------------------------------------------
// prep
// ---------------------------------------------------------------------------
__global__ void prep_kernel(float* kptr, float* kkptr,
                            const float* __restrict__ a,
                            const float* __restrict__ ma,
                            const float* __restrict__ mk,
                            float* wptr,
                            float* __restrict__ b)
{
    int m = blockIdx.x;
    int h = threadIdx.x >> 5;
    int lane = threadIdx.x & 31;
    size_t base = (size_t)m*NEC + h*HSZ;
    size_t i0 = base + lane, i1 = i0 + 32;

    float kk0 = kkptr[i0], kk1 = kkptr[i1];
    float ss = warp_sum(kk0*kk0 + kk1*kk1);
    float inv = 1.f / fmaxf(sqrtf(ss), 1e-12f);
    float n0 = kk0*inv, n1 = kk1*inv;
    kkptr[i0] = n0; kkptr[i1] = n1;

    float a0 = a[i0], a1 = a[i1];
    b[i0] = -n0*a0; b[i1] = -n1*a1;

    float ma0 = ma[i0], ma1 = ma[i1];
    float k0v = kptr[i0], k1v = kptr[i1];
    float w0 = wptr[i0], w1 = wptr[i1];
    float mk0 = mk[i0], mk1 = mk[i1];
    kptr[i0] = k0v * (ma0 + a0*(1.f - ma0)) * expf(w0*mk0);
    kptr[i1] = k1v * (ma1 + a1*(1.f - ma1)) * expf(w1*mk1);
    wptr[i0] = expf(-expf(w0));
    wptr[i1] = expf(-expf(w1));
}

// ---------------------------------------------------------------------------
// RWKV7 recurrence v3: 1 head per 256-thr block, 4-way column split.
// thread (i = tid>>2, qd = tid&3) owns s[i][qd*16 .. +16).
// ---------------------------------------------------------------------------
__global__ __launch_bounds__(256)
void wkv7_kernel(const float* __restrict__ q, const float* __restrict__ w,
                 const float* __restrict__ k, const float* __restrict__ v,
                 const float* __restrict__ a, const float* __restrict__ b,
                 float* __restrict__ y)
{
    const int bh = blockIdx.x;            // 0..63
    const int batch = bh >> 4, h = bh & 15;
    const int tid = threadIdx.x;
    const int i = tid >> 2, qd = tid & 3;

    __shared__ __align__(16) float buf[2][384];   // q,w,k,a,b,v x 64

    float s[16];
    #pragma unroll
    for (int j = 0; j < 16; j++) s[j] = 0.f;

    const size_t base = (size_t)batch * TSEQ * NEC + (size_t)h * HSZ;

    // loader: 384 floats/step over 256 threads
    const float* table[6] = {q, w, k, a, b, v};
    const float* s0 = table[tid>>6] + base + (tid & 63);
    const int o0 = tid;
    const float* s1 = (tid < 128) ? (table[4 + (tid>>6)] + base + (tid & 63)) : nullptr;
    const int o1 = 256 + tid;

    buf[0][o0] = s0[0];
    if (tid < 128) buf[0][o1] = s1[0];
    __syncthreads();

    int p = 0;
    for (int t = 0; t < TSEQ; t++) {
        float pre0 = 0.f, pre1 = 0.f;
        if (t + 1 < TSEQ) {
            size_t o = (size_t)(t+1)*NEC;
            pre0 = s0[o];
            if (tid < 128) pre1 = s1[o];
        }

        const float* bb = buf[p];
        const float4* q4 = (const float4*)(bb +   0 + qd*16);
        const float4* w4 = (const float4*)(bb +  64 + qd*16);
        const float4* k4 = (const float4*)(bb + 128 + qd*16);
        const float4* a4 = (const float4*)(bb + 192 + qd*16);
        const float4* b4 = (const float4*)(bb + 256 + qd*16);
        float vi = bb[320 + i];

        float sa0=0.f, sa1=0.f, sa2=0.f, sa3=0.f;
        #pragma unroll
        for (int j4 = 0; j4 < 4; j4++) {
            float4 av = a4[j4];
            sa0 = fmaf(s[j4*4+0], av.x, sa0);
            sa1 = fmaf(s[j4*4+1], av.y, sa1);
            sa2 = fmaf(s[j4*4+2], av.z, sa2);
            sa3 = fmaf(s[j4*4+3], av.w, sa3);
        }
        float sa = (sa0+sa1) + (sa2+sa3);
        sa += __shfl_xor_sync(0xffffffffu, sa, 1);
        sa += __shfl_xor_sync(0xffffffffu, sa, 2);

        float y0=0.f, y1=0.f, y2=0.f, y3=0.f;
        #pragma unroll
        for (int j4 = 0; j4 < 4; j4++) {
            float4 wv = w4[j4], kv = k4[j4], bv = b4[j4], qv = q4[j4];
            float t0 = fmaf(s[j4*4+0], wv.x, fmaf(sa, bv.x, vi*kv.x));
            float t1 = fmaf(s[j4*4+1], wv.y, fmaf(sa, bv.y, vi*kv.y));
            float t2 = fmaf(s[j4*4+2], wv.z, fmaf(sa, bv.z, vi*kv.z));
            float t3 = fmaf(s[j4*4+3], wv.w, fmaf(sa, bv.w, vi*kv.w));
            y0 = fmaf(t0, qv.x, y0);
            y1 = fmaf(t1, qv.y, y1);
            y2 = fmaf(t2, qv.z, y2);
            y3 = fmaf(t3, qv.w, y3);
            s[j4*4+0]=t0; s[j4*4+1]=t1; s[j4*4+2]=t2; s[j4*4+3]=t3;
        }
        float yi = (y0+y1) + (y2+y3);
        yi += __shfl_xor_sync(0xffffffffu, yi, 1);
        yi += __shfl_xor_sync(0xffffffffu, yi, 2);
        if (qd == 0) y[base + (size_t)t*NEC + i] = yi;

        if (t + 1 < TSEQ) {
            buf[p^1][o0] = pre0;
            if (tid < 128) buf[p^1][o1] = pre1;
        }
        __syncthreads();
        p ^= 1;
    }
}

// ---------------------------------------------------------------------------
// GroupNorm + bonus + gate -> z
// ---------------------------------------------------------------------------
__global__ void gn_kernel(const float* __restrict__ y,
                          const float* __restrict__ r,
                          const float* __restrict__ k,
                          const float* __restrict__ v,
                          const float* __restrict__ gg,
                          const float* __restrict__ ln_w,
                          const float* __restrict__ ln_b,
                          const float* __restrict__ faaaa,
                          float* __restrict__ z)
{
    int m = blockIdx.x;
    int h = threadIdx.x >> 5;
    int lane = threadIdx.x & 31;
    size_t base = (size_t)m*NEC + h*HSZ;
    int c0 = h*HSZ + lane, c1 = c0 + 32;
    size_t i0 = base + lane, i1 = i0 + 32;

    float y0 = y[i0], y1 = y[i1];
    float mu = warp_sum(y0 + y1) * (1.f/64.f);
    float d0 = y0 - mu, d1 = y1 - mu;
    float var = warp_sum(d0*d0 + d1*d1) * (1.f/64.f);
    float rstd = rsqrtf(var + EPSGN);
    float yn0 = d0*rstd*ln_w[c0] + ln_b[c0];
    float yn1 = d1*rstd*ln_w[c1] + ln_b[c1];

    float r0 = r[i0], r1 = r[i1];
    float k0v = k[i0], k1v = k[i1];
    float rk = warp_sum(r0*k0v*faaaa[c0] + r1*k1v*faaaa[c1]);

    float v0 = v[i0], v1 = v[i1];
    z[i0] = (yn0 + rk*v0) * gg[i0];
    z[i1] = (yn1 + rk*v1) * gg[i1];
}

// ---------------------------------------------------------------------------
// Host side
// ---------------------------------------------------------------------------
extern "C" void kernel_launch(void* const* d_in, const int* in_sizes, int n_in,
                              void* d_out, int out_size)
{
    const float* x          = (const float*)d_in[0];
    const float* time_maa_x = (const float*)d_in[1];
    const float* time_maa   = (const float*)d_in[2];
    const float* maa_w1     = (const float*)d_in[3];
    const float* maa_w2     = (const float*)d_in[4];
    const float* decay_w1   = (const float*)d_in[5];
    const float* decay_w2   = (const float*)d_in[6];
    const float* aaa_w1     = (const float*)d_in[7];
    const float* aaa_w2     = (const float*)d_in[8];
    const float* kkk_w1     = (const float*)d_in[9];
    const float* kkk_w2     = (const float*)d_in[10];
    const float* gate_w1    = (const float*)d_in[11];
    const float* gate_w2    = (const float*)d_in[12];
    const float* ma_w1      = (const float*)d_in[13];
    const float* ma_w2      = (const float*)d_in[14];
    const float* mk_w1      = (const float*)d_in[15];
    const float* mk_w2      = (const float*)d_in[16];
    const float* time_decay = (const float*)d_in[17];
    const float* time_faaaa = (const float*)d_in[18];
    const float* time_aaaaa = (const float*)d_in[19];
    const float* time_misc_a= (const float*)d_in[20];
    const float* time_misc_k= (const float*)d_in[21];
    const float* Wr         = (const float*)d_in[22];
    const float* Wk         = (const float*)d_in[23];
    const float* Wv         = (const float*)d_in[24];
    const float* Wo         = (const float*)d_in[25];
    const float* ln_w       = (const float*)d_in[26];
    const float* ln_b       = (const float*)d_in[27];
    float* out = (float*)d_out;

    float *xx,*mix,*hmaa,*hgate,*hdec,*haaa,*hma,*hkkk,*hmk,*xm;
    float *whi,*wlo;
    float *r,*gg,*k,*v,*w,*kk,*a,*ma,*mk,*b,*y,*z;
    cudaGetSymbolAddress((void**)&xx,   g_xx);
    cudaGetSymbolAddress((void**)&mix,  g_mix);
    cudaGetSymbolAddress((void**)&hmaa, g_hmaa);
    cudaGetSymbolAddress((void**)&hgate,g_hgate);
    cudaGetSymbolAddress((void**)&hdec, g_hdec);
    cudaGetSymbolAddress((void**)&haaa, g_haaa);
    cudaGetSymbolAddress((void**)&hma,  g_hma);
    cudaGetSymbolAddress((void**)&hkkk, g_hkkk);
    cudaGetSymbolAddress((void**)&hmk,  g_hmk);
    cudaGetSymbolAddress((void**)&xm,   g_xm);
    cudaGetSymbolAddress((void**)&whi,  g_whi);
    cudaGetSymbolAddress((void**)&wlo,  g_wlo);
    cudaGetSymbolAddress((void**)&r,    g_r);
    cudaGetSymbolAddress((void**)&gg,   g_gg);
    cudaGetSymbolAddress((void**)&k,    g_k);
    cudaGetSymbolAddress((void**)&v,    g_v);
    cudaGetSymbolAddress((void**)&w,    g_w);
    cudaGetSymbolAddress((void**)&kk,   g_kk);
    cudaGetSymbolAddress((void**)&a,    g_a);
    cudaGetSymbolAddress((void**)&ma,   g_ma);
    cudaGetSymbolAddress((void**)&mk,   g_mk);
    cudaGetSymbolAddress((void**)&b,    g_b);
    cudaGetSymbolAddress((void**)&y,    g_y);
    cudaGetSymbolAddress((void**)&z,    g_z);

    const float* xrg = xm + 0*(size_t)MT*NEC;
    const float* xwa = xm + 1*(size_t)MT*NEC;
    const float* xk  = xm + 2*(size_t)MT*NEC;
    const float* xv  = xm + 3*(size_t)MT*NEC;

    static bool attr_done = false;
    if (!attr_done) {
        cudaFuncSetAttribute(gemm_tc3, cudaFuncAttributeMaxDynamicSharedMemorySize,
                             2*G3_STG*4);
        attr_done = true;
    }
    const int g3_smem = 2*G3_STG*4;
    const size_t S = (size_t)MT*NEC;

    // 1) token shift
    shift_kernel<<<(unsigned)((S + 255)/256), 256>>>(x, time_maa_x, xx, mix);

    // 2) weight tf32 split (weights only)
    wsplit_kernel<<<(unsigned)((4*NM + 255)/256), 256>>>(Wr, Wk, Wv, Wo, whi, wlo);

    // 3) maa hidden (4 tiles)
    {
        NTArgs na = {};
        na.Aptr[0] = mix;
        for (int i = 0; i < 4; i++)
            na.t[i] = { maa_w1 + (size_t)i*32*NEC, hmaa + i*32, 128, 32, 1, 0 };
        lora_nt_kernel<<<dim3(4, MT/128), 128>>>(na);
    }

    // 4) xm fused (4 groups, all fp32)
    xm_kernel<<<dim3(8, MT/128, 4), 256>>>(hmaa, maa_w2, x, xx, time_maa, xm);

    // 5) hidden group 2 (10 tiles)
    {
        NTArgs na = {};
        na.Aptr[0] = xrg; na.Aptr[1] = xwa; na.Aptr[2] = xk;
        int ti = 0;
        for (int i = 0; i < 4; i++)
            na.t[ti++] = { gate_w1 + (size_t)i*32*NEC, hgate + i*32, 128, 32, 1, 0 };
        for (int i = 0; i < 2; i++)
            na.t[ti++] = { decay_w1 + (size_t)i*32*NEC, hdec + i*32, 64, 32, 1, 1 };
        na.t[ti++] = { aaa_w1, haaa, 16, 16, 0, 1 };
        na.t[ti++] = { ma_w1,  hma,  16, 16, 0, 1 };
        na.t[ti++] = { kkk_w1, hkkk, 16, 16, 1, 2 };
        na.t[ti++] = { mk_w1,  hmk,  16, 16, 0, 2 };
        lora_nt_kernel<<<dim3(10, MT/128), 128>>>(na);
    }

    // 6) big GEMMs: r, k, v (fp32 A, split-in-register)
    gemm_tc3<<<dim3(8,32), 256, g3_smem>>>(xrg, whi+0*NM, wlo+0*NM, r, MT, NEC, NEC);
    gemm_tc3<<<dim3(8,32), 256, g3_smem>>>(xk,  whi+1*NM, wlo+1*NM, k, MT, NEC, NEC);
    gemm_tc3<<<dim3(8,32), 256, g3_smem>>>(xv,  whi+2*NM, wlo+2*NM, v, MT, NEC, NEC);

    // 7) second stage (6 groups)
    {
        NNArgs nn = {};
        nn.g[0] = { hgate, gate_w2,  gg, 128, EPI_NONE, nullptr, nullptr };
        nn.g[1] = { hdec,  decay_w2, w,   64, EPI_W,    nullptr, time_decay };
        nn.g[2] = { hkkk,  kkk_w2,   kk,  16, EPI_ADD,  k,       nullptr };
        nn.g[3] = { haaa,  aaa_w2,   a,   16, EPI_SIG,  nullptr, time_aaaaa };
        nn.g[4] = { hma,   ma_w2,    ma,  16, EPI_SIG,  nullptr, time_misc_a };
        nn.g[5] = { hmk,   mk_w2,    mk,  16, EPI_SIG,  nullptr, time_misc_k };
        lora_nn_kernel<<<dim3(8, MT/128, 6), 256>>>(nn);
    }

    // 8) prep
    prep_kernel<<<MT, 512>>>(k, kk, a, ma, mk, w, b);

    // 9) recurrence (4-way split)
    wkv7_kernel<<<BATCH*NH, 256>>>(r, w, k, v, kk, b, y);

    // 10) groupnorm + bonus + gate -> z
    gn_kernel<<<MT, 512>>>(y, r, k, v, gg, ln_w, ln_b, time_faaaa, z);

    // 11) out = z @ Wo.T
    gemm_tc3<<<dim3(8,32), 256, g3_smem>>>(z, whi+3*NM, wlo+3*NM, out, MT, NEC, NEC);
}

// round 6
// speedup vs baseline: 2.1345x; 1.2136x over previous
#include <cuda_runtime.h>
#include <cuda_fp16.h>
#include <math.h>
#include <stdint.h>

// Problem constants
#define BATCH 4
#define TSEQ  1024
#define NEC   1024
#define NH    16
#define HSZ   64
#define MT    (BATCH*TSEQ)      // 4096 rows
#define EPSGN 0.00064f
#define NM    ((size_t)NEC*NEC) // 1M

// ---------------------------------------------------------------------------
// Scratch (device globals)
// ---------------------------------------------------------------------------
__device__ float    g_xx   [(size_t)MT*NEC];
__device__ float    g_mix  [(size_t)MT*NEC];
__device__ float    g_hmaa [(size_t)MT*128];
__device__ float    g_hgate[(size_t)MT*128];
__device__ float    g_hdec [(size_t)MT*64];
__device__ float    g_haaa [(size_t)MT*16];
__device__ float    g_hma  [(size_t)MT*16];
__device__ float    g_hkkk [(size_t)MT*16];
__device__ float    g_hmk  [(size_t)MT*16];
__device__ float    g_xm   [4][(size_t)MT*NEC];  // g1 fp32; g0/2/3 packed half2
__device__ uint32_t g_wpk  [4*NM];               // Wr,Wk,Wv,Wo packed (hi,lo) fp16
__device__ uint32_t g_zpk  [(size_t)MT*NEC];
__device__ float    g_r    [(size_t)MT*NEC];
__device__ float    g_gg   [(size_t)MT*NEC];
__device__ float    g_k    [(size_t)MT*NEC];
__device__ float    g_v    [(size_t)MT*NEC];
__device__ float    g_w    [(size_t)MT*NEC];
__device__ float    g_kk   [(size_t)MT*NEC];
__device__ float    g_a    [(size_t)MT*NEC];
__device__ float    g_ma   [(size_t)MT*NEC];
__device__ float    g_mk   [(size_t)MT*NEC];
__device__ float    g_b    [(size_t)MT*NEC];
__device__ float    g_y    [(size_t)MT*NEC];

enum { EPI_NONE=0, EPI_W=3, EPI_ADD=4, EPI_SIG=5 };

// ---------------------------------------------------------------------------
// fp16 split helpers
// ---------------------------------------------------------------------------
__device__ __forceinline__ uint32_t packf(float v){
    __half hi = __float2half_rn(v);
    __half lo = __float2half_rn(v - __half2float(hi));
    __half2 h2 = __halves2half2(hi, lo);
    return *reinterpret_cast<uint32_t*>(&h2);
}
__device__ __forceinline__ float unpackf(uint32_t u){
    __half2 h = *reinterpret_cast<__half2*>(&u);
    return __low2float(h) + __high2float(h);
}
__device__ __forceinline__ void mma_f16(float* c, const uint32_t* a, const uint32_t* b){
    asm volatile("mma.sync.aligned.m16n8k16.row.col.f32.f16.f16.f32 "
        "{%0,%1,%2,%3},{%4,%5,%6,%7},{%8,%9},{%0,%1,%2,%3};\n"
        : "+f"(c[0]), "+f"(c[1]), "+f"(c[2]), "+f"(c[3])
        : "r"(a[0]), "r"(a[1]), "r"(a[2]), "r"(a[3]), "r"(b[0]), "r"(b[1]));
}
__device__ __forceinline__ void cpa16(uint32_t dst, const void* src){
    asm volatile("cp.async.cg.shared.global [%0],[%1],16;\n"::"r"(dst),"l"(src));
}
__device__ __forceinline__ void cpa4(uint32_t dst, const void* src){
    asm volatile("cp.async.ca.shared.global [%0],[%1],4;\n"::"r"(dst),"l"(src));
}
#define CP_COMMIT() asm volatile("cp.async.commit_group;\n")
#define CP_WAIT0()  asm volatile("cp.async.wait_group 0;\n")
#define CP_WAIT1()  asm volatile("cp.async.wait_group 1;\n")

// ---------------------------------------------------------------------------
// Token shift
// ---------------------------------------------------------------------------
__global__ void shift_kernel(const float* __restrict__ x,
                             const float* __restrict__ tmaax,
                             float* __restrict__ xx,
                             float* __restrict__ mix)
{
    size_t i = (size_t)blockIdx.x * blockDim.x + threadIdx.x;
    if (i >= (size_t)MT * NEC) return;
    int c = (int)(i % NEC);
    size_t row = i / NEC;
    int t = (int)(row % TSEQ);
    float xv = x[i];
    float xp = (t > 0) ? x[i - NEC] : 0.f;
    float d = xp - xv;
    xx[i]  = d;
    mix[i] = fmaf(d, tmaax[c], xv);
}

// ---------------------------------------------------------------------------
// Weight pack (fp16 hi/lo) for Wr,Wk,Wv,Wo
// ---------------------------------------------------------------------------
__global__ void wpack_kernel(const float* __restrict__ Wr, const float* __restrict__ Wk,
                             const float* __restrict__ Wv, const float* __restrict__ Wo,
                             uint32_t* __restrict__ wpk)
{
    size_t i = (size_t)blockIdx.x * blockDim.x + threadIdx.x;
    if (i >= 4*NM) return;
    int seg = (int)(i >> 20);
    size_t off = i & (NM - 1);
    const float* src = (seg==0) ? Wr : (seg==1) ? Wk : (seg==2) ? Wv : Wo;
    wpk[i] = packf(src[off]);
}

// ---------------------------------------------------------------------------
// fp16 split-2 NT GEMM: C[M,N] = A * B^T with A,B packed (hi,lo) half2 words.
// 3 products: AhBh + AhBl + AlBh via mma.m16n8k16.
// Tile 128x128xBK32, 256 threads, cp.async double-buffered, 2 CTA/SM.
// ---------------------------------------------------------------------------
#define G4_LDS 36      // words per row in smem (32 + 4 pad)
#define G4_STG 9216    // words per stage: A 128*36 + B 128*36

__global__ __launch_bounds__(256, 2)
void gemm_tc4(const uint32_t* __restrict__ Apk,
              const uint32_t* __restrict__ Bpk,
              float* __restrict__ C, int M, int N, int K)
{
    extern __shared__ uint32_t sm4[];
    const int tid = threadIdx.x;
    const int bm0 = blockIdx.y*128, bn0 = blockIdx.x*128;
    const int warp = tid>>5, lane = tid&31, grp = lane>>2, q = lane&3;
    const int wm = (warp&1)*64, wn = (warp>>1)*32;
    const uint32_t sbase = (uint32_t)__cvta_generic_to_shared(sm4);

    float acc[4][4][4];
    #pragma unroll
    for (int mi=0;mi<4;mi++)
        #pragma unroll
        for (int ni=0;ni<4;ni++)
            #pragma unroll
            for (int e=0;e<4;e++) acc[mi][ni][e]=0.f;

    // loader: 4 A chunks + 4 B chunks of 16B per thread per stage
    const uint32_t* asrc[4]; const uint32_t* bsrc[4];
    uint32_t adst[4], bdst[4];
    #pragma unroll
    for (int l = 0; l < 4; l++) {
        int idx = tid + l*256;
        int r = idx >> 3, c4 = idx & 7;
        asrc[l] = Apk + (size_t)(bm0+r)*K + c4*4;
        bsrc[l] = Bpk + (size_t)(bn0+r)*K + c4*4;
        adst[l] = sbase + (uint32_t)(r*G4_LDS + c4*4)*4;
        bdst[l] = sbase + (uint32_t)(4608 + r*G4_LDS + c4*4)*4;
    }

#define G4_LOAD(st, kb) do {                                   \
        uint32_t _o = (st)*G4_STG*4;                           \
        _Pragma("unroll")                                      \
        for (int l = 0; l < 4; l++) {                          \
            cpa16(adst[l] + _o, asrc[l] + (kb));               \
            cpa16(bdst[l] + _o, bsrc[l] + (kb));               \
        }                                                      \
    } while(0)

    G4_LOAD(0, 0); CP_COMMIT();

    int p = 0;
    for (int kb = 0; kb < K; kb += 32) {
        CP_WAIT0();
        __syncthreads();
        if (kb + 32 < K) { G4_LOAD(p^1, kb+32); CP_COMMIT(); }

        const uint32_t* S = sm4 + p*G4_STG;

        #pragma unroll
        for (int kc = 0; kc < 32; kc += 16) {
            uint32_t ah[4][4], al[4][4], bh[4][2], bl[4][2];
            #pragma unroll
            for (int mi = 0; mi < 4; mi++) {
                int r0 = (wm + mi*16 + grp)*G4_LDS + kc + 2*q;
                uint2 w0 = *(const uint2*)&S[r0];
                uint2 w1 = *(const uint2*)&S[r0 + 8*G4_LDS];
                uint2 w2 = *(const uint2*)&S[r0 + 8];
                uint2 w3 = *(const uint2*)&S[r0 + 8*G4_LDS + 8];
                ah[mi][0]=__byte_perm(w0.x,w0.y,0x5410); al[mi][0]=__byte_perm(w0.x,w0.y,0x7632);
                ah[mi][1]=__byte_perm(w1.x,w1.y,0x5410); al[mi][1]=__byte_perm(w1.x,w1.y,0x7632);
                ah[mi][2]=__byte_perm(w2.x,w2.y,0x5410); al[mi][2]=__byte_perm(w2.x,w2.y,0x7632);
                ah[mi][3]=__byte_perm(w3.x,w3.y,0x5410); al[mi][3]=__byte_perm(w3.x,w3.y,0x7632);
            }
            #pragma unroll
            for (int ni = 0; ni < 4; ni++) {
                int c0 = 4608 + (wn + ni*8 + grp)*G4_LDS + kc + 2*q;
                uint2 u0 = *(const uint2*)&S[c0];
                uint2 u1 = *(const uint2*)&S[c0 + 8];
                bh[ni][0]=__byte_perm(u0.x,u0.y,0x5410); bl[ni][0]=__byte_perm(u0.x,u0.y,0x7632);
                bh[ni][1]=__byte_perm(u1.x,u1.y,0x5410); bl[ni][1]=__byte_perm(u1.x,u1.y,0x7632);
            }
            #pragma unroll
            for (int mi = 0; mi < 4; mi++)
                #pragma unroll
                for (int ni = 0; ni < 4; ni++) {
                    mma_f16(acc[mi][ni], ah[mi], bh[ni]);
                    mma_f16(acc[mi][ni], ah[mi], bl[ni]);
                    mma_f16(acc[mi][ni], al[mi], bh[ni]);
                }
        }
        __syncthreads();
        p ^= 1;
    }

    #pragma unroll
    for (int mi = 0; mi < 4; mi++) {
        int row0 = bm0 + wm + mi*16 + grp;
        #pragma unroll
        for (int ni = 0; ni < 4; ni++) {
            int col = bn0 + wn + ni*8 + 2*q;
            *(float2*)&C[(size_t)row0*N + col]     = make_float2(acc[mi][ni][0], acc[mi][ni][1]);
            *(float2*)&C[(size_t)(row0+8)*N + col] = make_float2(acc[mi][ni][2], acc[mi][ni][3]);
        }
    }
#undef G4_LOAD
}

// ---------------------------------------------------------------------------
// Grouped NT LoRA-hidden kernel: C = act(A @ B_tile^T), K=1024.
// A may be packed (hi,lo) fp16 words; unpack at smem fill.
// ---------------------------------------------------------------------------
struct NTTile { const float* B; float* C; int ldc; int nvalid; int tanhf; int asel; };
struct NTArgs { const void* Aptr[3]; int apk[3]; NTTile t[12]; };

__global__ __launch_bounds__(128)
void lora_nt_kernel(NTArgs args)
{
    constexpr int BK=32, K=NEC;
    __shared__ __align__(16) float As[BK][132];
    __shared__ __align__(16) float Bs[BK][36];
    NTTile tl = args.t[blockIdx.x];
    const int apk = args.apk[tl.asel];
    const int bm0 = blockIdx.y*128;
    const int tid = threadIdx.x;
    const int tx = tid & 7;
    const int ty = tid >> 3;

    float acc[8][4];
    #pragma unroll
    for (int i=0;i<8;i++)
        #pragma unroll
        for (int j=0;j<4;j++) acc[i][j]=0.f;

    for (int kb = 0; kb < K; kb += BK) {
        if (apk) {
            const uint32_t* A = (const uint32_t*)args.Aptr[tl.asel];
            #pragma unroll
            for (int l = 0; l < 8; l++) {
                int idx = tid + l*128;
                int r = idx >> 3, c = (idx & 7)*4;
                uint4 u = *(const uint4*)(A + (size_t)(bm0+r)*K + kb + c);
                As[c+0][r]=unpackf(u.x); As[c+1][r]=unpackf(u.y);
                As[c+2][r]=unpackf(u.z); As[c+3][r]=unpackf(u.w);
            }
        } else {
            const float* A = (const float*)args.Aptr[tl.asel];
            #pragma unroll
            for (int l = 0; l < 8; l++) {
                int idx = tid + l*128;
                int r = idx >> 3, c = (idx & 7)*4;
                float4 val = *(const float4*)(A + (size_t)(bm0+r)*K + kb + c);
                As[c+0][r]=val.x; As[c+1][r]=val.y; As[c+2][r]=val.z; As[c+3][r]=val.w;
            }
        }
        #pragma unroll
        for (int l = 0; l < 2; l++) {
            int idx = tid + l*128;
            int r = idx >> 3, c = (idx & 7)*4;
            float4 val = (r < tl.nvalid) ?
                *(const float4*)(tl.B + (size_t)r*K + kb + c) : make_float4(0,0,0,0);
            Bs[c+0][r]=val.x; Bs[c+1][r]=val.y; Bs[c+2][r]=val.z; Bs[c+3][r]=val.w;
        }
        __syncthreads();
        #pragma unroll
        for (int kk = 0; kk < BK; kk++) {
            float4 m0 = *(const float4*)&As[kk][ty*8];
            float4 m1 = *(const float4*)&As[kk][ty*8+4];
            float4 rn = *(const float4*)&Bs[kk][tx*4];
            float rm[8] = {m0.x,m0.y,m0.z,m0.w,m1.x,m1.y,m1.z,m1.w};
            #pragma unroll
            for (int i=0;i<8;i++) {
                acc[i][0] = fmaf(rm[i], rn.x, acc[i][0]);
                acc[i][1] = fmaf(rm[i], rn.y, acc[i][1]);
                acc[i][2] = fmaf(rm[i], rn.z, acc[i][2]);
                acc[i][3] = fmaf(rm[i], rn.w, acc[i][3]);
            }
        }
        __syncthreads();
    }
    #pragma unroll
    for (int i=0;i<8;i++) {
        int row = bm0 + ty*8 + i;
        #pragma unroll
        for (int j=0;j<4;j++) {
            int col = tx*4 + j;
            if (col < tl.nvalid) {
                float vv = acc[i][j];
                if (tl.tanhf) vv = tanhf(vv);
                tl.C[(size_t)row*tl.ldc + col] = vv;
            }
        }
    }
}

// ---------------------------------------------------------------------------
// Fused xm kernel: per group g, val = x + xx*(Ag @ Bg + time_maa[g]).
// g==1 -> fp32 out (xwa); else packed (hi,lo) fp16 out.
// ---------------------------------------------------------------------------
__global__ __launch_bounds__(256)
void xm_kernel(const float* __restrict__ hmaa,
               const float* __restrict__ maa_w2,
               const float* __restrict__ x,
               const float* __restrict__ xx,
               const float* __restrict__ time_maa,
               float* __restrict__ xmbase)
{
    constexpr int BM=128, BN=128, BK=32;
    __shared__ float As[BK][BM+1];
    __shared__ float Bs[BK][BN];
    const int g = blockIdx.z;
    const float* A = hmaa + g*32;
    const float* B = maa_w2 + (size_t)g*32*NEC;
    float* C = xmbase + (size_t)g*MT*NEC;
    const float* tm = time_maa + g*NEC;
    const int bm0 = blockIdx.y*BM, bn0 = blockIdx.x*BN;
    const int tid = threadIdx.x;
    const int tx = tid & 15, ty = tid >> 4;

    float acc[8][8];
    #pragma unroll
    for (int i=0;i<8;i++)
        #pragma unroll
        for (int j=0;j<8;j++) acc[i][j]=0.f;

    #pragma unroll
    for (int l = 0; l < 4; l++) {
        int idx = tid + l*256;
        int r = idx >> 3, c = (idx & 7)*4;
        float4 val = *(const float4*)(A + (size_t)(bm0+r)*128 + c);
        As[c+0][r]=val.x; As[c+1][r]=val.y; As[c+2][r]=val.z; As[c+3][r]=val.w;
    }
    #pragma unroll
    for (int l = 0; l < 4; l++) {
        int idx = tid + l*256;
        int r = idx >> 5, c = (idx & 31)*4;
        *(float4*)&Bs[r][c] = *(const float4*)(B + (size_t)r*NEC + bn0 + c);
    }
    __syncthreads();
    #pragma unroll
    for (int kk = 0; kk < BK; kk++) {
        float rm[8], rn[8];
        #pragma unroll
        for (int i=0;i<8;i++) rm[i] = As[kk][ty*8+i];
        #pragma unroll
        for (int j=0;j<8;j++) rn[j] = Bs[kk][tx*8+j];
        #pragma unroll
        for (int i=0;i<8;i++)
            #pragma unroll
            for (int j=0;j<8;j++) acc[i][j] = fmaf(rm[i], rn[j], acc[i][j]);
    }
    #pragma unroll
    for (int i=0;i<8;i++) {
        int row = bm0 + ty*8 + i;
        #pragma unroll
        for (int j=0;j<8;j+=2) {
            int col = bn0 + tx*8 + j;
            size_t idx = (size_t)row*NEC + col;
            float2 xv = *(const float2*)&x[idx];
            float2 dv = *(const float2*)&xx[idx];
            float v0 = fmaf(dv.x, acc[i][j]   + tm[col],   xv.x);
            float v1 = fmaf(dv.y, acc[i][j+1] + tm[col+1], xv.y);
            if (g == 1) {
                *(float2*)&C[idx] = make_float2(v0, v1);
            } else {
                uint2 pk = make_uint2(packf(v0), packf(v1));
                *(uint2*)&((uint32_t*)C)[idx] = pk;
            }
        }
    }
}

// ---------------------------------------------------------------------------
// Grouped second-stage NN kernel
// ---------------------------------------------------------------------------
struct NNGroup { const float* A; const float* B; float* C; int K; int epi;
                 const float* e0; const float* e2; };
struct NNArgs { NNGroup g[6]; };

__global__ __launch_bounds__(256)
void lora_nn_kernel(NNArgs args)
{
    constexpr int BM=128, BN=128, BK=16;
    __shared__ float As[BK][BM+1];
    __shared__ float Bs[BK][BN];
    NNGroup grp = args.g[blockIdx.z];
    const int K = grp.K;
    const int bm0 = blockIdx.y*BM, bn0 = blockIdx.x*BN;
    const int tid = threadIdx.x;
    const int tx = tid & 15, ty = tid >> 4;

    float acc[8][8];
    #pragma unroll
    for (int i=0;i<8;i++)
        #pragma unroll
        for (int j=0;j<8;j++) acc[i][j]=0.f;

    for (int kb = 0; kb < K; kb += BK) {
        #pragma unroll
        for (int l = 0; l < 2; l++) {
            int idx = tid + l*256;
            int r = idx >> 2, c = (idx & 3)*4;
            float4 val = *(const float4*)(grp.A + (size_t)(bm0+r)*K + kb + c);
            As[c+0][r]=val.x; As[c+1][r]=val.y; As[c+2][r]=val.z; As[c+3][r]=val.w;
        }
        #pragma unroll
        for (int l = 0; l < 2; l++) {
            int idx = tid + l*256;
            int r = idx >> 5, c = (idx & 31)*4;
            *(float4*)&Bs[r][c] = *(const float4*)(grp.B + (size_t)(kb+r)*NEC + bn0 + c);
        }
        __syncthreads();
        #pragma unroll
        for (int kk = 0; kk < BK; kk++) {
            float rm[8], rn[8];
            #pragma unroll
            for (int i=0;i<8;i++) rm[i] = As[kk][ty*8+i];
            #pragma unroll
            for (int j=0;j<8;j++) rn[j] = Bs[kk][tx*8+j];
            #pragma unroll
            for (int i=0;i<8;i++)
                #pragma unroll
                for (int j=0;j<8;j++) acc[i][j] = fmaf(rm[i], rn[j], acc[i][j]);
        }
        __syncthreads();
    }
    #pragma unroll
    for (int i=0;i<8;i++) {
        int row = bm0 + ty*8 + i;
        #pragma unroll
        for (int j=0;j<8;j++) {
            int col = bn0 + tx*8 + j;
            size_t idx = (size_t)row*NEC + col;
            float vv = acc[i][j], outv;
            switch (grp.epi) {
                case EPI_W: {
                    float tt = -(grp.e2[col] + vv);
                    float sp = (tt > 15.f) ? tt : log1pf(expf(tt));
                    outv = -sp - 0.5f;
                } break;
                case EPI_ADD: outv = grp.e0[idx] + vv; break;
                case EPI_SIG: {
                    float u = grp.e2[col] + vv;
                    outv = 1.f / (1.f + expf(-u));
                } break;
                default: outv = vv;
            }
            grp.C[idx] = outv;
        }
    }
}

// ---------------------------------------------------------------------------
// warp sum
// ---------------------------------------------------------------------------
__device__ __forceinline__ float warp_sum(float v)
{
    #pragma unroll
    for (int o = 16; o > 0; o >>= 1) v += __shfl_xor_sync(0xffffffffu, v, o);
    return v;
}

// ---------------------------------------------------------------------------
// prep
// ---------------------------------------------------------------------------
__global__ void prep_kernel(float* kptr, float* kkptr,
                            const float* __restrict__ a,
                            const float* __restrict__ ma,
                            const float* __restrict__ mk,
                            float* wptr,
                            float* __restrict__ b)
{
    int m = blockIdx.x;
    int h = threadIdx.x >> 5;
    int lane = threadIdx.x & 31;
    size_t base = (size_t)m*NEC + h*HSZ;
    size_t i0 = base + lane, i1 = i0 + 32;

    float kk0 = kkptr[i0], kk1 = kkptr[i1];
    float ss = warp_sum(kk0*kk0 + kk1*kk1);
    float inv = 1.f / fmaxf(sqrtf(ss), 1e-12f);
    float n0 = kk0*inv, n1 = kk1*inv;
    kkptr[i0] = n0; kkptr[i1] = n1;

    float a0 = a[i0], a1 = a[i1];
    b[i0] = -n0*a0; b[i1] = -n1*a1;

    float ma0 = ma[i0], ma1 = ma[i1];
    float k0v = kptr[i0], k1v = kptr[i1];
    float w0 = wptr[i0], w1 = wptr[i1];
    float mk0 = mk[i0], mk1 = mk[i1];
    kptr[i0] = k0v * (ma0 + a0*(1.f - ma0)) * expf(w0*mk0);
    kptr[i1] = k1v * (ma1 + a1*(1.f - ma1)) * expf(w1*mk1);
    wptr[i0] = expf(-expf(w0));
    wptr[i1] = expf(-expf(w1));
}

// ---------------------------------------------------------------------------
// RWKV7 recurrence: 1 head / 256-thr block, 4-way column split,
// 3-stage cp.async ring (2 steps of prefetch depth).
// ---------------------------------------------------------------------------
__global__ __launch_bounds__(256)
void wkv7_kernel(const float* __restrict__ q, const float* __restrict__ w,
                 const float* __restrict__ k, const float* __restrict__ v,
                 const float* __restrict__ a, const float* __restrict__ b,
                 float* __restrict__ y)
{
    const int bh = blockIdx.x;            // 0..63
    const int batch = bh >> 4, h = bh & 15;
    const int tid = threadIdx.x;
    const int i = tid >> 2, qd = tid & 3;

    __shared__ __align__(16) float buf[3][384];   // q,w,k,a,b,v x 64

    float s[16];
    #pragma unroll
    for (int j = 0; j < 16; j++) s[j] = 0.f;

    const size_t base = (size_t)batch * TSEQ * NEC + (size_t)h * HSZ;

    // loader: 384 floats/step over 256 threads (thread covers 1-2 slots)
    const float* table[6] = {q, w, k, a, b, v};
    const float* s0 = table[tid>>6] + base + (tid & 63);
    const float* s1 = (tid < 128) ? (table[4 + (tid>>6)] + base + (tid & 63)) : nullptr;
    const uint32_t sb = (uint32_t)__cvta_generic_to_shared(buf);
    const uint32_t d0 = sb + (uint32_t)tid*4;
    const uint32_t d1 = sb + (uint32_t)(256 + tid)*4;

    // prologue: stage 0 (t=0), stage 1 (t=1)
    cpa4(d0, s0);
    if (tid < 128) cpa4(d1, s1);
    CP_COMMIT();
    cpa4(d0 + 384*4, s0 + NEC);
    if (tid < 128) cpa4(d1 + 384*4, s1 + NEC);
    CP_COMMIT();

    int p = 0;
    for (int t = 0; t < TSEQ; t++) {
        CP_WAIT1();
        __syncthreads();

        // issue prefetch for t+2 into the buffer freed by step t-1
        {
            int st = p + 2; if (st >= 3) st -= 3;
            if (t + 2 < TSEQ) {
                size_t o = (size_t)(t+2)*NEC;
                cpa4(d0 + (uint32_t)st*384*4, s0 + o);
                if (tid < 128) cpa4(d1 + (uint32_t)st*384*4, s1 + o);
            }
            CP_COMMIT();
        }

        const float* bb = buf[p];
        const float4* q4 = (const float4*)(bb +   0 + qd*16);
        const float4* w4 = (const float4*)(bb +  64 + qd*16);
        const float4* k4 = (const float4*)(bb + 128 + qd*16);
        const float4* a4 = (const float4*)(bb + 192 + qd*16);
        const float4* b4 = (const float4*)(bb + 256 + qd*16);
        float vi = bb[320 + i];

        float sa0=0.f, sa1=0.f, sa2=0.f, sa3=0.f;
        #pragma unroll
        for (int j4 = 0; j4 < 4; j4++) {
            float4 av = a4[j4];
            sa0 = fmaf(s[j4*4+0], av.x, sa0);
            sa1 = fmaf(s[j4*4+1], av.y, sa1);
            sa2 = fmaf(s[j4*4+2], av.z, sa2);
            sa3 = fmaf(s[j4*4+3], av.w, sa3);
        }
        float sa = (sa0+sa1) + (sa2+sa3);
        sa += __shfl_xor_sync(0xffffffffu, sa, 1);
        sa += __shfl_xor_sync(0xffffffffu, sa, 2);

        float y0=0.f, y1=0.f, y2=0.f, y3=0.f;
        #pragma unroll
        for (int j4 = 0; j4 < 4; j4++) {
            float4 wv = w4[j4], kv = k4[j4], bv = b4[j4], qv = q4[j4];
            float t0 = fmaf(s[j4*4+0], wv.x, fmaf(sa, bv.x, vi*kv.x));
            float t1 = fmaf(s[j4*4+1], wv.y, fmaf(sa, bv.y, vi*kv.y));
            float t2 = fmaf(s[j4*4+2], wv.z, fmaf(sa, bv.z, vi*kv.z));
            float t3 = fmaf(s[j4*4+3], wv.w, fmaf(sa, bv.w, vi*kv.w));
            y0 = fmaf(t0, qv.x, y0);
            y1 = fmaf(t1, qv.y, y1);
            y2 = fmaf(t2, qv.z, y2);
            y3 = fmaf(t3, qv.w, y3);
            s[j4*4+0]=t0; s[j4*4+1]=t1; s[j4*4+2]=t2; s[j4*4+3]=t3;
        }
        float yi = (y0+y1) + (y2+y3);
        yi += __shfl_xor_sync(0xffffffffu, yi, 1);
        yi += __shfl_xor_sync(0xffffffffu, yi, 2);
        if (qd == 0) y[base + (size_t)t*NEC + i] = yi;

        if (++p == 3) p = 0;
    }
}

// ---------------------------------------------------------------------------
// GroupNorm + bonus + gate -> packed z
// ---------------------------------------------------------------------------
__global__ void gn_kernel(const float* __restrict__ y,
                          const float* __restrict__ r,
                          const float* __restrict__ k,
                          const float* __restrict__ v,
                          const float* __restrict__ gg,
                          const float* __restrict__ ln_w,
                          const float* __restrict__ ln_b,
                          const float* __restrict__ faaaa,
                          uint32_t* __restrict__ zpk)
{
    int m = blockIdx.x;
    int h = threadIdx.x >> 5;
    int lane = threadIdx.x & 31;
    size_t base = (size_t)m*NEC + h*HSZ;
    int c0 = h*HSZ + lane, c1 = c0 + 32;
    size_t i0 = base + lane, i1 = i0 + 32;

    float y0 = y[i0], y1 = y[i1];
    float mu = warp_sum(y0 + y1) * (1.f/64.f);
    float d0 = y0 - mu, d1 = y1 - mu;
    float var = warp_sum(d0*d0 + d1*d1) * (1.f/64.f);
    float rstd = rsqrtf(var + EPSGN);
    float yn0 = d0*rstd*ln_w[c0] + ln_b[c0];
    float yn1 = d1*rstd*ln_w[c1] + ln_b[c1];

    float r0 = r[i0], r1 = r[i1];
    float k0v = k[i0], k1v = k[i1];
    float rk = warp_sum(r0*k0v*faaaa[c0] + r1*k1v*faaaa[c1]);

    float v0 = v[i0], v1 = v[i1];
    zpk[i0] = packf((yn0 + rk*v0) * gg[i0]);
    zpk[i1] = packf((yn1 + rk*v1) * gg[i1]);
}

// ---------------------------------------------------------------------------
// Host side
// ---------------------------------------------------------------------------
extern "C" void kernel_launch(void* const* d_in, const int* in_sizes, int n_in,
                              void* d_out, int out_size)
{
    const float* x          = (const float*)d_in[0];
    const float* time_maa_x = (const float*)d_in[1];
    const float* time_maa   = (const float*)d_in[2];
    const float* maa_w1     = (const float*)d_in[3];
    const float* maa_w2     = (const float*)d_in[4];
    const float* decay_w1   = (const float*)d_in[5];
    const float* decay_w2   = (const float*)d_in[6];
    const float* aaa_w1     = (const float*)d_in[7];
    const float* aaa_w2     = (const float*)d_in[8];
    const float* kkk_w1     = (const float*)d_in[9];
    const float* kkk_w2     = (const float*)d_in[10];
    const float* gate_w1    = (const float*)d_in[11];
    const float* gate_w2    = (const float*)d_in[12];
    const float* ma_w1      = (const float*)d_in[13];
    const float* ma_w2      = (const float*)d_in[14];
    const float* mk_w1      = (const float*)d_in[15];
    const float* mk_w2      = (const float*)d_in[16];
    const float* time_decay = (const float*)d_in[17];
    const float* time_faaaa = (const float*)d_in[18];
    const float* time_aaaaa = (const float*)d_in[19];
    const float* time_misc_a= (const float*)d_in[20];
    const float* time_misc_k= (const float*)d_in[21];
    const float* Wr         = (const float*)d_in[22];
    const float* Wk         = (const float*)d_in[23];
    const float* Wv         = (const float*)d_in[24];
    const float* Wo         = (const float*)d_in[25];
    const float* ln_w       = (const float*)d_in[26];
    const float* ln_b       = (const float*)d_in[27];
    float* out = (float*)d_out;

    float *xx,*mix,*hmaa,*hgate,*hdec,*haaa,*hma,*hkkk,*hmk,*xm;
    uint32_t *wpk,*zpk;
    float *r,*gg,*k,*v,*w,*kk,*a,*ma,*mk,*b,*y;
    cudaGetSymbolAddress((void**)&xx,   g_xx);
    cudaGetSymbolAddress((void**)&mix,  g_mix);
    cudaGetSymbolAddress((void**)&hmaa, g_hmaa);
    cudaGetSymbolAddress((void**)&hgate,g_hgate);
    cudaGetSymbolAddress((void**)&hdec, g_hdec);
    cudaGetSymbolAddress((void**)&haaa, g_haaa);
    cudaGetSymbolAddress((void**)&hma,  g_hma);
    cudaGetSymbolAddress((void**)&hkkk, g_hkkk);
    cudaGetSymbolAddress((void**)&hmk,  g_hmk);
    cudaGetSymbolAddress((void**)&xm,   g_xm);
    cudaGetSymbolAddress((void**)&wpk,  g_wpk);
    cudaGetSymbolAddress((void**)&zpk,  g_zpk);
    cudaGetSymbolAddress((void**)&r,    g_r);
    cudaGetSymbolAddress((void**)&gg,   g_gg);
    cudaGetSymbolAddress((void**)&k,    g_k);
    cudaGetSymbolAddress((void**)&v,    g_v);
    cudaGetSymbolAddress((void**)&w,    g_w);
    cudaGetSymbolAddress((void**)&kk,   g_kk);
    cudaGetSymbolAddress((void**)&a,    g_a);
    cudaGetSymbolAddress((void**)&ma,   g_ma);
    cudaGetSymbolAddress((void**)&mk,   g_mk);
    cudaGetSymbolAddress((void**)&b,    g_b);
    cudaGetSymbolAddress((void**)&y,    g_y);

    const size_t S = (size_t)MT*NEC;
    const uint32_t* xrg_pk = (const uint32_t*)(xm + 0*S);
    const float*    xwa    = xm + 1*S;
    const uint32_t* xk_pk  = (const uint32_t*)(xm + 2*S);
    const uint32_t* xv_pk  = (const uint32_t*)(xm + 3*S);

    static bool attr_done = false;
    if (!attr_done) {
        cudaFuncSetAttribute(gemm_tc4, cudaFuncAttributeMaxDynamicSharedMemorySize,
                             2*G4_STG*4);
        attr_done = true;
    }
    const int g4_smem = 2*G4_STG*4;

    // 1) token shift
    shift_kernel<<<(unsigned)((S + 255)/256), 256>>>(x, time_maa_x, xx, mix);

    // 2) weight fp16 pack
    wpack_kernel<<<(unsigned)((4*NM + 255)/256), 256>>>(Wr, Wk, Wv, Wo, wpk);

    // 3) maa hidden (4 tiles)
    {
        NTArgs na = {};
        na.Aptr[0] = mix; na.apk[0] = 0;
        for (int i = 0; i < 4; i++)
            na.t[i] = { maa_w1 + (size_t)i*32*NEC, hmaa + i*32, 128, 32, 1, 0 };
        lora_nt_kernel<<<dim3(4, MT/128), 128>>>(na);
    }

    // 4) xm fused (4 groups; packed for 0/2/3, fp32 for 1)
    xm_kernel<<<dim3(8, MT/128, 4), 256>>>(hmaa, maa_w2, x, xx, time_maa, xm);

    // 5) hidden group 2 (10 tiles)
    {
        NTArgs na = {};
        na.Aptr[0] = xrg_pk; na.apk[0] = 1;
        na.Aptr[1] = xwa;    na.apk[1] = 0;
        na.Aptr[2] = xk_pk;  na.apk[2] = 1;
        int ti = 0;
        for (int i = 0; i < 4; i++)
            na.t[ti++] = { gate_w1 + (size_t)i*32*NEC, hgate + i*32, 128, 32, 1, 0 };
        for (int i = 0; i < 2; i++)
            na.t[ti++] = { decay_w1 + (size_t)i*32*NEC, hdec + i*32, 64, 32, 1, 1 };
        na.t[ti++] = { aaa_w1, haaa, 16, 16, 0, 1 };
        na.t[ti++] = { ma_w1,  hma,  16, 16, 0, 1 };
        na.t[ti++] = { kkk_w1, hkkk, 16, 16, 1, 2 };
        na.t[ti++] = { mk_w1,  hmk,  16, 16, 0, 2 };
        lora_nt_kernel<<<dim3(10, MT/128), 128>>>(na);
    }

    // 6) big GEMMs: r, k, v (fp16 split-2, packed operands)
    gemm_tc4<<<dim3(8,32), 256, g4_smem>>>(xrg_pk, wpk+0*NM, r, MT, NEC, NEC);
    gemm_tc4<<<dim3(8,32), 256, g4_smem>>>(xk_pk,  wpk+1*NM, k, MT, NEC, NEC);
    gemm_tc4<<<dim3(8,32), 256, g4_smem>>>(xv_pk,  wpk+2*NM, v, MT, NEC, NEC);

    // 7) second stage (6 groups)
    {
        NNArgs nn = {};
        nn.g[0] = { hgate, gate_w2,  gg, 128, EPI_NONE, nullptr, nullptr };
        nn.g[1] = { hdec,  decay_w2, w,   64, EPI_W,    nullptr, time_decay };
        nn.g[2] = { hkkk,  kkk_w2,   kk,  16, EPI_ADD,  k,       nullptr };
        nn.g[3] = { haaa,  aaa_w2,   a,   16, EPI_SIG,  nullptr, time_aaaaa };
        nn.g[4] = { hma,   ma_w2,    ma,  16, EPI_SIG,  nullptr, time_misc_a };
        nn.g[5] = { hmk,   mk_w2,    mk,  16, EPI_SIG,  nullptr, time_misc_k };
        lora_nn_kernel<<<dim3(8, MT/128, 6), 256>>>(nn);
    }

    // 8) prep
    prep_kernel<<<MT, 512>>>(k, kk, a, ma, mk, w, b);

    // 9) recurrence
    wkv7_kernel<<<BATCH*NH, 256>>>(r, w, k, v, kk, b, y);

    // 10) groupnorm + bonus + gate -> packed z
    gn_kernel<<<MT, 512>>>(y, r, k, v, gg, ln_w, ln_b, time_faaaa, zpk);

    // 11) out = z @ Wo.T
    gemm_tc4<<<dim3(8,32), 256, g4_smem>>>(zpk, wpk+3*NM, out, MT, NEC, NEC);
}

// round 8
// speedup vs baseline: 2.6189x; 1.2270x over previous
#include <cuda_runtime.h>
#include <cuda_fp16.h>
#include <math.h>
#include <stdint.h>

// Problem constants
#define BATCH 4
#define TSEQ  1024
#define NEC   1024
#define NH    16
#define HSZ   64
#define MT    (BATCH*TSEQ)      // 4096 rows
#define EPSGN 0.00064f
#define NM    ((size_t)NEC*NEC) // 1M

// ---------------------------------------------------------------------------
// Scratch (device globals)
// ---------------------------------------------------------------------------
__device__ float    g_xx   [(size_t)MT*NEC];
__device__ float    g_mix  [(size_t)MT*NEC];
__device__ float    g_hmaa [(size_t)MT*128];
__device__ float    g_hgate[(size_t)MT*128];
__device__ float    g_hdec [(size_t)MT*64];
__device__ float    g_haaa [(size_t)MT*16];
__device__ float    g_hma  [(size_t)MT*16];
__device__ float    g_hkkk [(size_t)MT*16];
__device__ float    g_hmk  [(size_t)MT*16];
__device__ float    g_xm   [4][(size_t)MT*NEC];  // g1 fp32; g0/2/3 packed half2
__device__ uint32_t g_wpk  [4*NM];               // Wr,Wk,Wv,Wo packed (hi,lo) fp16
__device__ uint32_t g_zpk  [(size_t)MT*NEC];
__device__ float    g_r    [(size_t)MT*NEC];
__device__ float    g_gg   [(size_t)MT*NEC];
__device__ float    g_k    [(size_t)MT*NEC];
__device__ float    g_v    [(size_t)MT*NEC];
__device__ float    g_w    [(size_t)MT*NEC];
__device__ float    g_kk   [(size_t)MT*NEC];
__device__ float    g_a    [(size_t)MT*NEC];
__device__ float    g_ma   [(size_t)MT*NEC];
__device__ float    g_mk   [(size_t)MT*NEC];
__device__ float    g_b    [(size_t)MT*NEC];
__device__ float    g_y    [(size_t)MT*NEC];

enum { EPI_NONE=0, EPI_W=3, EPI_ADD=4, EPI_SIG=5 };

// ---------------------------------------------------------------------------
// fp16 split helpers
// ---------------------------------------------------------------------------
__device__ __forceinline__ uint32_t packf(float v){
    __half hi = __float2half_rn(v);
    __half lo = __float2half_rn(v - __half2float(hi));
    __half2 h2 = __halves2half2(hi, lo);
    return *reinterpret_cast<uint32_t*>(&h2);
}
__device__ __forceinline__ float unpackf(uint32_t u){
    __half2 h = *reinterpret_cast<__half2*>(&u);
    return __low2float(h) + __high2float(h);
}
__device__ __forceinline__ void mma_f16(float* c, const uint32_t* a, const uint32_t* b){
    asm volatile("mma.sync.aligned.m16n8k16.row.col.f32.f16.f16.f32 "
        "{%0,%1,%2,%3},{%4,%5,%6,%7},{%8,%9},{%0,%1,%2,%3};\n"
        : "+f"(c[0]), "+f"(c[1]), "+f"(c[2]), "+f"(c[3])
        : "r"(a[0]), "r"(a[1]), "r"(a[2]), "r"(a[3]), "r"(b[0]), "r"(b[1]));
}
__device__ __forceinline__ void cpa16(uint32_t dst, const void* src){
    asm volatile("cp.async.cg.shared.global [%0],[%1],16;\n"::"r"(dst),"l"(src));
}
__device__ __forceinline__ void cpa4(uint32_t dst, const void* src){
    asm volatile("cp.async.ca.shared.global [%0],[%1],4;\n"::"r"(dst),"l"(src));
}
#define CP_COMMIT() asm volatile("cp.async.commit_group;\n")
#define CP_WAIT0()  asm volatile("cp.async.wait_group 0;\n")
#define CP_WAIT1()  asm volatile("cp.async.wait_group 1;\n")

// ---------------------------------------------------------------------------
// Token shift
// ---------------------------------------------------------------------------
__global__ void shift_kernel(const float* __restrict__ x,
                             const float* __restrict__ tmaax,
                             float* __restrict__ xx,
                             float* __restrict__ mix)
{
    size_t i = (size_t)blockIdx.x * blockDim.x + threadIdx.x;
    if (i >= (size_t)MT * NEC) return;
    int c = (int)(i % NEC);
    size_t row = i / NEC;
    int t = (int)(row % TSEQ);
    float xv = x[i];
    float xp = (t > 0) ? x[i - NEC] : 0.f;
    float d = xp - xv;
    xx[i]  = d;
    mix[i] = fmaf(d, tmaax[c], xv);
}

// ---------------------------------------------------------------------------
// Weight pack (fp16 hi/lo) for Wr,Wk,Wv,Wo
// ---------------------------------------------------------------------------
__global__ void wpack_kernel(const float* __restrict__ Wr, const float* __restrict__ Wk,
                             const float* __restrict__ Wv, const float* __restrict__ Wo,
                             uint32_t* __restrict__ wpk)
{
    size_t i = (size_t)blockIdx.x * blockDim.x + threadIdx.x;
    if (i >= 4*NM) return;
    int seg = (int)(i >> 20);
    size_t off = i & (NM - 1);
    const float* src = (seg==0) ? Wr : (seg==1) ? Wk : (seg==2) ? Wv : Wo;
    wpk[i] = packf(src[off]);
}

// ---------------------------------------------------------------------------
// fp16 split-2 NT GEMM (grouped over grid.z): C = A * B^T, packed operands.
// 3 products: AhBh + AhBl + AlBh via mma.m16n8k16.
// Tile 128x128xBK32, 256 threads, cp.async double-buffered, 2 CTA/SM.
// ---------------------------------------------------------------------------
#define G4_LDS 36      // words per row in smem (32 + 4 pad)
#define G4_STG 9216    // words per stage: A 128*36 + B 128*36

struct G4Args { const uint32_t* A[3]; const uint32_t* B[3]; float* C[3]; };

__global__ __launch_bounds__(256, 2)
void gemm_tc4(G4Args args, int N, int K)
{
    extern __shared__ uint32_t sm4[];
    const int z = blockIdx.z;
    const uint32_t* Apk = args.A[z];
    const uint32_t* Bpk = args.B[z];
    float* C = args.C[z];
    const int tid = threadIdx.x;
    const int bm0 = blockIdx.y*128, bn0 = blockIdx.x*128;
    const int warp = tid>>5, lane = tid&31, grp = lane>>2, q = lane&3;
    const int wm = (warp&1)*64, wn = (warp>>1)*32;
    const uint32_t sbase = (uint32_t)__cvta_generic_to_shared(sm4);

    float acc[4][4][4];
    #pragma unroll
    for (int mi=0;mi<4;mi++)
        #pragma unroll
        for (int ni=0;ni<4;ni++)
            #pragma unroll
            for (int e=0;e<4;e++) acc[mi][ni][e]=0.f;

    const uint32_t* asrc[4]; const uint32_t* bsrc[4];
    uint32_t adst[4], bdst[4];
    #pragma unroll
    for (int l = 0; l < 4; l++) {
        int idx = tid + l*256;
        int r = idx >> 3, c4 = idx & 7;
        asrc[l] = Apk + (size_t)(bm0+r)*K + c4*4;
        bsrc[l] = Bpk + (size_t)(bn0+r)*K + c4*4;
        adst[l] = sbase + (uint32_t)(r*G4_LDS + c4*4)*4;
        bdst[l] = sbase + (uint32_t)(4608 + r*G4_LDS + c4*4)*4;
    }

#define G4_LOAD(st, kb) do {                                   \
        uint32_t _o = (st)*G4_STG*4;                           \
        _Pragma("unroll")                                      \
        for (int l = 0; l < 4; l++) {                          \
            cpa16(adst[l] + _o, asrc[l] + (kb));               \
            cpa16(bdst[l] + _o, bsrc[l] + (kb));               \
        }                                                      \
    } while(0)

    G4_LOAD(0, 0); CP_COMMIT();

    int p = 0;
    for (int kb = 0; kb < K; kb += 32) {
        CP_WAIT0();
        __syncthreads();
        if (kb + 32 < K) { G4_LOAD(p^1, kb+32); CP_COMMIT(); }

        const uint32_t* S = sm4 + p*G4_STG;

        #pragma unroll
        for (int kc = 0; kc < 32; kc += 16) {
            uint32_t ah[4][4], al[4][4], bh[4][2], bl[4][2];
            #pragma unroll
            for (int mi = 0; mi < 4; mi++) {
                int r0 = (wm + mi*16 + grp)*G4_LDS + kc + 2*q;
                uint2 w0 = *(const uint2*)&S[r0];
                uint2 w1 = *(const uint2*)&S[r0 + 8*G4_LDS];
                uint2 w2 = *(const uint2*)&S[r0 + 8];
                uint2 w3 = *(const uint2*)&S[r0 + 8*G4_LDS + 8];
                ah[mi][0]=__byte_perm(w0.x,w0.y,0x5410); al[mi][0]=__byte_perm(w0.x,w0.y,0x7632);
                ah[mi][1]=__byte_perm(w1.x,w1.y,0x5410); al[mi][1]=__byte_perm(w1.x,w1.y,0x7632);
                ah[mi][2]=__byte_perm(w2.x,w2.y,0x5410); al[mi][2]=__byte_perm(w2.x,w2.y,0x7632);
                ah[mi][3]=__byte_perm(w3.x,w3.y,0x5410); al[mi][3]=__byte_perm(w3.x,w3.y,0x7632);
            }
            #pragma unroll
            for (int ni = 0; ni < 4; ni++) {
                int c0 = 4608 + (wn + ni*8 + grp)*G4_LDS + kc + 2*q;
                uint2 u0 = *(const uint2*)&S[c0];
                uint2 u1 = *(const uint2*)&S[c0 + 8];
                bh[ni][0]=__byte_perm(u0.x,u0.y,0x5410); bl[ni][0]=__byte_perm(u0.x,u0.y,0x7632);
                bh[ni][1]=__byte_perm(u1.x,u1.y,0x5410); bl[ni][1]=__byte_perm(u1.x,u1.y,0x7632);
            }
            #pragma unroll
            for (int mi = 0; mi < 4; mi++)
                #pragma unroll
                for (int ni = 0; ni < 4; ni++) {
                    mma_f16(acc[mi][ni], ah[mi], bh[ni]);
                    mma_f16(acc[mi][ni], ah[mi], bl[ni]);
                    mma_f16(acc[mi][ni], al[mi], bh[ni]);
                }
        }
        __syncthreads();
        p ^= 1;
    }

    #pragma unroll
    for (int mi = 0; mi < 4; mi++) {
        int row0 = bm0 + wm + mi*16 + grp;
        #pragma unroll
        for (int ni = 0; ni < 4; ni++) {
            int col = bn0 + wn + ni*8 + 2*q;
            *(float2*)&C[(size_t)row0*N + col]     = make_float2(acc[mi][ni][0], acc[mi][ni][1]);
            *(float2*)&C[(size_t)(row0+8)*N + col] = make_float2(acc[mi][ni][2], acc[mi][ni][3]);
        }
    }
#undef G4_LOAD
}

// ---------------------------------------------------------------------------
// Grouped NT LoRA-hidden kernel: C = act(A @ B_tile^T), K=1024.
// A may be packed (hi,lo) fp16 words; unpack at smem fill.
// ---------------------------------------------------------------------------
struct NTTile { const float* B; float* C; int ldc; int nvalid; int tanhf; int asel; };
struct NTArgs { const void* Aptr[3]; int apk[3]; NTTile t[12]; };

__global__ __launch_bounds__(128)
void lora_nt_kernel(NTArgs args)
{
    constexpr int BK=32, K=NEC;
    __shared__ __align__(16) float As[BK][132];
    __shared__ __align__(16) float Bs[BK][36];
    NTTile tl = args.t[blockIdx.x];
    const int apk = args.apk[tl.asel];
    const int bm0 = blockIdx.y*128;
    const int tid = threadIdx.x;
    const int tx = tid & 7;
    const int ty = tid >> 3;

    float acc[8][4];
    #pragma unroll
    for (int i=0;i<8;i++)
        #pragma unroll
        for (int j=0;j<4;j++) acc[i][j]=0.f;

    for (int kb = 0; kb < K; kb += BK) {
        if (apk) {
            const uint32_t* A = (const uint32_t*)args.Aptr[tl.asel];
            #pragma unroll
            for (int l = 0; l < 8; l++) {
                int idx = tid + l*128;
                int r = idx >> 3, c = (idx & 7)*4;
                uint4 u = *(const uint4*)(A + (size_t)(bm0+r)*K + kb + c);
                As[c+0][r]=unpackf(u.x); As[c+1][r]=unpackf(u.y);
                As[c+2][r]=unpackf(u.z); As[c+3][r]=unpackf(u.w);
            }
        } else {
            const float* A = (const float*)args.Aptr[tl.asel];
            #pragma unroll
            for (int l = 0; l < 8; l++) {
                int idx = tid + l*128;
                int r = idx >> 3, c = (idx & 7)*4;
                float4 val = *(const float4*)(A + (size_t)(bm0+r)*K + kb + c);
                As[c+0][r]=val.x; As[c+1][r]=val.y; As[c+2][r]=val.z; As[c+3][r]=val.w;
            }
        }
        #pragma unroll
        for (int l = 0; l < 2; l++) {
            int idx = tid + l*128;
            int r = idx >> 3, c = (idx & 7)*4;
            float4 val = (r < tl.nvalid) ?
                *(const float4*)(tl.B + (size_t)r*K + kb + c) : make_float4(0,0,0,0);
            Bs[c+0][r]=val.x; Bs[c+1][r]=val.y; Bs[c+2][r]=val.z; Bs[c+3][r]=val.w;
        }
        __syncthreads();
        #pragma unroll
        for (int kk = 0; kk < BK; kk++) {
            float4 m0 = *(const float4*)&As[kk][ty*8];
            float4 m1 = *(const float4*)&As[kk][ty*8+4];
            float4 rn = *(const float4*)&Bs[kk][tx*4];
            float rm[8] = {m0.x,m0.y,m0.z,m0.w,m1.x,m1.y,m1.z,m1.w};
            #pragma unroll
            for (int i=0;i<8;i++) {
                acc[i][0] = fmaf(rm[i], rn.x, acc[i][0]);
                acc[i][1] = fmaf(rm[i], rn.y, acc[i][1]);
                acc[i][2] = fmaf(rm[i], rn.z, acc[i][2]);
                acc[i][3] = fmaf(rm[i], rn.w, acc[i][3]);
            }
        }
        __syncthreads();
    }
    #pragma unroll
    for (int i=0;i<8;i++) {
        int row = bm0 + ty*8 + i;
        #pragma unroll
        for (int j=0;j<4;j++) {
            int col = tx*4 + j;
            if (col < tl.nvalid) {
                float vv = acc[i][j];
                if (tl.tanhf) vv = tanhf(vv);
                tl.C[(size_t)row*tl.ldc + col] = vv;
            }
        }
    }
}

// ---------------------------------------------------------------------------
// Fused xm kernel: per group g, val = x + xx*(Ag @ Bg + time_maa[g]).
// g==1 -> fp32 out (xwa); else packed (hi,lo) fp16 out.
// ---------------------------------------------------------------------------
__global__ __launch_bounds__(256)
void xm_kernel(const float* __restrict__ hmaa,
               const float* __restrict__ maa_w2,
               const float* __restrict__ x,
               const float* __restrict__ xx,
               const float* __restrict__ time_maa,
               float* __restrict__ xmbase)
{
    constexpr int BM=128, BN=128, BK=32;
    __shared__ float As[BK][BM+1];
    __shared__ float Bs[BK][BN];
    const int g = blockIdx.z;
    const float* A = hmaa + g*32;
    const float* B = maa_w2 + (size_t)g*32*NEC;
    float* C = xmbase + (size_t)g*MT*NEC;
    const float* tm = time_maa + g*NEC;
    const int bm0 = blockIdx.y*BM, bn0 = blockIdx.x*BN;
    const int tid = threadIdx.x;
    const int tx = tid & 15, ty = tid >> 4;

    float acc[8][8];
    #pragma unroll
    for (int i=0;i<8;i++)
        #pragma unroll
        for (int j=0;j<8;j++) acc[i][j]=0.f;

    #pragma unroll
    for (int l = 0; l < 4; l++) {
        int idx = tid + l*256;
        int r = idx >> 3, c = (idx & 7)*4;
        float4 val = *(const float4*)(A + (size_t)(bm0+r)*128 + c);
        As[c+0][r]=val.x; As[c+1][r]=val.y; As[c+2][r]=val.z; As[c+3][r]=val.w;
    }
    #pragma unroll
    for (int l = 0; l < 4; l++) {
        int idx = tid + l*256;
        int r = idx >> 5, c = (idx & 31)*4;
        *(float4*)&Bs[r][c] = *(const float4*)(B + (size_t)r*NEC + bn0 + c);
    }
    __syncthreads();
    #pragma unroll
    for (int kk = 0; kk < BK; kk++) {
        float rm[8], rn[8];
        #pragma unroll
        for (int i=0;i<8;i++) rm[i] = As[kk][ty*8+i];
        #pragma unroll
        for (int j=0;j<8;j++) rn[j] = Bs[kk][tx*8+j];
        #pragma unroll
        for (int i=0;i<8;i++)
            #pragma unroll
            for (int j=0;j<8;j++) acc[i][j] = fmaf(rm[i], rn[j], acc[i][j]);
    }
    #pragma unroll
    for (int i=0;i<8;i++) {
        int row = bm0 + ty*8 + i;
        #pragma unroll
        for (int j=0;j<8;j+=2) {
            int col = bn0 + tx*8 + j;
            size_t idx = (size_t)row*NEC + col;
            float2 xv = *(const float2*)&x[idx];
            float2 dv = *(const float2*)&xx[idx];
            float v0 = fmaf(dv.x, acc[i][j]   + tm[col],   xv.x);
            float v1 = fmaf(dv.y, acc[i][j+1] + tm[col+1], xv.y);
            if (g == 1) {
                *(float2*)&C[idx] = make_float2(v0, v1);
            } else {
                uint2 pk = make_uint2(packf(v0), packf(v1));
                *(uint2*)&((uint32_t*)C)[idx] = pk;
            }
        }
    }
}

// ---------------------------------------------------------------------------
// Grouped second-stage NN kernel
// ---------------------------------------------------------------------------
struct NNGroup { const float* A; const float* B; float* C; int K; int epi;
                 const float* e0; const float* e2; };
struct NNArgs { NNGroup g[6]; };

__global__ __launch_bounds__(256)
void lora_nn_kernel(NNArgs args)
{
    constexpr int BM=128, BN=128, BK=16;
    __shared__ float As[BK][BM+1];
    __shared__ float Bs[BK][BN];
    NNGroup grp = args.g[blockIdx.z];
    const int K = grp.K;
    const int bm0 = blockIdx.y*BM, bn0 = blockIdx.x*BN;
    const int tid = threadIdx.x;
    const int tx = tid & 15, ty = tid >> 4;

    float acc[8][8];
    #pragma unroll
    for (int i=0;i<8;i++)
        #pragma unroll
        for (int j=0;j<8;j++) acc[i][j]=0.f;

    for (int kb = 0; kb < K; kb += BK) {
        #pragma unroll
        for (int l = 0; l < 2; l++) {
            int idx = tid + l*256;
            int r = idx >> 2, c = (idx & 3)*4;
            float4 val = *(const float4*)(grp.A + (size_t)(bm0+r)*K + kb + c);
            As[c+0][r]=val.x; As[c+1][r]=val.y; As[c+2][r]=val.z; As[c+3][r]=val.w;
        }
        #pragma unroll
        for (int l = 0; l < 2; l++) {
            int idx = tid + l*256;
            int r = idx >> 5, c = (idx & 31)*4;
            *(float4*)&Bs[r][c] = *(const float4*)(grp.B + (size_t)(kb+r)*NEC + bn0 + c);
        }
        __syncthreads();
        #pragma unroll
        for (int kk = 0; kk < BK; kk++) {
            float rm[8], rn[8];
            #pragma unroll
            for (int i=0;i<8;i++) rm[i] = As[kk][ty*8+i];
            #pragma unroll
            for (int j=0;j<8;j++) rn[j] = Bs[kk][tx*8+j];
            #pragma unroll
            for (int i=0;i<8;i++)
                #pragma unroll
                for (int j=0;j<8;j++) acc[i][j] = fmaf(rm[i], rn[j], acc[i][j]);
        }
        __syncthreads();
    }
    #pragma unroll
    for (int i=0;i<8;i++) {
        int row = bm0 + ty*8 + i;
        #pragma unroll
        for (int j=0;j<8;j++) {
            int col = bn0 + tx*8 + j;
            size_t idx = (size_t)row*NEC + col;
            float vv = acc[i][j], outv;
            switch (grp.epi) {
                case EPI_W: {
                    float tt = -(grp.e2[col] + vv);
                    float sp = (tt > 15.f) ? tt : log1pf(expf(tt));
                    outv = -sp - 0.5f;
                } break;
                case EPI_ADD: outv = grp.e0[idx] + vv; break;
                case EPI_SIG: {
                    float u = grp.e2[col] + vv;
                    outv = 1.f / (1.f + expf(-u));
                } break;
                default: outv = vv;
            }
            grp.C[idx] = outv;
        }
    }
}

// ---------------------------------------------------------------------------
// warp sum
// ---------------------------------------------------------------------------
__device__ __forceinline__ float warp_sum(float v)
{
    #pragma unroll
    for (int o = 16; o > 0; o >>= 1) v += __shfl_xor_sync(0xffffffffu, v, o);
    return v;
}

// ---------------------------------------------------------------------------
// prep
// ---------------------------------------------------------------------------
__global__ void prep_kernel(float* kptr, float* kkptr,
                            const float* __restrict__ a,
                            const float* __restrict__ ma,
                            const float* __restrict__ mk,
                            float* wptr,
                            float* __restrict__ b)
{
    int m = blockIdx.x;
    int h = threadIdx.x >> 5;
    int lane = threadIdx.x & 31;
    size_t base = (size_t)m*NEC + h*HSZ;
    size_t i0 = base + lane, i1 = i0 + 32;

    float kk0 = kkptr[i0], kk1 = kkptr[i1];
    float ss = warp_sum(kk0*kk0 + kk1*kk1);
    float inv = 1.f / fmaxf(sqrtf(ss), 1e-12f);
    float n0 = kk0*inv, n1 = kk1*inv;
    kkptr[i0] = n0; kkptr[i1] = n1;

    float a0 = a[i0], a1 = a[i1];
    b[i0] = -n0*a0; b[i1] = -n1*a1;

    float ma0 = ma[i0], ma1 = ma[i1];
    float k0v = kptr[i0], k1v = kptr[i1];
    float w0 = wptr[i0], w1 = wptr[i1];
    float mk0 = mk[i0], mk1 = mk[i1];
    kptr[i0] = k0v * (ma0 + a0*(1.f - ma0)) * expf(w0*mk0);
    kptr[i1] = k1v * (ma1 + a1*(1.f - ma1)) * expf(w1*mk1);
    wptr[i0] = expf(-expf(w0));
    wptr[i1] = expf(-expf(w1));
}

// ---------------------------------------------------------------------------
// RWKV7 recurrence v4: rows are independent -> 2 blocks per head.
// Block handles 32 rows; 256 threads = 32 rows x 8-way column split.
// 3-stage cp.async ring (2 steps of prefetch depth).
// Shared slots per stage: q,w,k,a,b (full 64 each) + v (32) = 352 floats.
// ---------------------------------------------------------------------------
__global__ __launch_bounds__(256)
void wkv7_kernel(const float* __restrict__ q, const float* __restrict__ w,
                 const float* __restrict__ k, const float* __restrict__ v,
                 const float* __restrict__ a, const float* __restrict__ b,
                 float* __restrict__ y)
{
    const int blk = blockIdx.x;            // 0..127
    const int bh = blk >> 1, rh = blk & 1;
    const int batch = bh >> 4, h = bh & 15;
    const int tid = threadIdx.x;
    const int il = tid >> 3, qd = tid & 7;  // row-local, column-octant

    __shared__ __align__(16) float buf[3][352];

    float s[8];
    #pragma unroll
    for (int j = 0; j < 8; j++) s[j] = 0.f;

    const size_t base = (size_t)batch * TSEQ * NEC + (size_t)h * HSZ;

    // loader: 352 floats/step over 256 threads (slot tid; tid<96 also slot 256+tid)
    const float* table[4] = {q, w, k, a};
    const float* s0 = table[tid>>6] + base + (tid & 63);
    const float* s1 = nullptr;
    if (tid < 64)       s1 = b + base + tid;
    else if (tid < 96)  s1 = v + base + rh*32 + (tid - 64);
    const uint32_t sb = (uint32_t)__cvta_generic_to_shared(buf);
    const uint32_t d0 = sb + (uint32_t)tid*4;
    const uint32_t d1 = sb + (uint32_t)(256 + tid)*4;
    const uint32_t STRB = 352*4;

    // prologue: stages 0 (t=0) and 1 (t=1)
    cpa4(d0, s0);
    if (tid < 96) cpa4(d1, s1);
    CP_COMMIT();
    cpa4(d0 + STRB, s0 + NEC);
    if (tid < 96) cpa4(d1 + STRB, s1 + NEC);
    CP_COMMIT();

    const size_t ybase = base + (size_t)rh*32 + il;

    int p = 0;
    for (int t = 0; t < TSEQ; t++) {
        CP_WAIT1();
        __syncthreads();

        {
            int st = p + 2; if (st >= 3) st -= 3;
            if (t + 2 < TSEQ) {
                size_t o = (size_t)(t+2)*NEC;
                cpa4(d0 + (uint32_t)st*STRB, s0 + o);
                if (tid < 96) cpa4(d1 + (uint32_t)st*STRB, s1 + o);
            }
            CP_COMMIT();
        }

        const float* bb = buf[p];
        const int co = qd*8;
        const float4* q4 = (const float4*)(bb +   0 + co);
        const float4* w4 = (const float4*)(bb +  64 + co);
        const float4* k4 = (const float4*)(bb + 128 + co);
        const float4* a4 = (const float4*)(bb + 192 + co);
        const float4* b4 = (const float4*)(bb + 256 + co);
        float vi = bb[320 + il];

        float4 av0 = a4[0], av1 = a4[1];
        float sa0 = fmaf(s[0], av0.x, s[4]*av1.x);
        float sa1 = fmaf(s[1], av0.y, s[5]*av1.y);
        float sa2 = fmaf(s[2], av0.z, s[6]*av1.z);
        float sa3 = fmaf(s[3], av0.w, s[7]*av1.w);
        float sa = (sa0+sa1) + (sa2+sa3);
        sa += __shfl_xor_sync(0xffffffffu, sa, 1);
        sa += __shfl_xor_sync(0xffffffffu, sa, 2);
        sa += __shfl_xor_sync(0xffffffffu, sa, 4);

        float4 wv0 = w4[0], wv1 = w4[1];
        float4 kv0 = k4[0], kv1 = k4[1];
        float4 bv0 = b4[0], bv1 = b4[1];
        float4 qv0 = q4[0], qv1 = q4[1];

        float t0 = fmaf(s[0], wv0.x, fmaf(sa, bv0.x, vi*kv0.x));
        float t1 = fmaf(s[1], wv0.y, fmaf(sa, bv0.y, vi*kv0.y));
        float t2 = fmaf(s[2], wv0.z, fmaf(sa, bv0.z, vi*kv0.z));
        float t3 = fmaf(s[3], wv0.w, fmaf(sa, bv0.w, vi*kv0.w));
        float t4 = fmaf(s[4], wv1.x, fmaf(sa, bv1.x, vi*kv1.x));
        float t5 = fmaf(s[5], wv1.y, fmaf(sa, bv1.y, vi*kv1.y));
        float t6 = fmaf(s[6], wv1.z, fmaf(sa, bv1.z, vi*kv1.z));
        float t7 = fmaf(s[7], wv1.w, fmaf(sa, bv1.w, vi*kv1.w));
        s[0]=t0; s[1]=t1; s[2]=t2; s[3]=t3; s[4]=t4; s[5]=t5; s[6]=t6; s[7]=t7;

        float y0 = fmaf(t0, qv0.x, t4*qv1.x);
        float y1 = fmaf(t1, qv0.y, t5*qv1.y);
        float y2 = fmaf(t2, qv0.z, t6*qv1.z);
        float y3 = fmaf(t3, qv0.w, t7*qv1.w);
        float yi = (y0+y1) + (y2+y3);
        yi += __shfl_xor_sync(0xffffffffu, yi, 1);
        yi += __shfl_xor_sync(0xffffffffu, yi, 2);
        yi += __shfl_xor_sync(0xffffffffu, yi, 4);
        if (qd == 0) y[ybase + (size_t)t*NEC] = yi;

        if (++p == 3) p = 0;
    }
}

// ---------------------------------------------------------------------------
// GroupNorm + bonus + gate -> packed z
// ---------------------------------------------------------------------------
__global__ void gn_kernel(const float* __restrict__ y,
                          const float* __restrict__ r,
                          const float* __restrict__ k,
                          const float* __restrict__ v,
                          const float* __restrict__ gg,
                          const float* __restrict__ ln_w,
                          const float* __restrict__ ln_b,
                          const float* __restrict__ faaaa,
                          uint32_t* __restrict__ zpk)
{
    int m = blockIdx.x;
    int h = threadIdx.x >> 5;
    int lane = threadIdx.x & 31;
    size_t base = (size_t)m*NEC + h*HSZ;
    int c0 = h*HSZ + lane, c1 = c0 + 32;
    size_t i0 = base + lane, i1 = i0 + 32;

    float y0 = y[i0], y1 = y[i1];
    float mu = warp_sum(y0 + y1) * (1.f/64.f);
    float d0 = y0 - mu, d1 = y1 - mu;
    float var = warp_sum(d0*d0 + d1*d1) * (1.f/64.f);
    float rstd = rsqrtf(var + EPSGN);
    float yn0 = d0*rstd*ln_w[c0] + ln_b[c0];
    float yn1 = d1*rstd*ln_w[c1] + ln_b[c1];

    float r0 = r[i0], r1 = r[i1];
    float k0v = k[i0], k1v = k[i1];
    float rk = warp_sum(r0*k0v*faaaa[c0] + r1*k1v*faaaa[c1]);

    float v0 = v[i0], v1 = v[i1];
    zpk[i0] = packf((yn0 + rk*v0) * gg[i0]);
    zpk[i1] = packf((yn1 + rk*v1) * gg[i1]);
}

// ---------------------------------------------------------------------------
// Host side
// ---------------------------------------------------------------------------
extern "C" void kernel_launch(void* const* d_in, const int* in_sizes, int n_in,
                              void* d_out, int out_size)
{
    const float* x          = (const float*)d_in[0];
    const float* time_maa_x = (const float*)d_in[1];
    const float* time_maa   = (const float*)d_in[2];
    const float* maa_w1     = (const float*)d_in[3];
    const float* maa_w2     = (const float*)d_in[4];
    const float* decay_w1   = (const float*)d_in[5];
    const float* decay_w2   = (const float*)d_in[6];
    const float* aaa_w1     = (const float*)d_in[7];
    const float* aaa_w2     = (const float*)d_in[8];
    const float* kkk_w1     = (const float*)d_in[9];
    const float* kkk_w2     = (const float*)d_in[10];
    const float* gate_w1    = (const float*)d_in[11];
    const float* gate_w2    = (const float*)d_in[12];
    const float* ma_w1      = (const float*)d_in[13];
    const float* ma_w2      = (const float*)d_in[14];
    const float* mk_w1      = (const float*)d_in[15];
    const float* mk_w2      = (const float*)d_in[16];
    const float* time_decay = (const float*)d_in[17];
    const float* time_faaaa = (const float*)d_in[18];
    const float* time_aaaaa = (const float*)d_in[19];
    const float* time_misc_a= (const float*)d_in[20];
    const float* time_misc_k= (const float*)d_in[21];
    const float* Wr         = (const float*)d_in[22];
    const float* Wk         = (const float*)d_in[23];
    const float* Wv         = (const float*)d_in[24];
    const float* Wo         = (const float*)d_in[25];
    const float* ln_w       = (const float*)d_in[26];
    const float* ln_b       = (const float*)d_in[27];
    float* out = (float*)d_out;

    float *xx,*mix,*hmaa,*hgate,*hdec,*haaa,*hma,*hkkk,*hmk,*xm;
    uint32_t *wpk,*zpk;
    float *r,*gg,*k,*v,*w,*kk,*a,*ma,*mk,*b,*y;
    cudaGetSymbolAddress((void**)&xx,   g_xx);
    cudaGetSymbolAddress((void**)&mix,  g_mix);
    cudaGetSymbolAddress((void**)&hmaa, g_hmaa);
    cudaGetSymbolAddress((void**)&hgate,g_hgate);
    cudaGetSymbolAddress((void**)&hdec, g_hdec);
    cudaGetSymbolAddress((void**)&haaa, g_haaa);
    cudaGetSymbolAddress((void**)&hma,  g_hma);
    cudaGetSymbolAddress((void**)&hkkk, g_hkkk);
    cudaGetSymbolAddress((void**)&hmk,  g_hmk);
    cudaGetSymbolAddress((void**)&xm,   g_xm);
    cudaGetSymbolAddress((void**)&wpk,  g_wpk);
    cudaGetSymbolAddress((void**)&zpk,  g_zpk);
    cudaGetSymbolAddress((void**)&r,    g_r);
    cudaGetSymbolAddress((void**)&gg,   g_gg);
    cudaGetSymbolAddress((void**)&k,    g_k);
    cudaGetSymbolAddress((void**)&v,    g_v);
    cudaGetSymbolAddress((void**)&w,    g_w);
    cudaGetSymbolAddress((void**)&kk,   g_kk);
    cudaGetSymbolAddress((void**)&a,    g_a);
    cudaGetSymbolAddress((void**)&ma,   g_ma);
    cudaGetSymbolAddress((void**)&mk,   g_mk);
    cudaGetSymbolAddress((void**)&b,    g_b);
    cudaGetSymbolAddress((void**)&y,    g_y);

    const size_t S = (size_t)MT*NEC;
    const uint32_t* xrg_pk = (const uint32_t*)(xm + 0*S);
    const float*    xwa    = xm + 1*S;
    const uint32_t* xk_pk  = (const uint32_t*)(xm + 2*S);
    const uint32_t* xv_pk  = (const uint32_t*)(xm + 3*S);

    static bool attr_done = false;
    if (!attr_done) {
        cudaFuncSetAttribute(gemm_tc4, cudaFuncAttributeMaxDynamicSharedMemorySize,
                             2*G4_STG*4);
        attr_done = true;
    }
    const int g4_smem = 2*G4_STG*4;

    // 1) token shift
    shift_kernel<<<(unsigned)((S + 255)/256), 256>>>(x, time_maa_x, xx, mix);

    // 2) weight fp16 pack
    wpack_kernel<<<(unsigned)((4*NM + 255)/256), 256>>>(Wr, Wk, Wv, Wo, wpk);

    // 3) maa hidden (4 tiles)
    {
        NTArgs na = {};
        na.Aptr[0] = mix; na.apk[0] = 0;
        for (int i = 0; i < 4; i++)
            na.t[i] = { maa_w1 + (size_t)i*32*NEC, hmaa + i*32, 128, 32, 1, 0 };
        lora_nt_kernel<<<dim3(4, MT/128), 128>>>(na);
    }

    // 4) xm fused (4 groups; packed for 0/2/3, fp32 for 1)
    xm_kernel<<<dim3(8, MT/128, 4), 256>>>(hmaa, maa_w2, x, xx, time_maa, xm);

    // 5) hidden group 2 (10 tiles)
    {
        NTArgs na = {};
        na.Aptr[0] = xrg_pk; na.apk[0] = 1;
        na.Aptr[1] = xwa;    na.apk[1] = 0;
        na.Aptr[2] = xk_pk;  na.apk[2] = 1;
        int ti = 0;
        for (int i = 0; i < 4; i++)
            na.t[ti++] = { gate_w1 + (size_t)i*32*NEC, hgate + i*32, 128, 32, 1, 0 };
        for (int i = 0; i < 2; i++)
            na.t[ti++] = { decay_w1 + (size_t)i*32*NEC, hdec + i*32, 64, 32, 1, 1 };
        na.t[ti++] = { aaa_w1, haaa, 16, 16, 0, 1 };
        na.t[ti++] = { ma_w1,  hma,  16, 16, 0, 1 };
        na.t[ti++] = { kkk_w1, hkkk, 16, 16, 1, 2 };
        na.t[ti++] = { mk_w1,  hmk,  16, 16, 0, 2 };
        lora_nt_kernel<<<dim3(10, MT/128), 128>>>(na);
    }

    // 6) big GEMMs r,k,v fused in one launch (grid.z = 3)
    {
        G4Args ga = {};
        ga.A[0] = xrg_pk; ga.B[0] = wpk+0*NM; ga.C[0] = r;
        ga.A[1] = xk_pk;  ga.B[1] = wpk+1*NM; ga.C[1] = k;
        ga.A[2] = xv_pk;  ga.B[2] = wpk+2*NM; ga.C[2] = v;
        gemm_tc4<<<dim3(8,32,3), 256, g4_smem>>>(ga, NEC, NEC);
    }

    // 7) second stage (6 groups)
    {
        NNArgs nn = {};
        nn.g[0] = { hgate, gate_w2,  gg, 128, EPI_NONE, nullptr, nullptr };
        nn.g[1] = { hdec,  decay_w2, w,   64, EPI_W,    nullptr, time_decay };
        nn.g[2] = { hkkk,  kkk_w2,   kk,  16, EPI_ADD,  k,       nullptr };
        nn.g[3] = { haaa,  aaa_w2,   a,   16, EPI_SIG,  nullptr, time_aaaaa };
        nn.g[4] = { hma,   ma_w2,    ma,  16, EPI_SIG,  nullptr, time_misc_a };
        nn.g[5] = { hmk,   mk_w2,    mk,  16, EPI_SIG,  nullptr, time_misc_k };
        lora_nn_kernel<<<dim3(8, MT/128, 6), 256>>>(nn);
    }

    // 8) prep
    prep_kernel<<<MT, 512>>>(k, kk, a, ma, mk, w, b);

    // 9) recurrence (2 blocks per head)
    wkv7_kernel<<<BATCH*NH*2, 256>>>(r, w, k, v, kk, b, y);

    // 10) groupnorm + bonus + gate -> packed z
    gn_kernel<<<MT, 512>>>(y, r, k, v, gg, ln_w, ln_b, time_faaaa, zpk);

    // 11) out = z @ Wo.T
    {
        G4Args ga = {};
        ga.A[0] = zpk; ga.B[0] = wpk+3*NM; ga.C[0] = out;
        gemm_tc4<<<dim3(8,32,1), 256, g4_smem>>>(ga, NEC, NEC);
    }
}